// round 7
// baseline (speedup 1.0000x reference)
#include <cuda_runtime.h>
#include <math.h>

#define SEQn 2048
#define Dn   768
#define Hn   8
#define DQKn 128
#define DVn  192
#define NQKVn 1344   /* 8*128 + 128 + 192 */
#define NPn  256
#define DPn  128
#define FFIn 1536
#define DPIn 256
#define EPS_RMS 1.1920929e-07f
#define EPS_LN  1e-5f

/* ---------------- scratch (device globals; no allocation) ---------------- */
__device__ float g_xn[SEQn * Dn];
__device__ float g_qkv[SEQn * NQKVn];
__device__ float g_q[Hn * SEQn * DQKn];
__device__ float g_k[SEQn * DQKn];
__device__ float g_v[SEQn * DVn];
__device__ float g_sim[(size_t)Hn * SEQn * SEQn];      /* 134 MB */
__device__ float g_pb[Hn * NPn * NPn];
__device__ float g_ao[SEQn * Hn * DVn];
__device__ float g_t1[SEQn * FFIn];
__device__ float g_rsum[Hn * SEQn];
__device__ float g_pxn[NPn * NPn * DPn];
__device__ float g_pqk[NPn * NPn * 2 * DPn];
__device__ float g_pv[NPn * NPn * DPn];
__device__ float g_psim[(size_t)NPn * NPn * NPn];      /* 67 MB */
__device__ float g_prsum[NPn * NPn];
__device__ float g_pt[NPn * NPn * DPIn];

/* ---------------- helpers ---------------- */
__device__ __forceinline__ unsigned f2tf32(float x) {
    unsigned r;
    asm("cvt.rna.tf32.f32 %0, %1;" : "=r"(r) : "f"(x));
    return r;
}

__device__ __forceinline__ void mma_tf32(float* c, const unsigned* a, const unsigned* b) {
    asm volatile(
        "mma.sync.aligned.m16n8k8.row.col.f32.tf32.tf32.f32 "
        "{%0,%1,%2,%3}, {%4,%5,%6,%7}, {%8,%9}, {%0,%1,%2,%3};\n"
        : "+f"(c[0]), "+f"(c[1]), "+f"(c[2]), "+f"(c[3])
        : "r"(a[0]), "r"(a[1]), "r"(a[2]), "r"(a[3]), "r"(b[0]), "r"(b[1]));
}

__device__ __forceinline__ float softclamp_exp(float x) {
    float t = __expf(-0.4f * fabsf(x));
    float th = __fdividef(1.f - t, 1.f + t);
    return __expf(copysignf(5.f * th, x));
}

template <int OP>
__device__ __forceinline__ float blockReduce(float v) {
    __shared__ float s[33];
    int lane = threadIdx.x & 31, wid = threadIdx.x >> 5;
#pragma unroll
    for (int o = 16; o > 0; o >>= 1) {
        float ov = __shfl_down_sync(0xffffffffu, v, o);
        v = (OP == 0) ? (v + ov) : fmaxf(v, ov);
    }
    if (lane == 0) s[wid] = v;
    __syncthreads();
    if (threadIdx.x == 0) {
        int nw = (blockDim.x + 31) >> 5;
        float r = s[0];
        for (int i = 1; i < nw; i++) r = (OP == 0) ? (r + s[i]) : fmaxf(r, s[i]);
        s[32] = r;
    }
    __syncthreads();
    float r = s[32];
    __syncthreads();
    return r;
}

__global__ void zero_k(float* p, int n)
{
    int i = blockIdx.x * blockDim.x + threadIdx.x;
    if (i < n) p[i] = 0.f;
}

/* ---------------- TF32 tensor-core GEMM, 128x128 CTA, 4 warps (64x64/warp),
   BK=16 double-buffered.
   MODE: 0 plain(+bias), 1 relu(+bias), 2 accumulate into C(+bias),
         3 sim softmax: exp(softclamp(x+pb)) + atomic row sums,
         4 pair softmax: exp(x) + atomic row sums.
   rscale (optional): multiply output rows by 1/rscale[batch*M+m].
   Requires M % 128 == 0, K % 16 == 0, N % 16 == 0 (tile-edge guarded).      */
template <bool TB, int MODE>
__global__ __launch_bounds__(128) void gemm_tc(
    int M, int N, int K,
    const float* __restrict__ A, int lda, long long sA,
    const float* __restrict__ B, int ldb, long long sB,
    float* __restrict__ C, int ldc, long long sC,
    const float* __restrict__ bias,
    const float* __restrict__ pbias,
    float* __restrict__ rsum,
    const float* __restrict__ rscale)
{
    __shared__ unsigned As[2][16][136];   /* stride 136 ≡ 8 mod 32: conflict-free frags */
    __shared__ unsigned Bs[2][16][136];
    const int batch = blockIdx.z;
    A += (long long)batch * sA;
    B += (long long)batch * sB;
    C += (long long)batch * sC;
    const int bm = blockIdx.y * 128, bn = blockIdx.x * 128;
    const int tid = threadIdx.x;
    const int lane = tid & 31, warp = tid >> 5;
    const int g = lane >> 2, tg = lane & 3;
    const int warpM = warp & 1, warpN = warp >> 1;   /* 2 x 2 warps -> 64 x 64 tiles */

    /* staging maps: A row = tid (128 rows x 16 k, 4 float4 per thread) */
    const float* Aptr = A + (long long)(bm + tid) * lda;
    /* B !TB: 16 k-rows x 128 n; thread covers row tid>>3, cols (tid&7)*16 .. +15 */
    const int bkr = tid >> 3, bn16 = (tid & 7) * 16;
    /* B TB: n-row = tid, 16 k */
    bool bval[4];
#pragma unroll
    for (int c = 0; c < 4; c++)
        bval[c] = TB ? (bn + tid < N) : (bn + bn16 + c * 4 < N);
    const float4 f0 = make_float4(0.f, 0.f, 0.f, 0.f);

    float4 pa[4], pbv[4];
    /* prefetch + store stage 0 */
#pragma unroll
    for (int c = 0; c < 4; c++) {
        pa[c] = *(const float4*)(Aptr + c * 4);
        if (TB) pbv[c] = bval[c] ? *(const float4*)(B + (long long)(bn + tid) * ldb + c * 4) : f0;
        else    pbv[c] = bval[c] ? *(const float4*)(B + (long long)bkr * ldb + bn + bn16 + c * 4) : f0;
    }
#pragma unroll
    for (int c = 0; c < 4; c++) {
        const float* af = (const float*)&pa[c];
        const float* bf = (const float*)&pbv[c];
#pragma unroll
        for (int i = 0; i < 4; i++) {
            As[0][c * 4 + i][tid] = f2tf32(af[i]);
            if (TB) Bs[0][c * 4 + i][tid] = f2tf32(bf[i]);
            else    Bs[0][bkr][bn16 + c * 4 + i] = f2tf32(bf[i]);
        }
    }
    __syncthreads();

    float acc[4][8][4];
#pragma unroll
    for (int mt = 0; mt < 4; mt++)
#pragma unroll
        for (int nt = 0; nt < 8; nt++)
#pragma unroll
            for (int u = 0; u < 4; u++) acc[mt][nt][u] = 0.f;

    const int nst = K >> 4;
    for (int st = 0; st < nst; st++) {
        if (st + 1 < nst) {
            const int kb = (st + 1) << 4;
#pragma unroll
            for (int c = 0; c < 4; c++) {
                pa[c] = *(const float4*)(Aptr + kb + c * 4);
                if (TB) pbv[c] = bval[c] ? *(const float4*)(B + (long long)(bn + tid) * ldb + kb + c * 4) : f0;
                else    pbv[c] = bval[c] ? *(const float4*)(B + (long long)(kb + bkr) * ldb + bn + bn16 + c * 4) : f0;
            }
        }
        const int buf = st & 1;
#pragma unroll
        for (int ks = 0; ks < 2; ks++) {
            const int k8 = ks * 8;
            unsigned af[4][4], bf[8][2];
#pragma unroll
            for (int mt = 0; mt < 4; mt++) {
                int m = warpM * 64 + mt * 16 + g;
                af[mt][0] = As[buf][k8 + tg][m];
                af[mt][1] = As[buf][k8 + tg][m + 8];
                af[mt][2] = As[buf][k8 + tg + 4][m];
                af[mt][3] = As[buf][k8 + tg + 4][m + 8];
            }
#pragma unroll
            for (int nt = 0; nt < 8; nt++) {
                int n = warpN * 64 + nt * 8 + g;
                bf[nt][0] = Bs[buf][k8 + tg][n];
                bf[nt][1] = Bs[buf][k8 + tg + 4][n];
            }
#pragma unroll
            for (int mt = 0; mt < 4; mt++)
#pragma unroll
                for (int nt = 0; nt < 8; nt++)
                    mma_tf32(acc[mt][nt], af[mt], bf[nt]);
        }
        if (st + 1 < nst) {
            const int nb = (st + 1) & 1;
#pragma unroll
            for (int c = 0; c < 4; c++) {
                const float* af = (const float*)&pa[c];
                const float* bf = (const float*)&pbv[c];
#pragma unroll
                for (int i = 0; i < 4; i++) {
                    As[nb][c * 4 + i][tid] = f2tf32(af[i]);
                    if (TB) Bs[nb][c * 4 + i][tid] = f2tf32(bf[i]);
                    else    Bs[nb][bkr][bn16 + c * 4 + i] = f2tf32(bf[i]);
                }
            }
        }
        __syncthreads();
    }

    /* ---- epilogue (mma fragment ownership: rows g/g+8, cols tg*2, tg*2+1) ---- */
#pragma unroll
    for (int mt = 0; mt < 4; mt++) {
        const int m0 = bm + warpM * 64 + mt * 16 + g;
        const int m1 = m0 + 8;
        float inv0 = 1.f, inv1 = 1.f;
        if (rscale) {
            inv0 = 1.f / rscale[(size_t)batch * M + m0];
            inv1 = 1.f / rscale[(size_t)batch * M + m1];
        }
        const float* pbr0 = nullptr;
        const float* pbr1 = nullptr;
        if (MODE == 3) {
            pbr0 = pbias + (size_t)batch * (NPn * NPn) + (size_t)(m0 >> 3) * NPn;
            pbr1 = pbias + (size_t)batch * (NPn * NPn) + (size_t)(m1 >> 3) * NPn;
        }
        float r0 = 0.f, r1 = 0.f;
#pragma unroll
        for (int nt = 0; nt < 8; nt++) {
            const int n = bn + warpN * 64 + nt * 8 + tg * 2;
            if (n < N) {
                float c0 = acc[mt][nt][0], c1 = acc[mt][nt][1];
                float c2 = acc[mt][nt][2], c3 = acc[mt][nt][3];
                if (bias) {
                    float2 bb = *(const float2*)&bias[n];
                    c0 += bb.x; c1 += bb.y; c2 += bb.x; c3 += bb.y;
                }
                if (MODE == 1) {
                    c0 = fmaxf(c0, 0.f); c1 = fmaxf(c1, 0.f);
                    c2 = fmaxf(c2, 0.f); c3 = fmaxf(c3, 0.f);
                }
                if (MODE == 3) {
                    float pb0v = pbr0[n >> 3], pb1v = pbr1[n >> 3];
                    c0 = softclamp_exp(c0 + pb0v);
                    c1 = softclamp_exp(c1 + pb0v);
                    c2 = softclamp_exp(c2 + pb1v);
                    c3 = softclamp_exp(c3 + pb1v);
                    r0 += c0 + c1; r1 += c2 + c3;
                }
                if (MODE == 4) {
                    c0 = __expf(c0); c1 = __expf(c1);
                    c2 = __expf(c2); c3 = __expf(c3);
                    r0 += c0 + c1; r1 += c2 + c3;
                }
                if (rscale) { c0 *= inv0; c1 *= inv0; c2 *= inv1; c3 *= inv1; }
                float2 w0, w1;
                if (MODE == 2) {
                    float2 o0 = *(const float2*)&C[(long long)m0 * ldc + n];
                    float2 o1 = *(const float2*)&C[(long long)m1 * ldc + n];
                    w0.x = c0 + o0.x; w0.y = c1 + o0.y;
                    w1.x = c2 + o1.x; w1.y = c3 + o1.y;
                } else {
                    w0.x = c0; w0.y = c1; w1.x = c2; w1.y = c3;
                }
                *(float2*)&C[(long long)m0 * ldc + n] = w0;
                *(float2*)&C[(long long)m1 * ldc + n] = w1;
            }
        }
        if (MODE == 3 || MODE == 4) {
            r0 += __shfl_xor_sync(0xffffffffu, r0, 1);
            r0 += __shfl_xor_sync(0xffffffffu, r0, 2);
            r1 += __shfl_xor_sync(0xffffffffu, r1, 1);
            r1 += __shfl_xor_sync(0xffffffffu, r1, 2);
            if (tg == 0) {
                atomicAdd(&rsum[(size_t)batch * M + m0], r0);
                atomicAdd(&rsum[(size_t)batch * M + m1], r1);
            }
        }
    }
}

/* ---------------- norms ---------------- */
__global__ void rmsnorm_k(const float* __restrict__ x, const float* __restrict__ w,
                          float* __restrict__ y, int cols)
{
    long long r = blockIdx.x;
    const float* xr = x + r * cols;
    float ss = 0.f;
    for (int c = threadIdx.x; c < cols; c += blockDim.x) { float v = xr[c]; ss += v * v; }
    ss = blockReduce<0>(ss);
    float inv = rsqrtf(ss / cols + EPS_RMS);
    for (int c = threadIdx.x; c < cols; c += blockDim.x)
        y[r * cols + c] = xr[c] * inv * w[c];
}

/* res += rmsnorm(x)*w1; if (w2) out = rmsnorm(res)*w2.  cols=768, 256 thr. */
__global__ void rmsnorm_add_norm_k(const float* __restrict__ x, const float* __restrict__ w1,
                                   float* __restrict__ res, const float* __restrict__ w2,
                                   float* __restrict__ out)
{
    long long r = blockIdx.x;
    const int cols = Dn;
    const float* xr = x + r * cols;
    float xv[3], rv[3];
    float ss = 0.f;
#pragma unroll
    for (int u = 0; u < 3; u++) {
        xv[u] = xr[threadIdx.x + u * 256];
        ss += xv[u] * xv[u];
    }
    ss = blockReduce<0>(ss);
    float inv = rsqrtf(ss / cols + EPS_RMS);
    float ss2 = 0.f;
#pragma unroll
    for (int u = 0; u < 3; u++) {
        int c = threadIdx.x + u * 256;
        float v = res[r * cols + c] + xv[u] * inv * w1[c];
        res[r * cols + c] = v;
        rv[u] = v;
        ss2 += v * v;
    }
    if (w2) {
        ss2 = blockReduce<0>(ss2);
        float inv2 = rsqrtf(ss2 / cols + EPS_RMS);
#pragma unroll
        for (int u = 0; u < 3; u++) {
            int c = threadIdx.x + u * 256;
            out[r * cols + c] = rv[u] * inv2 * w2[c];
        }
    }
}

/* ---------------- qkv post: per-head LayerNorm + scale + rotary ---------------- */
__global__ void qkv_post_k(const float* __restrict__ qkv,
                           const float* __restrict__ qn, const float* __restrict__ kn,
                           const float* __restrict__ vn,
                           float* __restrict__ q, float* __restrict__ k, float* __restrict__ v)
{
    int n = blockIdx.x, s = blockIdx.y, t = threadIdx.x;
    int len = (s == 9) ? 192 : 128;
    int off = (s < 8) ? s * 128 : (s == 8 ? 1024 : 1152);
    __shared__ float xs[192];
    float x = 0.f;
    if (t < len) x = qkv[(long long)n * NQKVn + off + t];
    float sum = blockReduce<0>(t < len ? x : 0.f);
    float sq  = blockReduce<0>(t < len ? x * x : 0.f);
    float mu = sum / len;
    float var = sq / len - mu * mu;
    float inv = rsqrtf(var + EPS_LN);
    float y = 0.f;
    if (t < len) {
        const float* w = (s < 8) ? qn : (s == 8 ? kn : vn);
        y = (x - mu) * inv * w[t];
        if (s < 8) y *= 0.125f;
    }
    if (s == 9) { if (t < 192) v[n * DVn + t] = y; return; }
    xs[t] = y;
    __syncthreads();
    if (t < 128) {
        int d2 = t & 63;
        float invf = (d2 == 0) ? 0.1f : 0.0f;
        float f = (float)n * invf;
        float c = cosf(f), si = sinf(f);
        float rh = (t < 64) ? -xs[t + 64] : xs[t - 64];
        float out = y * c + rh * si;
        if (s < 8) q[((size_t)s * SEQn + n) * DQKn + t] = out;
        else       k[n * DQKn + t] = out;
    }
}

/* ------------- pairwise bias: rms -> gelu -> [128->8].
   8 warps/block, 8 pairs per warp; proj preloaded in registers. ------------- */
__global__ __launch_bounds__(256) void pb_kernel(
    const float* __restrict__ pair, const float* __restrict__ rw,
    const float* __restrict__ proj, float* __restrict__ pb)
{
    const int lane = threadIdx.x & 31;
    const int warp = threadIdx.x >> 5;
    const int pair0 = (blockIdx.x * 8 + warp) * 8;
    /* preload proj rows lane*4 .. lane*4+3 (8 heads each) */
    float pr[4][8];
#pragma unroll
    for (int c = 0; c < 4; c++) {
        const float* p0 = proj + (size_t)(lane * 4 + c) * Hn;
        float4 a = *(const float4*)p0;
        float4 b = *(const float4*)(p0 + 4);
        pr[c][0] = a.x; pr[c][1] = a.y; pr[c][2] = a.z; pr[c][3] = a.w;
        pr[c][4] = b.x; pr[c][5] = b.y; pr[c][6] = b.z; pr[c][7] = b.w;
    }
    const float4 w4 = *(const float4*)(rw + lane * 4);

    for (int pp = 0; pp < 8; pp++) {
        const int idx = pair0 + pp;
        float4 x = *(const float4*)(pair + (size_t)idx * DPn + lane * 4);
        float ss = x.x * x.x + x.y * x.y + x.z * x.z + x.w * x.w;
#pragma unroll
        for (int off = 16; off > 0; off >>= 1)
            ss += __shfl_xor_sync(0xffffffffu, ss, off);
        float inv = rsqrtf(ss * (1.f / DPn) + EPS_RMS);
        float gl[4];
        {
            float y0 = x.x * inv * w4.x, y1 = x.y * inv * w4.y;
            float y2 = x.z * inv * w4.z, y3 = x.w * inv * w4.w;
            gl[0] = 0.5f * y0 * (1.f + erff(y0 * 0.70710678118654752f));
            gl[1] = 0.5f * y1 * (1.f + erff(y1 * 0.70710678118654752f));
            gl[2] = 0.5f * y2 * (1.f + erff(y2 * 0.70710678118654752f));
            gl[3] = 0.5f * y3 * (1.f + erff(y3 * 0.70710678118654752f));
        }
        float p[8] = {0.f, 0.f, 0.f, 0.f, 0.f, 0.f, 0.f, 0.f};
#pragma unroll
        for (int c = 0; c < 4; c++)
#pragma unroll
            for (int h = 0; h < 8; h++)
                p[h] = fmaf(gl[c], pr[c][h], p[h]);
#pragma unroll
        for (int off = 16; off > 0; off >>= 1)
#pragma unroll
            for (int h = 0; h < 8; h++)
                p[h] += __shfl_xor_sync(0xffffffffu, p[h], off);
        if (lane < 8) {
            float out = p[0];
#pragma unroll
            for (int h = 1; h < 8; h++) if (lane == h) out = p[h];
            int i = idx >> 8, j = idx & 255;
            pb[((size_t)lane * NPn + i) * NPn + j] = out;
        }
    }
}

/* ---------------- host launcher ---------------- */
static inline void launch_gemm(bool tb, int mode, int M, int N, int K,
                               const float* A, int lda, long long sA,
                               const float* B, int ldb, long long sB,
                               float* C, int ldc, long long sC, int batch,
                               const float* bias, const float* pbias,
                               float* rsum, const float* rscale)
{
    dim3 g((N + 127) / 128, M / 128, batch), b(128);
    if (tb) {
        if (mode == 3)      gemm_tc<true, 3><<<g, b>>>(M, N, K, A, lda, sA, B, ldb, sB, C, ldc, sC, bias, pbias, rsum, rscale);
        else if (mode == 4) gemm_tc<true, 4><<<g, b>>>(M, N, K, A, lda, sA, B, ldb, sB, C, ldc, sC, bias, pbias, rsum, rscale);
        else                gemm_tc<true, 0><<<g, b>>>(M, N, K, A, lda, sA, B, ldb, sB, C, ldc, sC, bias, pbias, rsum, rscale);
    } else {
        if (mode == 1)      gemm_tc<false, 1><<<g, b>>>(M, N, K, A, lda, sA, B, ldb, sB, C, ldc, sC, bias, pbias, rsum, rscale);
        else if (mode == 2) gemm_tc<false, 2><<<g, b>>>(M, N, K, A, lda, sA, B, ldb, sB, C, ldc, sC, bias, pbias, rsum, rscale);
        else                gemm_tc<false, 0><<<g, b>>>(M, N, K, A, lda, sA, B, ldb, sB, C, ldc, sC, bias, pbias, rsum, rscale);
    }
}

extern "C" void kernel_launch(void* const* d_in, const int* in_sizes, int n_in,
                              void* d_out, int out_size)
{
    (void)in_sizes; (void)n_in; (void)out_size;
    const float* in_single = (const float*)d_in[0];
    const float* in_pair   = (const float*)d_in[1];
    const float* W_attn_pre  = (const float*)d_in[2];
    const float* W_attn_post = (const float*)d_in[3];
    const float* W_qkv  = (const float*)d_in[4];
    const float* W_qn   = (const float*)d_in[5];
    const float* W_kn   = (const float*)d_in[6];
    const float* W_vn   = (const float*)d_in[7];
    const float* W_brms = (const float*)d_in[8];
    const float* W_bproj= (const float*)d_in[9];
    const float* W_out  = (const float*)d_in[10];
    const float* W_ffpre = (const float*)d_in[11];
    const float* W_ffpost= (const float*)d_in[12];
    const float* W_ff1  = (const float*)d_in[13];
    const float* B_ff1  = (const float*)d_in[14];
    const float* W_ff2  = (const float*)d_in[15];
    const float* B_ff2  = (const float*)d_in[16];
    const float* W_ppre = (const float*)d_in[17];
    const float* W_pqk  = (const float*)d_in[18];
    const float* W_pv   = (const float*)d_in[19];
    const float* B_pv   = (const float*)d_in[20];
    const float* W_pffpre = (const float*)d_in[21];
    const float* W_pff1 = (const float*)d_in[22];
    const float* B_pff1 = (const float*)d_in[23];
    const float* W_pff2 = (const float*)d_in[24];
    const float* B_pff2 = (const float*)d_in[25];

    float *xn, *qkv, *q, *k, *v, *sim, *pb, *ao, *t1, *rsum;
    float *pxn, *pqk, *pv, *psim, *prsum, *pt;
    cudaGetSymbolAddress((void**)&xn, g_xn);
    cudaGetSymbolAddress((void**)&qkv, g_qkv);
    cudaGetSymbolAddress((void**)&q, g_q);
    cudaGetSymbolAddress((void**)&k, g_k);
    cudaGetSymbolAddress((void**)&v, g_v);
    cudaGetSymbolAddress((void**)&sim, g_sim);
    cudaGetSymbolAddress((void**)&pb, g_pb);
    cudaGetSymbolAddress((void**)&ao, g_ao);
    cudaGetSymbolAddress((void**)&t1, g_t1);
    cudaGetSymbolAddress((void**)&rsum, g_rsum);
    cudaGetSymbolAddress((void**)&pxn, g_pxn);
    cudaGetSymbolAddress((void**)&pqk, g_pqk);
    cudaGetSymbolAddress((void**)&pv, g_pv);
    cudaGetSymbolAddress((void**)&psim, g_psim);
    cudaGetSymbolAddress((void**)&prsum, g_prsum);
    cudaGetSymbolAddress((void**)&pt, g_pt);

    /* residual streams live directly in d_out: [single | pairwise] */
    float* single = (float*)d_out;
    float* pair   = (float*)d_out + (size_t)SEQn * Dn;
    cudaMemcpyAsync(single, in_single, (size_t)SEQn * Dn * 4, cudaMemcpyDeviceToDevice);
    cudaMemcpyAsync(pair, in_pair, (size_t)NPn * NPn * DPn * 4, cudaMemcpyDeviceToDevice);

    /* xn = rmsnorm(single, attn_pre[0]) for the first layer */
    rmsnorm_k<<<SEQn, 256>>>(single, W_attn_pre, xn, Dn);

    for (int i = 0; i < 4; i++) {
        /* ---- single-track attention ---- */
        launch_gemm(false, 0, SEQn, NQKVn, Dn, xn, Dn, 0,
                    W_qkv + (long long)i * Dn * NQKVn, NQKVn, 0, qkv, NQKVn, 0, 1,
                    nullptr, nullptr, nullptr, nullptr);
        qkv_post_k<<<dim3(SEQn, 10), 192>>>(qkv, W_qn + i * DQKn, W_kn + i * DQKn,
                                            W_vn + i * DVn, q, k, v);
        pb_kernel<<<NPn * NPn / 64, 256>>>(pair, W_brms + i * DPn, W_bproj + i * DPn * Hn, pb);
        zero_k<<<(Hn * SEQn + 255) / 256, 256>>>(rsum, Hn * SEQn);
        /* P = exp(softclamp(qk^T + pb)), rowsums accumulated */
        launch_gemm(true, 3, SEQn, SEQn, DQKn, q, DQKn, (long long)SEQn * DQKn,
                    k, DQKn, 0, sim, SEQn, (long long)SEQn * SEQn, Hn,
                    nullptr, pb, rsum, nullptr);
        /* O = (P/rowsum) V */
        launch_gemm(false, 0, SEQn, DVn, SEQn, sim, SEQn, (long long)SEQn * SEQn,
                    v, DVn, 0, ao, Hn * DVn, DVn, Hn,
                    nullptr, nullptr, nullptr, rsum);
        launch_gemm(false, 0, SEQn, Dn, Hn * DVn, ao, Hn * DVn, 0,
                    W_out + (long long)i * Hn * DVn * Dn, Dn, 0, t1, Dn, 0, 1,
                    nullptr, nullptr, nullptr, nullptr);
        /* single += rms(t1)*attn_post; xn = rms(single)*ff_pre */
        rmsnorm_add_norm_k<<<SEQn, 256>>>(t1, W_attn_post + i * Dn, single,
                                          W_ffpre + i * Dn, xn);

        /* ---- single-track FF ---- */
        launch_gemm(false, 1, SEQn, FFIn, Dn, xn, Dn, 0,
                    W_ff1 + (long long)i * Dn * FFIn, FFIn, 0, ao, FFIn, 0, 1,
                    B_ff1 + i * FFIn, nullptr, nullptr, nullptr);
        launch_gemm(false, 0, SEQn, Dn, FFIn, ao, FFIn, 0,
                    W_ff2 + (long long)i * FFIn * Dn, Dn, 0, t1, Dn, 0, 1,
                    B_ff2 + i * Dn, nullptr, nullptr, nullptr);
        /* single += rms(t1)*ff_post; xn = rms(single)*attn_pre[i+1] (if any) */
        rmsnorm_add_norm_k<<<SEQn, 256>>>(t1, W_ffpost + i * Dn, single,
                                          (i < 3) ? W_attn_pre + (i + 1) * Dn : nullptr, xn);

        /* ---- pairwise track (layers 0, 2) ---- */
        if ((i & 1) == 0) {
            int j = i / 2;
            rmsnorm_k<<<NPn * NPn, 128>>>(pair, W_ppre + j * DPn, pxn, DPn);
            launch_gemm(false, 0, NPn * NPn, 2 * DPn, DPn, pxn, DPn, 0,
                        W_pqk + (long long)j * DPn * 2 * DPn, 2 * DPn, 0,
                        pqk, 2 * DPn, 0, 1, nullptr, nullptr, nullptr, nullptr);
            launch_gemm(false, 0, NPn * NPn, DPn, DPn, pxn, DPn, 0,
                        W_pv + (long long)j * DPn * DPn, DPn, 0,
                        pv, DPn, 0, 1, B_pv + j * DPn, nullptr, nullptr, nullptr);
            zero_k<<<(NPn * NPn + 255) / 256, 256>>>(prsum, NPn * NPn);
            launch_gemm(true, 4, NPn, NPn, DPn, pqk, 2 * DPn, (long long)NPn * 2 * DPn,
                        pqk + DPn, 2 * DPn, (long long)NPn * 2 * DPn,
                        psim, NPn, (long long)NPn * NPn, NPn,
                        nullptr, nullptr, prsum, nullptr);
            /* pair += (P/rowsum) V */
            launch_gemm(false, 2, NPn, DPn, NPn, psim, NPn, (long long)NPn * NPn,
                        pv, DPn, (long long)NPn * DPn,
                        pair, DPn, (long long)NPn * DPn, NPn,
                        nullptr, nullptr, nullptr, prsum);
            rmsnorm_k<<<NPn * NPn, 128>>>(pair, W_pffpre + j * DPn, pxn, DPn);
            launch_gemm(false, 1, NPn * NPn, DPIn, DPn, pxn, DPn, 0,
                        W_pff1 + (long long)j * DPn * DPIn, DPIn, 0,
                        pt, DPIn, 0, 1, B_pff1 + j * DPIn, nullptr, nullptr, nullptr);
            /* pair += ff2(pt) */
            launch_gemm(false, 2, NPn * NPn, DPn, DPIn, pt, DPIn, 0,
                        W_pff2 + (long long)j * DPIn * DPn, DPn, 0,
                        pair, DPn, 0, 1, B_pff2 + j * DPn, nullptr, nullptr, nullptr);
        }
    }
}

// round 8
// speedup vs baseline: 1.3864x; 1.3864x over previous
#include <cuda_runtime.h>
#include <math.h>

#define SEQn 2048
#define Dn   768
#define Hn   8
#define DQKn 128
#define DVn  192
#define NQKVn 1344   /* 8*128 + 128 + 192 */
#define NPn  256
#define DPn  128
#define FFIn 1536
#define DPIn 256
#define EPS_RMS 1.1920929e-07f
#define EPS_LN  1e-5f

/* ---------------- scratch (device globals; no allocation) ---------------- */
__device__ float g_xn[SEQn * Dn];
__device__ float g_qkv[SEQn * NQKVn];
__device__ float g_q[Hn * SEQn * DQKn];
__device__ float g_k[SEQn * DQKn];
__device__ float g_v[SEQn * DVn];
__device__ float g_sim[(size_t)Hn * SEQn * SEQn];      /* 134 MB */
__device__ float g_pb[Hn * NPn * NPn];
__device__ float g_ao[SEQn * Hn * DVn];
__device__ float g_t1[SEQn * FFIn];
__device__ float g_rsum[Hn * SEQn];
__device__ float g_pxn[NPn * NPn * DPn];
__device__ float g_pqk[NPn * NPn * 2 * DPn];
__device__ float g_pv[NPn * NPn * DPn];
__device__ float g_psim[(size_t)NPn * NPn * NPn];      /* 67 MB */
__device__ float g_prsum[NPn * NPn];
__device__ float g_pt[NPn * NPn * DPIn];

/* ---------------- helpers ---------------- */
__device__ __forceinline__ unsigned f2tf32(float x) {
    unsigned r;
    asm("cvt.rna.tf32.f32 %0, %1;" : "=r"(r) : "f"(x));
    return r;
}

__device__ __forceinline__ void mma_tf32(float* c, const unsigned* a, const unsigned* b) {
    asm volatile(
        "mma.sync.aligned.m16n8k8.row.col.f32.tf32.tf32.f32 "
        "{%0,%1,%2,%3}, {%4,%5,%6,%7}, {%8,%9}, {%0,%1,%2,%3};\n"
        : "+f"(c[0]), "+f"(c[1]), "+f"(c[2]), "+f"(c[3])
        : "r"(a[0]), "r"(a[1]), "r"(a[2]), "r"(a[3]), "r"(b[0]), "r"(b[1]));
}

__device__ __forceinline__ float softclamp_exp(float x) {
    float t = __expf(-0.4f * fabsf(x));
    float th = __fdividef(1.f - t, 1.f + t);
    return __expf(copysignf(5.f * th, x));
}

template <int OP>
__device__ __forceinline__ float blockReduce(float v) {
    __shared__ float s[33];
    int lane = threadIdx.x & 31, wid = threadIdx.x >> 5;
#pragma unroll
    for (int o = 16; o > 0; o >>= 1) {
        float ov = __shfl_down_sync(0xffffffffu, v, o);
        v = (OP == 0) ? (v + ov) : fmaxf(v, ov);
    }
    if (lane == 0) s[wid] = v;
    __syncthreads();
    if (threadIdx.x == 0) {
        int nw = (blockDim.x + 31) >> 5;
        float r = s[0];
        for (int i = 1; i < nw; i++) r = (OP == 0) ? (r + s[i]) : fmaxf(r, s[i]);
        s[32] = r;
    }
    __syncthreads();
    float r = s[32];
    __syncthreads();
    return r;
}

__global__ void zero_k(float* p, int n)
{
    int i = blockIdx.x * blockDim.x + threadIdx.x;
    if (i < n) p[i] = 0.f;
}

/* ---------------- TF32 tensor-core GEMM, 128x128 CTA, BK=16, dbl-buffered.
   8 warps, 64x32 warp tiles (Round-6 proven config).
   MODE: 0 plain(+bias), 1 relu(+bias), 2 accumulate into C(+bias),
         3 sim softmax: exp(softclamp(x+pb)) + atomic row sums,
         4 pair softmax: exp(x) + atomic row sums.
   rscale (optional): multiply output rows by 1/rscale[batch*M+m].
   Requires M % 128 == 0, K % 16 == 0 (N guarded).                         */
template <bool TB, int MODE>
__global__ __launch_bounds__(256) void gemm_tc(
    int M, int N, int K,
    const float* __restrict__ A, int lda, long long sA,
    const float* __restrict__ B, int ldb, long long sB,
    float* __restrict__ C, int ldc, long long sC,
    const float* __restrict__ bias,
    const float* __restrict__ pbias,
    float* __restrict__ rsum,
    const float* __restrict__ rscale)
{
    __shared__ unsigned As[2][16][136];   /* stride 136 ≡ 8 mod 32: frag loads conflict-free */
    __shared__ unsigned Bs[2][16][136];
    const int batch = blockIdx.z;
    A += (long long)batch * sA;
    B += (long long)batch * sB;
    C += (long long)batch * sC;
    const int bm = blockIdx.y * 128, bn = blockIdx.x * 128;
    const int tid = threadIdx.x;
    const int lane = tid & 31, warp = tid >> 5;
    const int g = lane >> 2, tg = lane & 3;
    const int warpM = warp & 1, warpN = warp >> 1;   /* 2 x 4 warps -> 64 x 32 tiles */

    /* staging maps */
    const int arow = tid >> 1, ak8 = (tid & 1) * 8;          /* A: 128 rows x 16 k */
    const float* Aptr = A + (long long)(bm + arow) * lda + ak8;
    const int brow = tid >> 1, bk8 = (tid & 1) * 8;          /* TB:  n-row, k segment */
    const int bkr = tid >> 4, bn8 = (tid & 15) * 8;          /* !TB: k-row, n segment */
    const bool bval_t  = TB ? (bn + brow < N) : true;
    const bool bval_n0 = TB ? true : (bn + bn8 < N);
    const bool bval_n1 = TB ? true : (bn + bn8 + 4 < N);
    const float4 f0 = make_float4(0.f, 0.f, 0.f, 0.f);

    float4 pa0, pa1, pb0, pb1;
    /* prefetch stage 0 */
    {
        pa0 = *(const float4*)(Aptr);
        pa1 = *(const float4*)(Aptr + 4);
        if (TB) {
            pb0 = bval_t ? *(const float4*)(B + (long long)(bn + brow) * ldb + bk8) : f0;
            pb1 = bval_t ? *(const float4*)(B + (long long)(bn + brow) * ldb + bk8 + 4) : f0;
        } else {
            pb0 = bval_n0 ? *(const float4*)(B + (long long)bkr * ldb + bn + bn8) : f0;
            pb1 = bval_n1 ? *(const float4*)(B + (long long)bkr * ldb + bn + bn8 + 4) : f0;
        }
    }
    /* store stage 0 */
    {
        const float* af = (const float*)&pa0;
#pragma unroll
        for (int i = 0; i < 4; i++) As[0][ak8 + i][arow] = f2tf32(af[i]);
        af = (const float*)&pa1;
#pragma unroll
        for (int i = 0; i < 4; i++) As[0][ak8 + 4 + i][arow] = f2tf32(af[i]);
        if (TB) {
            const float* bf = (const float*)&pb0;
#pragma unroll
            for (int i = 0; i < 4; i++) Bs[0][bk8 + i][brow] = f2tf32(bf[i]);
            bf = (const float*)&pb1;
#pragma unroll
            for (int i = 0; i < 4; i++) Bs[0][bk8 + 4 + i][brow] = f2tf32(bf[i]);
        } else {
            const float* bf = (const float*)&pb0;
#pragma unroll
            for (int i = 0; i < 4; i++) Bs[0][bkr][bn8 + i] = f2tf32(bf[i]);
            bf = (const float*)&pb1;
#pragma unroll
            for (int i = 0; i < 4; i++) Bs[0][bkr][bn8 + 4 + i] = f2tf32(bf[i]);
        }
    }
    __syncthreads();

    float acc[4][4][4];
#pragma unroll
    for (int mt = 0; mt < 4; mt++)
#pragma unroll
        for (int nt = 0; nt < 4; nt++)
#pragma unroll
            for (int u = 0; u < 4; u++) acc[mt][nt][u] = 0.f;

    const int nst = K >> 4;
    for (int st = 0; st < nst; st++) {
        if (st + 1 < nst) {
            int kb = (st + 1) << 4;
            pa0 = *(const float4*)(Aptr + kb);
            pa1 = *(const float4*)(Aptr + kb + 4);
            if (TB) {
                pb0 = bval_t ? *(const float4*)(B + (long long)(bn + brow) * ldb + kb + bk8) : f0;
                pb1 = bval_t ? *(const float4*)(B + (long long)(bn + brow) * ldb + kb + bk8 + 4) : f0;
            } else {
                pb0 = bval_n0 ? *(const float4*)(B + (long long)(kb + bkr) * ldb + bn + bn8) : f0;
                pb1 = bval_n1 ? *(const float4*)(B + (long long)(kb + bkr) * ldb + bn + bn8 + 4) : f0;
            }
        }
        const int buf = st & 1;
#pragma unroll
        for (int ks = 0; ks < 2; ks++) {
            const int k8 = ks * 8;
            unsigned af[4][4], bf[4][2];
#pragma unroll
            for (int mt = 0; mt < 4; mt++) {
                int m = warpM * 64 + mt * 16 + g;
                af[mt][0] = As[buf][k8 + tg][m];
                af[mt][1] = As[buf][k8 + tg][m + 8];
                af[mt][2] = As[buf][k8 + tg + 4][m];
                af[mt][3] = As[buf][k8 + tg + 4][m + 8];
            }
#pragma unroll
            for (int nt = 0; nt < 4; nt++) {
                int n = warpN * 32 + nt * 8 + g;
                bf[nt][0] = Bs[buf][k8 + tg][n];
                bf[nt][1] = Bs[buf][k8 + tg + 4][n];
            }
#pragma unroll
            for (int mt = 0; mt < 4; mt++)
#pragma unroll
                for (int nt = 0; nt < 4; nt++)
                    mma_tf32(acc[mt][nt], af[mt], bf[nt]);
        }
        if (st + 1 < nst) {
            const int nb = (st + 1) & 1;
            const float* af = (const float*)&pa0;
#pragma unroll
            for (int i = 0; i < 4; i++) As[nb][ak8 + i][arow] = f2tf32(af[i]);
            af = (const float*)&pa1;
#pragma unroll
            for (int i = 0; i < 4; i++) As[nb][ak8 + 4 + i][arow] = f2tf32(af[i]);
            if (TB) {
                const float* bfp = (const float*)&pb0;
#pragma unroll
                for (int i = 0; i < 4; i++) Bs[nb][bk8 + i][brow] = f2tf32(bfp[i]);
                bfp = (const float*)&pb1;
#pragma unroll
                for (int i = 0; i < 4; i++) Bs[nb][bk8 + 4 + i][brow] = f2tf32(bfp[i]);
            } else {
                const float* bfp = (const float*)&pb0;
#pragma unroll
                for (int i = 0; i < 4; i++) Bs[nb][bkr][bn8 + i] = f2tf32(bfp[i]);
                bfp = (const float*)&pb1;
#pragma unroll
                for (int i = 0; i < 4; i++) Bs[nb][bkr][bn8 + 4 + i] = f2tf32(bfp[i]);
            }
        }
        __syncthreads();
    }

    /* ---- epilogue (mma fragment ownership: rows g/g+8, cols tg*2, tg*2+1) ---- */
#pragma unroll
    for (int mt = 0; mt < 4; mt++) {
        const int m0 = bm + warpM * 64 + mt * 16 + g;
        const int m1 = m0 + 8;
        float inv0 = 1.f, inv1 = 1.f;
        if (rscale) {
            inv0 = 1.f / rscale[(size_t)batch * M + m0];
            inv1 = 1.f / rscale[(size_t)batch * M + m1];
        }
        const float* pbr0 = nullptr;
        const float* pbr1 = nullptr;
        if (MODE == 3) {
            pbr0 = pbias + (size_t)batch * (NPn * NPn) + (size_t)(m0 >> 3) * NPn;
            pbr1 = pbias + (size_t)batch * (NPn * NPn) + (size_t)(m1 >> 3) * NPn;
        }
        float r0 = 0.f, r1 = 0.f;
#pragma unroll
        for (int nt = 0; nt < 4; nt++) {
            const int n = bn + warpN * 32 + nt * 8 + tg * 2;
            if (n < N) {
                float c0 = acc[mt][nt][0], c1 = acc[mt][nt][1];
                float c2 = acc[mt][nt][2], c3 = acc[mt][nt][3];
                if (bias) {
                    float2 bb = *(const float2*)&bias[n];
                    c0 += bb.x; c1 += bb.y; c2 += bb.x; c3 += bb.y;
                }
                if (MODE == 1) {
                    c0 = fmaxf(c0, 0.f); c1 = fmaxf(c1, 0.f);
                    c2 = fmaxf(c2, 0.f); c3 = fmaxf(c3, 0.f);
                }
                if (MODE == 3) {
                    float pb0v = pbr0[n >> 3], pb1v = pbr1[n >> 3];
                    c0 = softclamp_exp(c0 + pb0v);
                    c1 = softclamp_exp(c1 + pb0v);
                    c2 = softclamp_exp(c2 + pb1v);
                    c3 = softclamp_exp(c3 + pb1v);
                    r0 += c0 + c1; r1 += c2 + c3;
                }
                if (MODE == 4) {
                    c0 = __expf(c0); c1 = __expf(c1);
                    c2 = __expf(c2); c3 = __expf(c3);
                    r0 += c0 + c1; r1 += c2 + c3;
                }
                if (rscale) { c0 *= inv0; c1 *= inv0; c2 *= inv1; c3 *= inv1; }
                float2 w0, w1;
                if (MODE == 2) {
                    float2 o0 = *(const float2*)&C[(long long)m0 * ldc + n];
                    float2 o1 = *(const float2*)&C[(long long)m1 * ldc + n];
                    w0.x = c0 + o0.x; w0.y = c1 + o0.y;
                    w1.x = c2 + o1.x; w1.y = c3 + o1.y;
                } else {
                    w0.x = c0; w0.y = c1; w1.x = c2; w1.y = c3;
                }
                *(float2*)&C[(long long)m0 * ldc + n] = w0;
                *(float2*)&C[(long long)m1 * ldc + n] = w1;
            }
        }
        if (MODE == 3 || MODE == 4) {
            r0 += __shfl_xor_sync(0xffffffffu, r0, 1);
            r0 += __shfl_xor_sync(0xffffffffu, r0, 2);
            r1 += __shfl_xor_sync(0xffffffffu, r1, 1);
            r1 += __shfl_xor_sync(0xffffffffu, r1, 2);
            if (tg == 0) {
                atomicAdd(&rsum[(size_t)batch * M + m0], r0);
                atomicAdd(&rsum[(size_t)batch * M + m1], r1);
            }
        }
    }
}

/* ---------------- norms ---------------- */
__global__ void rmsnorm_k(const float* __restrict__ x, const float* __restrict__ w,
                          float* __restrict__ y, int cols)
{
    long long r = blockIdx.x;
    const float* xr = x + r * cols;
    float ss = 0.f;
    for (int c = threadIdx.x; c < cols; c += blockDim.x) { float v = xr[c]; ss += v * v; }
    ss = blockReduce<0>(ss);
    float inv = rsqrtf(ss / cols + EPS_RMS);
    for (int c = threadIdx.x; c < cols; c += blockDim.x)
        y[r * cols + c] = xr[c] * inv * w[c];
}

/* res += rmsnorm(x)*w1; if (w2) out = rmsnorm(res)*w2.  cols=768, 256 thr. */
__global__ void rmsnorm_add_norm_k(const float* __restrict__ x, const float* __restrict__ w1,
                                   float* __restrict__ res, const float* __restrict__ w2,
                                   float* __restrict__ out)
{
    long long r = blockIdx.x;
    const int cols = Dn;
    const float* xr = x + r * cols;
    float xv[3], rv[3];
    float ss = 0.f;
#pragma unroll
    for (int u = 0; u < 3; u++) {
        xv[u] = xr[threadIdx.x + u * 256];
        ss += xv[u] * xv[u];
    }
    ss = blockReduce<0>(ss);
    float inv = rsqrtf(ss / cols + EPS_RMS);
    float ss2 = 0.f;
#pragma unroll
    for (int u = 0; u < 3; u++) {
        int c = threadIdx.x + u * 256;
        float v = res[r * cols + c] + xv[u] * inv * w1[c];
        res[r * cols + c] = v;
        rv[u] = v;
        ss2 += v * v;
    }
    if (w2) {
        ss2 = blockReduce<0>(ss2);
        float inv2 = rsqrtf(ss2 / cols + EPS_RMS);
#pragma unroll
        for (int u = 0; u < 3; u++) {
            int c = threadIdx.x + u * 256;
            out[r * cols + c] = rv[u] * inv2 * w2[c];
        }
    }
}

/* ---------------- qkv post: per-head LayerNorm + scale + rotary ---------------- */
__global__ void qkv_post_k(const float* __restrict__ qkv,
                           const float* __restrict__ qn, const float* __restrict__ kn,
                           const float* __restrict__ vn,
                           float* __restrict__ q, float* __restrict__ k, float* __restrict__ v)
{
    int n = blockIdx.x, s = blockIdx.y, t = threadIdx.x;
    int len = (s == 9) ? 192 : 128;
    int off = (s < 8) ? s * 128 : (s == 8 ? 1024 : 1152);
    __shared__ float xs[192];
    float x = 0.f;
    if (t < len) x = qkv[(long long)n * NQKVn + off + t];
    float sum = blockReduce<0>(t < len ? x : 0.f);
    float sq  = blockReduce<0>(t < len ? x * x : 0.f);
    float mu = sum / len;
    float var = sq / len - mu * mu;
    float inv = rsqrtf(var + EPS_LN);
    float y = 0.f;
    if (t < len) {
        const float* w = (s < 8) ? qn : (s == 8 ? kn : vn);
        y = (x - mu) * inv * w[t];
        if (s < 8) y *= 0.125f;
    }
    if (s == 9) { if (t < 192) v[n * DVn + t] = y; return; }
    xs[t] = y;
    __syncthreads();
    if (t < 128) {
        int d2 = t & 63;
        float invf = (d2 == 0) ? 0.1f : 0.0f;
        float f = (float)n * invf;
        float c = cosf(f), si = sinf(f);
        float rh = (t < 64) ? -xs[t + 64] : xs[t - 64];
        float out = y * c + rh * si;
        if (s < 8) q[((size_t)s * SEQn + n) * DQKn + t] = out;
        else       k[n * DQKn + t] = out;
    }
}

/* ------------- pairwise bias: rms -> gelu -> [128->8].
   8 warps/block, 8 pairs per warp; proj preloaded in registers. ------------- */
__global__ __launch_bounds__(256) void pb_kernel(
    const float* __restrict__ pair, const float* __restrict__ rw,
    const float* __restrict__ proj, float* __restrict__ pb)
{
    const int lane = threadIdx.x & 31;
    const int warp = threadIdx.x >> 5;
    const int pair0 = (blockIdx.x * 8 + warp) * 8;
    /* preload proj rows lane*4 .. lane*4+3 (8 heads each) */
    float pr[4][8];
#pragma unroll
    for (int c = 0; c < 4; c++) {
        const float* p0 = proj + (size_t)(lane * 4 + c) * Hn;
        float4 a = *(const float4*)p0;
        float4 b = *(const float4*)(p0 + 4);
        pr[c][0] = a.x; pr[c][1] = a.y; pr[c][2] = a.z; pr[c][3] = a.w;
        pr[c][4] = b.x; pr[c][5] = b.y; pr[c][6] = b.z; pr[c][7] = b.w;
    }
    const float4 w4 = *(const float4*)(rw + lane * 4);

    for (int pp = 0; pp < 8; pp++) {
        const int idx = pair0 + pp;
        float4 x = *(const float4*)(pair + (size_t)idx * DPn + lane * 4);
        float ss = x.x * x.x + x.y * x.y + x.z * x.z + x.w * x.w;
#pragma unroll
        for (int off = 16; off > 0; off >>= 1)
            ss += __shfl_xor_sync(0xffffffffu, ss, off);
        float inv = rsqrtf(ss * (1.f / DPn) + EPS_RMS);
        float gl[4];
        {
            float y0 = x.x * inv * w4.x, y1 = x.y * inv * w4.y;
            float y2 = x.z * inv * w4.z, y3 = x.w * inv * w4.w;
            gl[0] = 0.5f * y0 * (1.f + erff(y0 * 0.70710678118654752f));
            gl[1] = 0.5f * y1 * (1.f + erff(y1 * 0.70710678118654752f));
            gl[2] = 0.5f * y2 * (1.f + erff(y2 * 0.70710678118654752f));
            gl[3] = 0.5f * y3 * (1.f + erff(y3 * 0.70710678118654752f));
        }
        float p[8] = {0.f, 0.f, 0.f, 0.f, 0.f, 0.f, 0.f, 0.f};
#pragma unroll
        for (int c = 0; c < 4; c++)
#pragma unroll
            for (int h = 0; h < 8; h++)
                p[h] = fmaf(gl[c], pr[c][h], p[h]);
#pragma unroll
        for (int off = 16; off > 0; off >>= 1)
#pragma unroll
            for (int h = 0; h < 8; h++)
                p[h] += __shfl_xor_sync(0xffffffffu, p[h], off);
        if (lane < 8) {
            float out = p[0];
#pragma unroll
            for (int h = 1; h < 8; h++) if (lane == h) out = p[h];
            int i = idx >> 8, j = idx & 255;
            pb[((size_t)lane * NPn + i) * NPn + j] = out;
        }
    }
}

/* ---------------- host launcher ---------------- */
static inline void launch_gemm(bool tb, int mode, int M, int N, int K,
                               const float* A, int lda, long long sA,
                               const float* B, int ldb, long long sB,
                               float* C, int ldc, long long sC, int batch,
                               const float* bias, const float* pbias,
                               float* rsum, const float* rscale)
{
    dim3 g((N + 127) / 128, M / 128, batch), b(256);
    if (tb) {
        if (mode == 3)      gemm_tc<true, 3><<<g, b>>>(M, N, K, A, lda, sA, B, ldb, sB, C, ldc, sC, bias, pbias, rsum, rscale);
        else if (mode == 4) gemm_tc<true, 4><<<g, b>>>(M, N, K, A, lda, sA, B, ldb, sB, C, ldc, sC, bias, pbias, rsum, rscale);
        else                gemm_tc<true, 0><<<g, b>>>(M, N, K, A, lda, sA, B, ldb, sB, C, ldc, sC, bias, pbias, rsum, rscale);
    } else {
        if (mode == 1)      gemm_tc<false, 1><<<g, b>>>(M, N, K, A, lda, sA, B, ldb, sB, C, ldc, sC, bias, pbias, rsum, rscale);
        else if (mode == 2) gemm_tc<false, 2><<<g, b>>>(M, N, K, A, lda, sA, B, ldb, sB, C, ldc, sC, bias, pbias, rsum, rscale);
        else                gemm_tc<false, 0><<<g, b>>>(M, N, K, A, lda, sA, B, ldb, sB, C, ldc, sC, bias, pbias, rsum, rscale);
    }
}

extern "C" void kernel_launch(void* const* d_in, const int* in_sizes, int n_in,
                              void* d_out, int out_size)
{
    (void)in_sizes; (void)n_in; (void)out_size;
    const float* in_single = (const float*)d_in[0];
    const float* in_pair   = (const float*)d_in[1];
    const float* W_attn_pre  = (const float*)d_in[2];
    const float* W_attn_post = (const float*)d_in[3];
    const float* W_qkv  = (const float*)d_in[4];
    const float* W_qn   = (const float*)d_in[5];
    const float* W_kn   = (const float*)d_in[6];
    const float* W_vn   = (const float*)d_in[7];
    const float* W_brms = (const float*)d_in[8];
    const float* W_bproj= (const float*)d_in[9];
    const float* W_out  = (const float*)d_in[10];
    const float* W_ffpre = (const float*)d_in[11];
    const float* W_ffpost= (const float*)d_in[12];
    const float* W_ff1  = (const float*)d_in[13];
    const float* B_ff1  = (const float*)d_in[14];
    const float* W_ff2  = (const float*)d_in[15];
    const float* B_ff2  = (const float*)d_in[16];
    const float* W_ppre = (const float*)d_in[17];
    const float* W_pqk  = (const float*)d_in[18];
    const float* W_pv   = (const float*)d_in[19];
    const float* B_pv   = (const float*)d_in[20];
    const float* W_pffpre = (const float*)d_in[21];
    const float* W_pff1 = (const float*)d_in[22];
    const float* B_pff1 = (const float*)d_in[23];
    const float* W_pff2 = (const float*)d_in[24];
    const float* B_pff2 = (const float*)d_in[25];

    float *xn, *qkv, *q, *k, *v, *sim, *pb, *ao, *t1, *rsum;
    float *pxn, *pqk, *pv, *psim, *prsum, *pt;
    cudaGetSymbolAddress((void**)&xn, g_xn);
    cudaGetSymbolAddress((void**)&qkv, g_qkv);
    cudaGetSymbolAddress((void**)&q, g_q);
    cudaGetSymbolAddress((void**)&k, g_k);
    cudaGetSymbolAddress((void**)&v, g_v);
    cudaGetSymbolAddress((void**)&sim, g_sim);
    cudaGetSymbolAddress((void**)&pb, g_pb);
    cudaGetSymbolAddress((void**)&ao, g_ao);
    cudaGetSymbolAddress((void**)&t1, g_t1);
    cudaGetSymbolAddress((void**)&rsum, g_rsum);
    cudaGetSymbolAddress((void**)&pxn, g_pxn);
    cudaGetSymbolAddress((void**)&pqk, g_pqk);
    cudaGetSymbolAddress((void**)&pv, g_pv);
    cudaGetSymbolAddress((void**)&psim, g_psim);
    cudaGetSymbolAddress((void**)&prsum, g_prsum);
    cudaGetSymbolAddress((void**)&pt, g_pt);

    /* residual streams live directly in d_out: [single | pairwise] */
    float* single = (float*)d_out;
    float* pair   = (float*)d_out + (size_t)SEQn * Dn;
    cudaMemcpyAsync(single, in_single, (size_t)SEQn * Dn * 4, cudaMemcpyDeviceToDevice);
    cudaMemcpyAsync(pair, in_pair, (size_t)NPn * NPn * DPn * 4, cudaMemcpyDeviceToDevice);

    /* xn = rmsnorm(single, attn_pre[0]) for the first layer */
    rmsnorm_k<<<SEQn, 256>>>(single, W_attn_pre, xn, Dn);

    for (int i = 0; i < 4; i++) {
        /* ---- single-track attention ---- */
        launch_gemm(false, 0, SEQn, NQKVn, Dn, xn, Dn, 0,
                    W_qkv + (long long)i * Dn * NQKVn, NQKVn, 0, qkv, NQKVn, 0, 1,
                    nullptr, nullptr, nullptr, nullptr);
        qkv_post_k<<<dim3(SEQn, 10), 192>>>(qkv, W_qn + i * DQKn, W_kn + i * DQKn,
                                            W_vn + i * DVn, q, k, v);
        pb_kernel<<<NPn * NPn / 64, 256>>>(pair, W_brms + i * DPn, W_bproj + i * DPn * Hn, pb);
        zero_k<<<(Hn * SEQn + 255) / 256, 256>>>(rsum, Hn * SEQn);
        /* P = exp(softclamp(qk^T + pb)), rowsums accumulated */
        launch_gemm(true, 3, SEQn, SEQn, DQKn, q, DQKn, (long long)SEQn * DQKn,
                    k, DQKn, 0, sim, SEQn, (long long)SEQn * SEQn, Hn,
                    nullptr, pb, rsum, nullptr);
        /* O = (P/rowsum) V */
        launch_gemm(false, 0, SEQn, DVn, SEQn, sim, SEQn, (long long)SEQn * SEQn,
                    v, DVn, 0, ao, Hn * DVn, DVn, Hn,
                    nullptr, nullptr, nullptr, rsum);
        launch_gemm(false, 0, SEQn, Dn, Hn * DVn, ao, Hn * DVn, 0,
                    W_out + (long long)i * Hn * DVn * Dn, Dn, 0, t1, Dn, 0, 1,
                    nullptr, nullptr, nullptr, nullptr);
        /* single += rms(t1)*attn_post; xn = rms(single)*ff_pre */
        rmsnorm_add_norm_k<<<SEQn, 256>>>(t1, W_attn_post + i * Dn, single,
                                          W_ffpre + i * Dn, xn);

        /* ---- single-track FF ---- */
        launch_gemm(false, 1, SEQn, FFIn, Dn, xn, Dn, 0,
                    W_ff1 + (long long)i * Dn * FFIn, FFIn, 0, ao, FFIn, 0, 1,
                    B_ff1 + i * FFIn, nullptr, nullptr, nullptr);
        launch_gemm(false, 0, SEQn, Dn, FFIn, ao, FFIn, 0,
                    W_ff2 + (long long)i * FFIn * Dn, Dn, 0, t1, Dn, 0, 1,
                    B_ff2 + i * Dn, nullptr, nullptr, nullptr);
        /* single += rms(t1)*ff_post; xn = rms(single)*attn_pre[i+1] (if any) */
        rmsnorm_add_norm_k<<<SEQn, 256>>>(t1, W_ffpost + i * Dn, single,
                                          (i < 3) ? W_attn_pre + (i + 1) * Dn : nullptr, xn);

        /* ---- pairwise track (layers 0, 2) ---- */
        if ((i & 1) == 0) {
            int j = i / 2;
            rmsnorm_k<<<NPn * NPn, 128>>>(pair, W_ppre + j * DPn, pxn, DPn);
            launch_gemm(false, 0, NPn * NPn, 2 * DPn, DPn, pxn, DPn, 0,
                        W_pqk + (long long)j * DPn * 2 * DPn, 2 * DPn, 0,
                        pqk, 2 * DPn, 0, 1, nullptr, nullptr, nullptr, nullptr);
            launch_gemm(false, 0, NPn * NPn, DPn, DPn, pxn, DPn, 0,
                        W_pv + (long long)j * DPn * DPn, DPn, 0,
                        pv, DPn, 0, 1, B_pv + j * DPn, nullptr, nullptr, nullptr);
            zero_k<<<(NPn * NPn + 255) / 256, 256>>>(prsum, NPn * NPn);
            launch_gemm(true, 4, NPn, NPn, DPn, pqk, 2 * DPn, (long long)NPn * 2 * DPn,
                        pqk + DPn, 2 * DPn, (long long)NPn * 2 * DPn,
                        psim, NPn, (long long)NPn * NPn, NPn,
                        nullptr, nullptr, prsum, nullptr);
            /* pair += (P/rowsum) V */
            launch_gemm(false, 2, NPn, DPn, NPn, psim, NPn, (long long)NPn * NPn,
                        pv, DPn, (long long)NPn * DPn,
                        pair, DPn, (long long)NPn * DPn, NPn,
                        nullptr, nullptr, nullptr, prsum);
            rmsnorm_k<<<NPn * NPn, 128>>>(pair, W_pffpre + j * DPn, pxn, DPn);
            launch_gemm(false, 1, NPn * NPn, DPIn, DPn, pxn, DPn, 0,
                        W_pff1 + (long long)j * DPn * DPIn, DPIn, 0,
                        pt, DPIn, 0, 1, B_pff1 + j * DPIn, nullptr, nullptr, nullptr);
            /* pair += ff2(pt) */
            launch_gemm(false, 2, NPn * NPn, DPn, DPIn, pt, DPIn, 0,
                        W_pff2 + (long long)j * DPIn * DPn, DPn, 0,
                        pair, DPn, 0, 1, B_pff2 + j * DPn, nullptr, nullptr, nullptr);
        }
    }
}

// round 9
// speedup vs baseline: 1.4385x; 1.0376x over previous
#include <cuda_runtime.h>
#include <math.h>

#define SEQn 2048
#define Dn   768
#define Hn   8
#define DQKn 128
#define DVn  192
#define NQKVn 1344   /* 8*128 + 128 + 192 */
#define NPn  256
#define DPn  128
#define FFIn 1536
#define DPIn 256
#define EPS_RMS 1.1920929e-07f
#define EPS_LN  1e-5f

/* ---------------- scratch (device globals; no allocation) ---------------- */
__device__ float g_xn[SEQn * Dn];
__device__ float g_qkv[SEQn * NQKVn];
__device__ float g_q[Hn * SEQn * DQKn];
__device__ float g_k[SEQn * DQKn];
__device__ float g_v[SEQn * DVn];
__device__ float g_sim[(size_t)Hn * SEQn * SEQn];      /* 134 MB */
__device__ float g_pb[Hn * NPn * NPn];
__device__ float g_ao[SEQn * Hn * DVn];
__device__ float g_t1[SEQn * FFIn];
__device__ float g_rsum[Hn * SEQn];
__device__ float g_pxn[NPn * NPn * DPn];
__device__ float g_pqk[NPn * NPn * 2 * DPn];
__device__ float g_pv[NPn * NPn * DPn];
__device__ float g_psim[(size_t)NPn * NPn * NPn];      /* 67 MB */
__device__ float g_prsum[NPn * NPn];
__device__ float g_pt[NPn * NPn * DPIn];

/* ---------------- helpers ---------------- */
__device__ __forceinline__ unsigned f2tf32(float x) {
    unsigned r;
    asm("cvt.rna.tf32.f32 %0, %1;" : "=r"(r) : "f"(x));
    return r;
}

__device__ __forceinline__ void mma_tf32(float* c, const unsigned* a, const unsigned* b) {
    asm volatile(
        "mma.sync.aligned.m16n8k8.row.col.f32.tf32.tf32.f32 "
        "{%0,%1,%2,%3}, {%4,%5,%6,%7}, {%8,%9}, {%0,%1,%2,%3};\n"
        : "+f"(c[0]), "+f"(c[1]), "+f"(c[2]), "+f"(c[3])
        : "r"(a[0]), "r"(a[1]), "r"(a[2]), "r"(a[3]), "r"(b[0]), "r"(b[1]));
}

__device__ __forceinline__ float softclamp_exp(float x) {
    float t = __expf(-0.4f * fabsf(x));
    float th = __fdividef(1.f - t, 1.f + t);
    return __expf(copysignf(5.f * th, x));
}

template <int OP>
__device__ __forceinline__ float blockReduce(float v) {
    __shared__ float s[33];
    int lane = threadIdx.x & 31, wid = threadIdx.x >> 5;
#pragma unroll
    for (int o = 16; o > 0; o >>= 1) {
        float ov = __shfl_down_sync(0xffffffffu, v, o);
        v = (OP == 0) ? (v + ov) : fmaxf(v, ov);
    }
    if (lane == 0) s[wid] = v;
    __syncthreads();
    if (threadIdx.x == 0) {
        int nw = (blockDim.x + 31) >> 5;
        float r = s[0];
        for (int i = 1; i < nw; i++) r = (OP == 0) ? (r + s[i]) : fmaxf(r, s[i]);
        s[32] = r;
    }
    __syncthreads();
    float r = s[32];
    __syncthreads();
    return r;
}

/* combined sum reduction of two values (one sync round); block <= 8 warps-1 */
__device__ __forceinline__ float2 blockReduce2(float a, float b) {
    __shared__ float sa[8], sb[8];
    int lane = threadIdx.x & 31, wid = threadIdx.x >> 5;
#pragma unroll
    for (int o = 16; o > 0; o >>= 1) {
        a += __shfl_down_sync(0xffffffffu, a, o);
        b += __shfl_down_sync(0xffffffffu, b, o);
    }
    if (lane == 0) { sa[wid] = a; sb[wid] = b; }
    __syncthreads();
    if (threadIdx.x == 0) {
        int nw = (blockDim.x + 31) >> 5;
        float ra = sa[0], rb = sb[0];
        for (int i = 1; i < nw; i++) { ra += sa[i]; rb += sb[i]; }
        sa[7] = ra; sb[7] = rb;
    }
    __syncthreads();
    float2 r = make_float2(sa[7], sb[7]);
    __syncthreads();
    return r;
}

__global__ void zero_k(float* p, int n)
{
    int i = blockIdx.x * blockDim.x + threadIdx.x;
    if (i < n) p[i] = 0.f;
}

/* ---------------- TF32 tensor-core GEMM, 128 x (NT*32) CTA, BK=16, dbl-buf.
   8 warps in 2 x 4 grid; warp tile 64 x (NT*8). NT=4 -> CTA 128x128 (std),
   NT=6 -> CTA 128x192 (AV exact fit).
   MODE: 0 plain(+bias), 1 relu(+bias), 2 accumulate into C(+bias),
         3 sim softmax: exp(softclamp(x+pb)) + atomic row sums,
         4 pair softmax: exp(x) + atomic row sums.
   rscale (optional): multiply output rows by 1/rscale[batch*M+m].
   Requires M % 128 == 0, K % 16 == 0 (N guarded). TB only with NT=4.       */
template <bool TB, int MODE, int NT>
__global__ __launch_bounds__(256) void gemm_tc(
    int M, int N, int K,
    const float* __restrict__ A, int lda, long long sA,
    const float* __restrict__ B, int ldb, long long sB,
    float* __restrict__ C, int ldc, long long sC,
    const float* __restrict__ bias,
    const float* __restrict__ pbias,
    float* __restrict__ rsum,
    const float* __restrict__ rscale)
{
    constexpr int BN = NT * 32;
    constexpr int BNP = BN + 8;          /* ≡ 8 mod 32: conflict-free frags */
    constexpr int NCH = NT / 2;          /* float4 staging chunks (!TB)     */
    __shared__ unsigned As[2][16][136];
    __shared__ unsigned Bs[2][16][BNP];
    const int batch = blockIdx.z;
    A += (long long)batch * sA;
    B += (long long)batch * sB;
    C += (long long)batch * sC;
    const int bm = blockIdx.y * 128, bn = blockIdx.x * BN;
    const int tid = threadIdx.x;
    const int lane = tid & 31, warp = tid >> 5;
    const int g = lane >> 2, tg = lane & 3;
    const int warpM = warp & 1, warpN = warp >> 1;

    /* staging maps */
    const int arow = tid >> 1, ak8 = (tid & 1) * 8;          /* A: 128 rows x 16 k */
    const float* Aptr = A + (long long)(bm + arow) * lda + ak8;
    const int brow = tid >> 1, bk8 = (tid & 1) * 8;          /* TB:  n-row, k segment */
    const int bkr = tid >> 4, bnc = (tid & 15) * (2 * NT);   /* !TB: k-row, n segment */
    const bool bvt = TB ? (bn + brow < N) : true;
    bool bvn[NCH];
#pragma unroll
    for (int c = 0; c < NCH; c++) bvn[c] = TB ? true : (bn + bnc + 4 * c < N);
    const float4 f0 = make_float4(0.f, 0.f, 0.f, 0.f);

    float4 pa0, pa1, pbv[NCH];
    /* prefetch stage 0 */
    {
        pa0 = *(const float4*)(Aptr);
        pa1 = *(const float4*)(Aptr + 4);
        if (TB) {
            pbv[0] = bvt ? *(const float4*)(B + (long long)(bn + brow) * ldb + bk8) : f0;
            pbv[1] = bvt ? *(const float4*)(B + (long long)(bn + brow) * ldb + bk8 + 4) : f0;
        } else {
#pragma unroll
            for (int c = 0; c < NCH; c++)
                pbv[c] = bvn[c] ? *(const float4*)(B + (long long)bkr * ldb + bn + bnc + 4 * c) : f0;
        }
    }
    /* store stage 0 */
    {
        const float* af = (const float*)&pa0;
#pragma unroll
        for (int i = 0; i < 4; i++) As[0][ak8 + i][arow] = f2tf32(af[i]);
        af = (const float*)&pa1;
#pragma unroll
        for (int i = 0; i < 4; i++) As[0][ak8 + 4 + i][arow] = f2tf32(af[i]);
        if (TB) {
            const float* bf = (const float*)&pbv[0];
#pragma unroll
            for (int i = 0; i < 4; i++) Bs[0][bk8 + i][brow] = f2tf32(bf[i]);
            bf = (const float*)&pbv[1];
#pragma unroll
            for (int i = 0; i < 4; i++) Bs[0][bk8 + 4 + i][brow] = f2tf32(bf[i]);
        } else {
#pragma unroll
            for (int c = 0; c < NCH; c++) {
                const float* bf = (const float*)&pbv[c];
#pragma unroll
                for (int i = 0; i < 4; i++) Bs[0][bkr][bnc + 4 * c + i] = f2tf32(bf[i]);
            }
        }
    }
    __syncthreads();

    float acc[4][NT][4];
#pragma unroll
    for (int mt = 0; mt < 4; mt++)
#pragma unroll
        for (int nt = 0; nt < NT; nt++)
#pragma unroll
            for (int u = 0; u < 4; u++) acc[mt][nt][u] = 0.f;

    const int nst = K >> 4;
    for (int st = 0; st < nst; st++) {
        if (st + 1 < nst) {
            int kb = (st + 1) << 4;
            pa0 = *(const float4*)(Aptr + kb);
            pa1 = *(const float4*)(Aptr + kb + 4);
            if (TB) {
                pbv[0] = bvt ? *(const float4*)(B + (long long)(bn + brow) * ldb + kb + bk8) : f0;
                pbv[1] = bvt ? *(const float4*)(B + (long long)(bn + brow) * ldb + kb + bk8 + 4) : f0;
            } else {
#pragma unroll
                for (int c = 0; c < NCH; c++)
                    pbv[c] = bvn[c] ? *(const float4*)(B + (long long)(kb + bkr) * ldb + bn + bnc + 4 * c) : f0;
            }
        }
        const int buf = st & 1;
#pragma unroll
        for (int ks = 0; ks < 2; ks++) {
            const int k8 = ks * 8;
            unsigned af[4][4], bf[NT][2];
#pragma unroll
            for (int mt = 0; mt < 4; mt++) {
                int m = warpM * 64 + mt * 16 + g;
                af[mt][0] = As[buf][k8 + tg][m];
                af[mt][1] = As[buf][k8 + tg][m + 8];
                af[mt][2] = As[buf][k8 + tg + 4][m];
                af[mt][3] = As[buf][k8 + tg + 4][m + 8];
            }
#pragma unroll
            for (int nt = 0; nt < NT; nt++) {
                int n = warpN * (NT * 8) + nt * 8 + g;
                bf[nt][0] = Bs[buf][k8 + tg][n];
                bf[nt][1] = Bs[buf][k8 + tg + 4][n];
            }
#pragma unroll
            for (int mt = 0; mt < 4; mt++)
#pragma unroll
                for (int nt = 0; nt < NT; nt++)
                    mma_tf32(acc[mt][nt], af[mt], bf[nt]);
        }
        if (st + 1 < nst) {
            const int nb = (st + 1) & 1;
            const float* af = (const float*)&pa0;
#pragma unroll
            for (int i = 0; i < 4; i++) As[nb][ak8 + i][arow] = f2tf32(af[i]);
            af = (const float*)&pa1;
#pragma unroll
            for (int i = 0; i < 4; i++) As[nb][ak8 + 4 + i][arow] = f2tf32(af[i]);
            if (TB) {
                const float* bfp = (const float*)&pbv[0];
#pragma unroll
                for (int i = 0; i < 4; i++) Bs[nb][bk8 + i][brow] = f2tf32(bfp[i]);
                bfp = (const float*)&pbv[1];
#pragma unroll
                for (int i = 0; i < 4; i++) Bs[nb][bk8 + 4 + i][brow] = f2tf32(bfp[i]);
            } else {
#pragma unroll
                for (int c = 0; c < NCH; c++) {
                    const float* bfp = (const float*)&pbv[c];
#pragma unroll
                    for (int i = 0; i < 4; i++) Bs[nb][bkr][bnc + 4 * c + i] = f2tf32(bfp[i]);
                }
            }
        }
        __syncthreads();
    }

    /* ---- epilogue (mma fragment ownership: rows g/g+8, cols tg*2, tg*2+1) ---- */
#pragma unroll
    for (int mt = 0; mt < 4; mt++) {
        const int m0 = bm + warpM * 64 + mt * 16 + g;
        const int m1 = m0 + 8;
        float inv0 = 1.f, inv1 = 1.f;
        if (rscale) {
            inv0 = 1.f / rscale[(size_t)batch * M + m0];
            inv1 = 1.f / rscale[(size_t)batch * M + m1];
        }
        const float* pbr0 = nullptr;
        const float* pbr1 = nullptr;
        if (MODE == 3) {
            pbr0 = pbias + (size_t)batch * (NPn * NPn) + (size_t)(m0 >> 3) * NPn;
            pbr1 = pbias + (size_t)batch * (NPn * NPn) + (size_t)(m1 >> 3) * NPn;
        }
        float r0 = 0.f, r1 = 0.f;
#pragma unroll
        for (int nt = 0; nt < NT; nt++) {
            const int n = bn + warpN * (NT * 8) + nt * 8 + tg * 2;
            if (n < N) {
                float c0 = acc[mt][nt][0], c1 = acc[mt][nt][1];
                float c2 = acc[mt][nt][2], c3 = acc[mt][nt][3];
                if (bias) {
                    float2 bb = *(const float2*)&bias[n];
                    c0 += bb.x; c1 += bb.y; c2 += bb.x; c3 += bb.y;
                }
                if (MODE == 1) {
                    c0 = fmaxf(c0, 0.f); c1 = fmaxf(c1, 0.f);
                    c2 = fmaxf(c2, 0.f); c3 = fmaxf(c3, 0.f);
                }
                if (MODE == 3) {
                    float pb0v = pbr0[n >> 3], pb1v = pbr1[n >> 3];
                    c0 = softclamp_exp(c0 + pb0v);
                    c1 = softclamp_exp(c1 + pb0v);
                    c2 = softclamp_exp(c2 + pb1v);
                    c3 = softclamp_exp(c3 + pb1v);
                    r0 += c0 + c1; r1 += c2 + c3;
                }
                if (MODE == 4) {
                    c0 = __expf(c0); c1 = __expf(c1);
                    c2 = __expf(c2); c3 = __expf(c3);
                    r0 += c0 + c1; r1 += c2 + c3;
                }
                if (rscale) { c0 *= inv0; c1 *= inv0; c2 *= inv1; c3 *= inv1; }
                float2 w0, w1;
                if (MODE == 2) {
                    float2 o0 = *(const float2*)&C[(long long)m0 * ldc + n];
                    float2 o1 = *(const float2*)&C[(long long)m1 * ldc + n];
                    w0.x = c0 + o0.x; w0.y = c1 + o0.y;
                    w1.x = c2 + o1.x; w1.y = c3 + o1.y;
                } else {
                    w0.x = c0; w0.y = c1; w1.x = c2; w1.y = c3;
                }
                *(float2*)&C[(long long)m0 * ldc + n] = w0;
                *(float2*)&C[(long long)m1 * ldc + n] = w1;
            }
        }
        if (MODE == 3 || MODE == 4) {
            r0 += __shfl_xor_sync(0xffffffffu, r0, 1);
            r0 += __shfl_xor_sync(0xffffffffu, r0, 2);
            r1 += __shfl_xor_sync(0xffffffffu, r1, 1);
            r1 += __shfl_xor_sync(0xffffffffu, r1, 2);
            if (tg == 0) {
                atomicAdd(&rsum[(size_t)batch * M + m0], r0);
                atomicAdd(&rsum[(size_t)batch * M + m1], r1);
            }
        }
    }
}

/* ---------------- norms ---------------- */
__global__ void rmsnorm_k(const float* __restrict__ x, const float* __restrict__ w,
                          float* __restrict__ y, int cols)
{
    long long r = blockIdx.x;
    const float* xr = x + r * cols;
    float ss = 0.f;
    for (int c = threadIdx.x; c < cols; c += blockDim.x) { float v = xr[c]; ss += v * v; }
    ss = blockReduce<0>(ss);
    float inv = rsqrtf(ss / cols + EPS_RMS);
    for (int c = threadIdx.x; c < cols; c += blockDim.x)
        y[r * cols + c] = xr[c] * inv * w[c];
}

/* res += rmsnorm(x)*w1; if (w2) out = rmsnorm(res)*w2.  cols=768, 256 thr. */
__global__ void rmsnorm_add_norm_k(const float* __restrict__ x, const float* __restrict__ w1,
                                   float* __restrict__ res, const float* __restrict__ w2,
                                   float* __restrict__ out)
{
    long long r = blockIdx.x;
    const int cols = Dn;
    const float* xr = x + r * cols;
    float xv[3], rv[3];
    float ss = 0.f;
#pragma unroll
    for (int u = 0; u < 3; u++) {
        xv[u] = xr[threadIdx.x + u * 256];
        ss += xv[u] * xv[u];
    }
    ss = blockReduce<0>(ss);
    float inv = rsqrtf(ss / cols + EPS_RMS);
    float ss2 = 0.f;
#pragma unroll
    for (int u = 0; u < 3; u++) {
        int c = threadIdx.x + u * 256;
        float v = res[r * cols + c] + xv[u] * inv * w1[c];
        res[r * cols + c] = v;
        rv[u] = v;
        ss2 += v * v;
    }
    if (w2) {
        ss2 = blockReduce<0>(ss2);
        float inv2 = rsqrtf(ss2 / cols + EPS_RMS);
#pragma unroll
        for (int u = 0; u < 3; u++) {
            int c = threadIdx.x + u * 256;
            out[r * cols + c] = rv[u] * inv2 * w2[c];
        }
    }
}

/* ---------------- qkv post: per-head LayerNorm + scale + rotary ---------------- */
__global__ void qkv_post_k(const float* __restrict__ qkv,
                           const float* __restrict__ qn, const float* __restrict__ kn,
                           const float* __restrict__ vn,
                           float* __restrict__ q, float* __restrict__ k, float* __restrict__ v)
{
    int n = blockIdx.x, s = blockIdx.y, t = threadIdx.x;
    int len = (s == 9) ? 192 : 128;
    int off = (s < 8) ? s * 128 : (s == 8 ? 1024 : 1152);
    __shared__ float xs[192];
    float x = 0.f;
    if (t < len) x = qkv[(long long)n * NQKVn + off + t];
    float2 sums = blockReduce2(t < len ? x : 0.f, t < len ? x * x : 0.f);
    float mu = sums.x / len;
    float var = sums.y / len - mu * mu;
    float inv = rsqrtf(var + EPS_LN);
    float y = 0.f;
    if (t < len) {
        const float* w = (s < 8) ? qn : (s == 8 ? kn : vn);
        y = (x - mu) * inv * w[t];
        if (s < 8) y *= 0.125f;
    }
    if (s == 9) { if (t < 192) v[n * DVn + t] = y; return; }
    xs[t] = y;
    __syncthreads();
    if (t < 128) {
        int d2 = t & 63;
        float invf = (d2 == 0) ? 0.1f : 0.0f;
        float f = (float)n * invf;
        float c = cosf(f), si = sinf(f);
        float rh = (t < 64) ? -xs[t + 64] : xs[t - 64];
        float out = y * c + rh * si;
        if (s < 8) q[((size_t)s * SEQn + n) * DQKn + t] = out;
        else       k[n * DQKn + t] = out;
    }
}

/* ------------- pairwise bias: rms -> gelu -> [128->8].
   8 warps/block, 8 pairs per warp; proj preloaded; next-row prefetch. ------ */
__global__ __launch_bounds__(256) void pb_kernel(
    const float* __restrict__ pair, const float* __restrict__ rw,
    const float* __restrict__ proj, float* __restrict__ pb)
{
    const int lane = threadIdx.x & 31;
    const int warp = threadIdx.x >> 5;
    const int pair0 = (blockIdx.x * 8 + warp) * 8;
    /* preload proj rows lane*4 .. lane*4+3 (8 heads each) */
    float pr[4][8];
#pragma unroll
    for (int c = 0; c < 4; c++) {
        const float* p0 = proj + (size_t)(lane * 4 + c) * Hn;
        float4 a = *(const float4*)p0;
        float4 b = *(const float4*)(p0 + 4);
        pr[c][0] = a.x; pr[c][1] = a.y; pr[c][2] = a.z; pr[c][3] = a.w;
        pr[c][4] = b.x; pr[c][5] = b.y; pr[c][6] = b.z; pr[c][7] = b.w;
    }
    const float4 w4 = *(const float4*)(rw + lane * 4);

    float4 xnext = *(const float4*)(pair + (size_t)pair0 * DPn + lane * 4);
    for (int pp = 0; pp < 8; pp++) {
        const int idx = pair0 + pp;
        float4 x = xnext;
        if (pp < 7)
            xnext = *(const float4*)(pair + (size_t)(idx + 1) * DPn + lane * 4);
        float ss = x.x * x.x + x.y * x.y + x.z * x.z + x.w * x.w;
#pragma unroll
        for (int off = 16; off > 0; off >>= 1)
            ss += __shfl_xor_sync(0xffffffffu, ss, off);
        float inv = rsqrtf(ss * (1.f / DPn) + EPS_RMS);
        float gl[4];
        {
            float y0 = x.x * inv * w4.x, y1 = x.y * inv * w4.y;
            float y2 = x.z * inv * w4.z, y3 = x.w * inv * w4.w;
            gl[0] = 0.5f * y0 * (1.f + erff(y0 * 0.70710678118654752f));
            gl[1] = 0.5f * y1 * (1.f + erff(y1 * 0.70710678118654752f));
            gl[2] = 0.5f * y2 * (1.f + erff(y2 * 0.70710678118654752f));
            gl[3] = 0.5f * y3 * (1.f + erff(y3 * 0.70710678118654752f));
        }
        float p[8] = {0.f, 0.f, 0.f, 0.f, 0.f, 0.f, 0.f, 0.f};
#pragma unroll
        for (int c = 0; c < 4; c++)
#pragma unroll
            for (int h = 0; h < 8; h++)
                p[h] = fmaf(gl[c], pr[c][h], p[h]);
#pragma unroll
        for (int off = 16; off > 0; off >>= 1)
#pragma unroll
            for (int h = 0; h < 8; h++)
                p[h] += __shfl_xor_sync(0xffffffffu, p[h], off);
        if (lane < 8) {
            float out = p[0];
#pragma unroll
            for (int h = 1; h < 8; h++) if (lane == h) out = p[h];
            int i = idx >> 8, j = idx & 255;
            pb[((size_t)lane * NPn + i) * NPn + j] = out;
        }
    }
}

/* ---------------- host launcher ---------------- */
static inline void launch_gemm(bool tb, int mode, int M, int N, int K,
                               const float* A, int lda, long long sA,
                               const float* B, int ldb, long long sB,
                               float* C, int ldc, long long sC, int batch,
                               const float* bias, const float* pbias,
                               float* rsum, const float* rscale)
{
    dim3 g((N + 127) / 128, M / 128, batch), b(256);
    if (tb) {
        if (mode == 3)      gemm_tc<true, 3, 4><<<g, b>>>(M, N, K, A, lda, sA, B, ldb, sB, C, ldc, sC, bias, pbias, rsum, rscale);
        else if (mode == 4) gemm_tc<true, 4, 4><<<g, b>>>(M, N, K, A, lda, sA, B, ldb, sB, C, ldc, sC, bias, pbias, rsum, rscale);
        else                gemm_tc<true, 0, 4><<<g, b>>>(M, N, K, A, lda, sA, B, ldb, sB, C, ldc, sC, bias, pbias, rsum, rscale);
    } else {
        if (mode == 1)      gemm_tc<false, 1, 4><<<g, b>>>(M, N, K, A, lda, sA, B, ldb, sB, C, ldc, sC, bias, pbias, rsum, rscale);
        else if (mode == 2) gemm_tc<false, 2, 4><<<g, b>>>(M, N, K, A, lda, sA, B, ldb, sB, C, ldc, sC, bias, pbias, rsum, rscale);
        else                gemm_tc<false, 0, 4><<<g, b>>>(M, N, K, A, lda, sA, B, ldb, sB, C, ldc, sC, bias, pbias, rsum, rscale);
    }
}

extern "C" void kernel_launch(void* const* d_in, const int* in_sizes, int n_in,
                              void* d_out, int out_size)
{
    (void)in_sizes; (void)n_in; (void)out_size;
    const float* in_single = (const float*)d_in[0];
    const float* in_pair   = (const float*)d_in[1];
    const float* W_attn_pre  = (const float*)d_in[2];
    const float* W_attn_post = (const float*)d_in[3];
    const float* W_qkv  = (const float*)d_in[4];
    const float* W_qn   = (const float*)d_in[5];
    const float* W_kn   = (const float*)d_in[6];
    const float* W_vn   = (const float*)d_in[7];
    const float* W_brms = (const float*)d_in[8];
    const float* W_bproj= (const float*)d_in[9];
    const float* W_out  = (const float*)d_in[10];
    const float* W_ffpre = (const float*)d_in[11];
    const float* W_ffpost= (const float*)d_in[12];
    const float* W_ff1  = (const float*)d_in[13];
    const float* B_ff1  = (const float*)d_in[14];
    const float* W_ff2  = (const float*)d_in[15];
    const float* B_ff2  = (const float*)d_in[16];
    const float* W_ppre = (const float*)d_in[17];
    const float* W_pqk  = (const float*)d_in[18];
    const float* W_pv   = (const float*)d_in[19];
    const float* B_pv   = (const float*)d_in[20];
    const float* W_pffpre = (const float*)d_in[21];
    const float* W_pff1 = (const float*)d_in[22];
    const float* B_pff1 = (const float*)d_in[23];
    const float* W_pff2 = (const float*)d_in[24];
    const float* B_pff2 = (const float*)d_in[25];

    float *xn, *qkv, *q, *k, *v, *sim, *pb, *ao, *t1, *rsum;
    float *pxn, *pqk, *pv, *psim, *prsum, *pt;
    cudaGetSymbolAddress((void**)&xn, g_xn);
    cudaGetSymbolAddress((void**)&qkv, g_qkv);
    cudaGetSymbolAddress((void**)&q, g_q);
    cudaGetSymbolAddress((void**)&k, g_k);
    cudaGetSymbolAddress((void**)&v, g_v);
    cudaGetSymbolAddress((void**)&sim, g_sim);
    cudaGetSymbolAddress((void**)&pb, g_pb);
    cudaGetSymbolAddress((void**)&ao, g_ao);
    cudaGetSymbolAddress((void**)&t1, g_t1);
    cudaGetSymbolAddress((void**)&rsum, g_rsum);
    cudaGetSymbolAddress((void**)&pxn, g_pxn);
    cudaGetSymbolAddress((void**)&pqk, g_pqk);
    cudaGetSymbolAddress((void**)&pv, g_pv);
    cudaGetSymbolAddress((void**)&psim, g_psim);
    cudaGetSymbolAddress((void**)&prsum, g_prsum);
    cudaGetSymbolAddress((void**)&pt, g_pt);

    /* residual streams live directly in d_out: [single | pairwise] */
    float* single = (float*)d_out;
    float* pair   = (float*)d_out + (size_t)SEQn * Dn;
    cudaMemcpyAsync(single, in_single, (size_t)SEQn * Dn * 4, cudaMemcpyDeviceToDevice);
    cudaMemcpyAsync(pair, in_pair, (size_t)NPn * NPn * DPn * 4, cudaMemcpyDeviceToDevice);

    /* xn = rmsnorm(single, attn_pre[0]) for the first layer */
    rmsnorm_k<<<SEQn, 256>>>(single, W_attn_pre, xn, Dn);

    for (int i = 0; i < 4; i++) {
        /* ---- single-track attention ---- */
        launch_gemm(false, 0, SEQn, NQKVn, Dn, xn, Dn, 0,
                    W_qkv + (long long)i * Dn * NQKVn, NQKVn, 0, qkv, NQKVn, 0, 1,
                    nullptr, nullptr, nullptr, nullptr);
        qkv_post_k<<<dim3(SEQn, 10), 192>>>(qkv, W_qn + i * DQKn, W_kn + i * DQKn,
                                            W_vn + i * DVn, q, k, v);
        pb_kernel<<<NPn * NPn / 64, 256>>>(pair, W_brms + i * DPn, W_bproj + i * DPn * Hn, pb);
        zero_k<<<(Hn * SEQn + 255) / 256, 256>>>(rsum, Hn * SEQn);
        /* P = exp(softclamp(qk^T + pb)), rowsums accumulated */
        launch_gemm(true, 3, SEQn, SEQn, DQKn, q, DQKn, (long long)SEQn * DQKn,
                    k, DQKn, 0, sim, SEQn, (long long)SEQn * SEQn, Hn,
                    nullptr, pb, rsum, nullptr);
        /* O = (P/rowsum) V  — NT=6: CTA 128x192, exact fit for DVn */
        {
            dim3 g(1, SEQn / 128, Hn), b(256);
            gemm_tc<false, 0, 6><<<g, b>>>(SEQn, DVn, SEQn,
                sim, SEQn, (long long)SEQn * SEQn,
                v, DVn, 0, ao, Hn * DVn, DVn,
                nullptr, nullptr, nullptr, rsum);
        }
        launch_gemm(false, 0, SEQn, Dn, Hn * DVn, ao, Hn * DVn, 0,
                    W_out + (long long)i * Hn * DVn * Dn, Dn, 0, t1, Dn, 0, 1,
                    nullptr, nullptr, nullptr, nullptr);
        /* single += rms(t1)*attn_post; xn = rms(single)*ff_pre */
        rmsnorm_add_norm_k<<<SEQn, 256>>>(t1, W_attn_post + i * Dn, single,
                                          W_ffpre + i * Dn, xn);

        /* ---- single-track FF ---- */
        launch_gemm(false, 1, SEQn, FFIn, Dn, xn, Dn, 0,
                    W_ff1 + (long long)i * Dn * FFIn, FFIn, 0, ao, FFIn, 0, 1,
                    B_ff1 + i * FFIn, nullptr, nullptr, nullptr);
        launch_gemm(false, 0, SEQn, Dn, FFIn, ao, FFIn, 0,
                    W_ff2 + (long long)i * FFIn * Dn, Dn, 0, t1, Dn, 0, 1,
                    B_ff2 + i * Dn, nullptr, nullptr, nullptr);
        /* single += rms(t1)*ff_post; xn = rms(single)*attn_pre[i+1] (if any) */
        rmsnorm_add_norm_k<<<SEQn, 256>>>(t1, W_ffpost + i * Dn, single,
                                          (i < 3) ? W_attn_pre + (i + 1) * Dn : nullptr, xn);

        /* ---- pairwise track (layers 0, 2) ---- */
        if ((i & 1) == 0) {
            int j = i / 2;
            rmsnorm_k<<<NPn * NPn, 128>>>(pair, W_ppre + j * DPn, pxn, DPn);
            launch_gemm(false, 0, NPn * NPn, 2 * DPn, DPn, pxn, DPn, 0,
                        W_pqk + (long long)j * DPn * 2 * DPn, 2 * DPn, 0,
                        pqk, 2 * DPn, 0, 1, nullptr, nullptr, nullptr, nullptr);
            launch_gemm(false, 0, NPn * NPn, DPn, DPn, pxn, DPn, 0,
                        W_pv + (long long)j * DPn * DPn, DPn, 0,
                        pv, DPn, 0, 1, B_pv + j * DPn, nullptr, nullptr, nullptr);
            zero_k<<<(NPn * NPn + 255) / 256, 256>>>(prsum, NPn * NPn);
            launch_gemm(true, 4, NPn, NPn, DPn, pqk, 2 * DPn, (long long)NPn * 2 * DPn,
                        pqk + DPn, 2 * DPn, (long long)NPn * 2 * DPn,
                        psim, NPn, (long long)NPn * NPn, NPn,
                        nullptr, nullptr, prsum, nullptr);
            /* pair += (P/rowsum) V */
            launch_gemm(false, 2, NPn, DPn, NPn, psim, NPn, (long long)NPn * NPn,
                        pv, DPn, (long long)NPn * DPn,
                        pair, DPn, (long long)NPn * DPn, NPn,
                        nullptr, nullptr, nullptr, prsum);
            rmsnorm_k<<<NPn * NPn, 128>>>(pair, W_pffpre + j * DPn, pxn, DPn);
            launch_gemm(false, 1, NPn * NPn, DPIn, DPn, pxn, DPn, 0,
                        W_pff1 + (long long)j * DPn * DPIn, DPIn, 0,
                        pt, DPIn, 0, 1, B_pff1 + j * DPIn, nullptr, nullptr, nullptr);
            /* pair += ff2(pt) */
            launch_gemm(false, 2, NPn * NPn, DPn, DPIn, pt, DPIn, 0,
                        W_pff2 + (long long)j * DPIn * DPn, DPn, 0,
                        pair, DPn, 0, 1, B_pff2 + j * DPn, nullptr, nullptr, nullptr);
        }
    }
}

// round 10
// speedup vs baseline: 1.5546x; 1.0807x over previous
#include <cuda_runtime.h>
#include <math.h>

#define SEQn 2048
#define Dn   768
#define Hn   8
#define DQKn 128
#define DVn  192
#define NQKVn 1344   /* 8*128 + 128 + 192 */
#define NPn  256
#define DPn  128
#define FFIn 1536
#define DPIn 256
#define EPS_RMS 1.1920929e-07f
#define EPS_LN  1e-5f

/* ---------------- scratch (device globals; no allocation) ---------------- */
__device__ float g_xn[SEQn * Dn];
__device__ float g_qkv[SEQn * NQKVn];
__device__ float g_q[Hn * SEQn * DQKn];
__device__ float g_k[SEQn * DQKn];
__device__ float g_v[SEQn * DVn];
__device__ float g_sim[(size_t)Hn * SEQn * SEQn];      /* 134 MB */
__device__ float g_pb[Hn * NPn * NPn];
__device__ float g_ao[SEQn * Hn * DVn];
__device__ float g_t1[SEQn * FFIn];
__device__ float g_rsum[Hn * SEQn];
__device__ float g_pxn[NPn * NPn * DPn];
__device__ float g_pqk[NPn * NPn * 2 * DPn];
__device__ float g_pv[NPn * NPn * DPn];
__device__ float g_psim[(size_t)NPn * NPn * NPn];      /* 67 MB */
__device__ float g_prsum[NPn * NPn];
__device__ float g_pt[NPn * NPn * DPIn];

/* ---------------- helpers ---------------- */
__device__ __forceinline__ unsigned f2tf32(float x) {
    unsigned r;
    asm("cvt.rna.tf32.f32 %0, %1;" : "=r"(r) : "f"(x));
    return r;
}

__device__ __forceinline__ void mma_tf32(float* c, const unsigned* a, const unsigned* b) {
    asm volatile(
        "mma.sync.aligned.m16n8k8.row.col.f32.tf32.tf32.f32 "
        "{%0,%1,%2,%3}, {%4,%5,%6,%7}, {%8,%9}, {%0,%1,%2,%3};\n"
        : "+f"(c[0]), "+f"(c[1]), "+f"(c[2]), "+f"(c[3])
        : "r"(a[0]), "r"(a[1]), "r"(a[2]), "r"(a[3]), "r"(b[0]), "r"(b[1]));
}

__device__ __forceinline__ float softclamp_exp(float x) {
    float t = __expf(-0.4f * fabsf(x));
    float th = __fdividef(1.f - t, 1.f + t);
    return __expf(copysignf(5.f * th, x));
}

template <int OP>
__device__ __forceinline__ float blockReduce(float v) {
    __shared__ float s[33];
    int lane = threadIdx.x & 31, wid = threadIdx.x >> 5;
#pragma unroll
    for (int o = 16; o > 0; o >>= 1) {
        float ov = __shfl_down_sync(0xffffffffu, v, o);
        v = (OP == 0) ? (v + ov) : fmaxf(v, ov);
    }
    if (lane == 0) s[wid] = v;
    __syncthreads();
    if (threadIdx.x == 0) {
        int nw = (blockDim.x + 31) >> 5;
        float r = s[0];
        for (int i = 1; i < nw; i++) r = (OP == 0) ? (r + s[i]) : fmaxf(r, s[i]);
        s[32] = r;
    }
    __syncthreads();
    float r = s[32];
    __syncthreads();
    return r;
}

/* combined sum reduction of two values (one sync round); block <= 8 warps */
__device__ __forceinline__ float2 blockReduce2(float a, float b) {
    __shared__ float sa[8], sb[8];
    int lane = threadIdx.x & 31, wid = threadIdx.x >> 5;
#pragma unroll
    for (int o = 16; o > 0; o >>= 1) {
        a += __shfl_down_sync(0xffffffffu, a, o);
        b += __shfl_down_sync(0xffffffffu, b, o);
    }
    if (lane == 0) { sa[wid] = a; sb[wid] = b; }
    __syncthreads();
    if (threadIdx.x == 0) {
        int nw = (blockDim.x + 31) >> 5;
        float ra = sa[0], rb = sb[0];
        for (int i = 1; i < nw; i++) { ra += sa[i]; rb += sb[i]; }
        sa[7] = ra; sb[7] = rb;
    }
    __syncthreads();
    float2 r = make_float2(sa[7], sb[7]);
    __syncthreads();
    return r;
}

__global__ void zero_k(float* p, int n)
{
    int i = blockIdx.x * blockDim.x + threadIdx.x;
    if (i < n) p[i] = 0.f;
}

/* ---------------- TF32 tensor-core GEMM, 128 x (NT*32) CTA, BK=16, dbl-buf.
   8 warps in 2 x 4 grid; warp tile 64 x (NT*8). NT=4 -> CTA 128x128 (std),
   NT=6 -> CTA 128x192 (AV exact fit).
   MODE: 0 plain(+bias), 1 relu(+bias), 2 accumulate into C(+bias),
         3 sim softmax: exp(softclamp(x+pb)) + atomic row sums,
         4 pair softmax: exp(x) + atomic row sums,
         5 split-K: atomicAdd into C (+bias only from kz==0 split).
   ksplit: blockIdx.z = batch*ksplit + kz; each split covers K columns
           starting at kz*K (K = per-split depth). !TB only for ksplit>1.
   rscale (optional): multiply output rows by 1/rscale[batch*M+m].
   Requires M % 128 == 0, K % 16 == 0 (N guarded). TB only with NT=4.       */
template <bool TB, int MODE, int NT>
__global__ __launch_bounds__(256) void gemm_tc(
    int M, int N, int K,
    const float* __restrict__ A, int lda, long long sA,
    const float* __restrict__ B, int ldb, long long sB,
    float* __restrict__ C, int ldc, long long sC,
    const float* __restrict__ bias,
    const float* __restrict__ pbias,
    float* __restrict__ rsum,
    const float* __restrict__ rscale,
    int ksplit)
{
    constexpr int BN = NT * 32;
    constexpr int BNP = BN + 8;          /* ≡ 8 mod 32: conflict-free frags */
    constexpr int NCH = NT / 2;          /* float4 staging chunks (!TB)     */
    __shared__ unsigned As[2][16][136];
    __shared__ unsigned Bs[2][16][BNP];
    const int zz = blockIdx.z;
    const int batch = zz / ksplit;
    const int kz = zz - batch * ksplit;
    A += (long long)batch * sA + (long long)kz * K;
    B += (long long)batch * sB;
    if (!TB) B += (long long)kz * K * ldb;
    C += (long long)batch * sC;
    const int bm = blockIdx.y * 128, bn = blockIdx.x * BN;
    const int tid = threadIdx.x;
    const int lane = tid & 31, warp = tid >> 5;
    const int g = lane >> 2, tg = lane & 3;
    const int warpM = warp & 1, warpN = warp >> 1;

    /* staging maps */
    const int arow = tid >> 1, ak8 = (tid & 1) * 8;          /* A: 128 rows x 16 k */
    const float* Aptr = A + (long long)(bm + arow) * lda + ak8;
    const int brow = tid >> 1, bk8 = (tid & 1) * 8;          /* TB:  n-row, k segment */
    const int bkr = tid >> 4, bnc = (tid & 15) * (2 * NT);   /* !TB: k-row, n segment */
    const bool bvt = TB ? (bn + brow < N) : true;
    bool bvn[NCH];
#pragma unroll
    for (int c = 0; c < NCH; c++) bvn[c] = TB ? true : (bn + bnc + 4 * c < N);
    const float4 f0 = make_float4(0.f, 0.f, 0.f, 0.f);

    float4 pa0, pa1, pbv[NCH];
    /* prefetch stage 0 */
    {
        pa0 = *(const float4*)(Aptr);
        pa1 = *(const float4*)(Aptr + 4);
        if (TB) {
            pbv[0] = bvt ? *(const float4*)(B + (long long)(bn + brow) * ldb + bk8) : f0;
            pbv[1] = bvt ? *(const float4*)(B + (long long)(bn + brow) * ldb + bk8 + 4) : f0;
        } else {
#pragma unroll
            for (int c = 0; c < NCH; c++)
                pbv[c] = bvn[c] ? *(const float4*)(B + (long long)bkr * ldb + bn + bnc + 4 * c) : f0;
        }
    }
    /* store stage 0 */
    {
        const float* af = (const float*)&pa0;
#pragma unroll
        for (int i = 0; i < 4; i++) As[0][ak8 + i][arow] = f2tf32(af[i]);
        af = (const float*)&pa1;
#pragma unroll
        for (int i = 0; i < 4; i++) As[0][ak8 + 4 + i][arow] = f2tf32(af[i]);
        if (TB) {
            const float* bf = (const float*)&pbv[0];
#pragma unroll
            for (int i = 0; i < 4; i++) Bs[0][bk8 + i][brow] = f2tf32(bf[i]);
            bf = (const float*)&pbv[1];
#pragma unroll
            for (int i = 0; i < 4; i++) Bs[0][bk8 + 4 + i][brow] = f2tf32(bf[i]);
        } else {
#pragma unroll
            for (int c = 0; c < NCH; c++) {
                const float* bf = (const float*)&pbv[c];
#pragma unroll
                for (int i = 0; i < 4; i++) Bs[0][bkr][bnc + 4 * c + i] = f2tf32(bf[i]);
            }
        }
    }
    __syncthreads();

    float acc[4][NT][4];
#pragma unroll
    for (int mt = 0; mt < 4; mt++)
#pragma unroll
        for (int nt = 0; nt < NT; nt++)
#pragma unroll
            for (int u = 0; u < 4; u++) acc[mt][nt][u] = 0.f;

    const int nst = K >> 4;
    for (int st = 0; st < nst; st++) {
        if (st + 1 < nst) {
            int kb = (st + 1) << 4;
            pa0 = *(const float4*)(Aptr + kb);
            pa1 = *(const float4*)(Aptr + kb + 4);
            if (TB) {
                pbv[0] = bvt ? *(const float4*)(B + (long long)(bn + brow) * ldb + kb + bk8) : f0;
                pbv[1] = bvt ? *(const float4*)(B + (long long)(bn + brow) * ldb + kb + bk8 + 4) : f0;
            } else {
#pragma unroll
                for (int c = 0; c < NCH; c++)
                    pbv[c] = bvn[c] ? *(const float4*)(B + (long long)(kb + bkr) * ldb + bn + bnc + 4 * c) : f0;
            }
        }
        const int buf = st & 1;
#pragma unroll
        for (int ks = 0; ks < 2; ks++) {
            const int k8 = ks * 8;
            unsigned af[4][4], bf[NT][2];
#pragma unroll
            for (int mt = 0; mt < 4; mt++) {
                int m = warpM * 64 + mt * 16 + g;
                af[mt][0] = As[buf][k8 + tg][m];
                af[mt][1] = As[buf][k8 + tg][m + 8];
                af[mt][2] = As[buf][k8 + tg + 4][m];
                af[mt][3] = As[buf][k8 + tg + 4][m + 8];
            }
#pragma unroll
            for (int nt = 0; nt < NT; nt++) {
                int n = warpN * (NT * 8) + nt * 8 + g;
                bf[nt][0] = Bs[buf][k8 + tg][n];
                bf[nt][1] = Bs[buf][k8 + tg + 4][n];
            }
#pragma unroll
            for (int mt = 0; mt < 4; mt++)
#pragma unroll
                for (int nt = 0; nt < NT; nt++)
                    mma_tf32(acc[mt][nt], af[mt], bf[nt]);
        }
        if (st + 1 < nst) {
            const int nb = (st + 1) & 1;
            const float* af = (const float*)&pa0;
#pragma unroll
            for (int i = 0; i < 4; i++) As[nb][ak8 + i][arow] = f2tf32(af[i]);
            af = (const float*)&pa1;
#pragma unroll
            for (int i = 0; i < 4; i++) As[nb][ak8 + 4 + i][arow] = f2tf32(af[i]);
            if (TB) {
                const float* bfp = (const float*)&pbv[0];
#pragma unroll
                for (int i = 0; i < 4; i++) Bs[nb][bk8 + i][brow] = f2tf32(bfp[i]);
                bfp = (const float*)&pbv[1];
#pragma unroll
                for (int i = 0; i < 4; i++) Bs[nb][bk8 + 4 + i][brow] = f2tf32(bfp[i]);
            } else {
#pragma unroll
                for (int c = 0; c < NCH; c++) {
                    const float* bfp = (const float*)&pbv[c];
#pragma unroll
                    for (int i = 0; i < 4; i++) Bs[nb][bkr][bnc + 4 * c + i] = f2tf32(bfp[i]);
                }
            }
        }
        __syncthreads();
    }

    /* ---- epilogue (mma fragment ownership: rows g/g+8, cols tg*2, tg*2+1) ---- */
#pragma unroll
    for (int mt = 0; mt < 4; mt++) {
        const int m0 = bm + warpM * 64 + mt * 16 + g;
        const int m1 = m0 + 8;
        float inv0 = 1.f, inv1 = 1.f;
        if (rscale) {
            inv0 = 1.f / rscale[(size_t)batch * M + m0];
            inv1 = 1.f / rscale[(size_t)batch * M + m1];
        }
        const float* pbr0 = nullptr;
        const float* pbr1 = nullptr;
        if (MODE == 3) {
            pbr0 = pbias + (size_t)batch * (NPn * NPn) + (size_t)(m0 >> 3) * NPn;
            pbr1 = pbias + (size_t)batch * (NPn * NPn) + (size_t)(m1 >> 3) * NPn;
        }
        float r0 = 0.f, r1 = 0.f;
#pragma unroll
        for (int nt = 0; nt < NT; nt++) {
            const int n = bn + warpN * (NT * 8) + nt * 8 + tg * 2;
            if (n < N) {
                float c0 = acc[mt][nt][0], c1 = acc[mt][nt][1];
                float c2 = acc[mt][nt][2], c3 = acc[mt][nt][3];
                if (bias && (MODE != 5 || kz == 0)) {
                    float2 bb = *(const float2*)&bias[n];
                    c0 += bb.x; c1 += bb.y; c2 += bb.x; c3 += bb.y;
                }
                if (MODE == 1) {
                    c0 = fmaxf(c0, 0.f); c1 = fmaxf(c1, 0.f);
                    c2 = fmaxf(c2, 0.f); c3 = fmaxf(c3, 0.f);
                }
                if (MODE == 3) {
                    float pb0v = pbr0[n >> 3], pb1v = pbr1[n >> 3];
                    c0 = softclamp_exp(c0 + pb0v);
                    c1 = softclamp_exp(c1 + pb0v);
                    c2 = softclamp_exp(c2 + pb1v);
                    c3 = softclamp_exp(c3 + pb1v);
                    r0 += c0 + c1; r1 += c2 + c3;
                }
                if (MODE == 4) {
                    c0 = __expf(c0); c1 = __expf(c1);
                    c2 = __expf(c2); c3 = __expf(c3);
                    r0 += c0 + c1; r1 += c2 + c3;
                }
                if (rscale) { c0 *= inv0; c1 *= inv0; c2 *= inv1; c3 *= inv1; }
                if (MODE == 5) {
                    float* p0 = &C[(long long)m0 * ldc + n];
                    float* p1 = &C[(long long)m1 * ldc + n];
                    atomicAdd(p0, c0); atomicAdd(p0 + 1, c1);
                    atomicAdd(p1, c2); atomicAdd(p1 + 1, c3);
                } else {
                    float2 w0, w1;
                    if (MODE == 2) {
                        float2 o0 = *(const float2*)&C[(long long)m0 * ldc + n];
                        float2 o1 = *(const float2*)&C[(long long)m1 * ldc + n];
                        w0.x = c0 + o0.x; w0.y = c1 + o0.y;
                        w1.x = c2 + o1.x; w1.y = c3 + o1.y;
                    } else {
                        w0.x = c0; w0.y = c1; w1.x = c2; w1.y = c3;
                    }
                    *(float2*)&C[(long long)m0 * ldc + n] = w0;
                    *(float2*)&C[(long long)m1 * ldc + n] = w1;
                }
            }
        }
        if (MODE == 3 || MODE == 4) {
            r0 += __shfl_xor_sync(0xffffffffu, r0, 1);
            r0 += __shfl_xor_sync(0xffffffffu, r0, 2);
            r1 += __shfl_xor_sync(0xffffffffu, r1, 1);
            r1 += __shfl_xor_sync(0xffffffffu, r1, 2);
            if (tg == 0) {
                atomicAdd(&rsum[(size_t)batch * M + m0], r0);
                atomicAdd(&rsum[(size_t)batch * M + m1], r1);
            }
        }
    }
}

/* ---------------- norms ---------------- */
__global__ void rmsnorm_k(const float* __restrict__ x, const float* __restrict__ w,
                          float* __restrict__ y, int cols)
{
    long long r = blockIdx.x;
    const float* xr = x + r * cols;
    float ss = 0.f;
    for (int c = threadIdx.x; c < cols; c += blockDim.x) { float v = xr[c]; ss += v * v; }
    ss = blockReduce<0>(ss);
    float inv = rsqrtf(ss / cols + EPS_RMS);
    for (int c = threadIdx.x; c < cols; c += blockDim.x)
        y[r * cols + c] = xr[c] * inv * w[c];
}

/* res += rmsnorm(x)*w1; if (w2) out = rmsnorm(res)*w2.  cols=768, 256 thr. */
__global__ void rmsnorm_add_norm_k(const float* __restrict__ x, const float* __restrict__ w1,
                                   float* __restrict__ res, const float* __restrict__ w2,
                                   float* __restrict__ out)
{
    long long r = blockIdx.x;
    const int cols = Dn;
    const float* xr = x + r * cols;
    float xv[3], rv[3];
    float ss = 0.f;
#pragma unroll
    for (int u = 0; u < 3; u++) {
        xv[u] = xr[threadIdx.x + u * 256];
        ss += xv[u] * xv[u];
    }
    ss = blockReduce<0>(ss);
    float inv = rsqrtf(ss / cols + EPS_RMS);
    float ss2 = 0.f;
#pragma unroll
    for (int u = 0; u < 3; u++) {
        int c = threadIdx.x + u * 256;
        float v = res[r * cols + c] + xv[u] * inv * w1[c];
        res[r * cols + c] = v;
        rv[u] = v;
        ss2 += v * v;
    }
    if (w2) {
        ss2 = blockReduce<0>(ss2);
        float inv2 = rsqrtf(ss2 / cols + EPS_RMS);
#pragma unroll
        for (int u = 0; u < 3; u++) {
            int c = threadIdx.x + u * 256;
            out[r * cols + c] = rv[u] * inv2 * w2[c];
        }
    }
}

/* ---------------- qkv post: per-head LayerNorm + scale + rotary ---------------- */
__global__ void qkv_post_k(const float* __restrict__ qkv,
                           const float* __restrict__ qn, const float* __restrict__ kn,
                           const float* __restrict__ vn,
                           float* __restrict__ q, float* __restrict__ k, float* __restrict__ v)
{
    int n = blockIdx.x, s = blockIdx.y, t = threadIdx.x;
    int len = (s == 9) ? 192 : 128;
    int off = (s < 8) ? s * 128 : (s == 8 ? 1024 : 1152);
    __shared__ float xs[192];
    float x = 0.f;
    if (t < len) x = qkv[(long long)n * NQKVn + off + t];
    float2 sums = blockReduce2(t < len ? x : 0.f, t < len ? x * x : 0.f);
    float mu = sums.x / len;
    float var = sums.y / len - mu * mu;
    float inv = rsqrtf(var + EPS_LN);
    float y = 0.f;
    if (t < len) {
        const float* w = (s < 8) ? qn : (s == 8 ? kn : vn);
        y = (x - mu) * inv * w[t];
        if (s < 8) y *= 0.125f;
    }
    if (s == 9) { if (t < 192) v[n * DVn + t] = y; return; }
    xs[t] = y;
    __syncthreads();
    if (t < 128) {
        int d2 = t & 63;
        float invf = (d2 == 0) ? 0.1f : 0.0f;
        float f = (float)n * invf;
        float c = cosf(f), si = sinf(f);
        float rh = (t < 64) ? -xs[t + 64] : xs[t - 64];
        float out = y * c + rh * si;
        if (s < 8) q[((size_t)s * SEQn + n) * DQKn + t] = out;
        else       k[n * DQKn + t] = out;
    }
}

/* ------------- pairwise bias: rms -> gelu -> [128->8].
   8 warps/block, 8 pairs per warp; proj preloaded; next-row prefetch. ------ */
__global__ __launch_bounds__(256) void pb_kernel(
    const float* __restrict__ pair, const float* __restrict__ rw,
    const float* __restrict__ proj, float* __restrict__ pb)
{
    const int lane = threadIdx.x & 31;
    const int warp = threadIdx.x >> 5;
    const int pair0 = (blockIdx.x * 8 + warp) * 8;
    float pr[4][8];
#pragma unroll
    for (int c = 0; c < 4; c++) {
        const float* p0 = proj + (size_t)(lane * 4 + c) * Hn;
        float4 a = *(const float4*)p0;
        float4 b = *(const float4*)(p0 + 4);
        pr[c][0] = a.x; pr[c][1] = a.y; pr[c][2] = a.z; pr[c][3] = a.w;
        pr[c][4] = b.x; pr[c][5] = b.y; pr[c][6] = b.z; pr[c][7] = b.w;
    }
    const float4 w4 = *(const float4*)(rw + lane * 4);

    float4 xnext = *(const float4*)(pair + (size_t)pair0 * DPn + lane * 4);
    for (int pp = 0; pp < 8; pp++) {
        const int idx = pair0 + pp;
        float4 x = xnext;
        if (pp < 7)
            xnext = *(const float4*)(pair + (size_t)(idx + 1) * DPn + lane * 4);
        float ss = x.x * x.x + x.y * x.y + x.z * x.z + x.w * x.w;
#pragma unroll
        for (int off = 16; off > 0; off >>= 1)
            ss += __shfl_xor_sync(0xffffffffu, ss, off);
        float inv = rsqrtf(ss * (1.f / DPn) + EPS_RMS);
        float gl[4];
        {
            float y0 = x.x * inv * w4.x, y1 = x.y * inv * w4.y;
            float y2 = x.z * inv * w4.z, y3 = x.w * inv * w4.w;
            gl[0] = 0.5f * y0 * (1.f + erff(y0 * 0.70710678118654752f));
            gl[1] = 0.5f * y1 * (1.f + erff(y1 * 0.70710678118654752f));
            gl[2] = 0.5f * y2 * (1.f + erff(y2 * 0.70710678118654752f));
            gl[3] = 0.5f * y3 * (1.f + erff(y3 * 0.70710678118654752f));
        }
        float p[8] = {0.f, 0.f, 0.f, 0.f, 0.f, 0.f, 0.f, 0.f};
#pragma unroll
        for (int c = 0; c < 4; c++)
#pragma unroll
            for (int h = 0; h < 8; h++)
                p[h] = fmaf(gl[c], pr[c][h], p[h]);
#pragma unroll
        for (int off = 16; off > 0; off >>= 1)
#pragma unroll
            for (int h = 0; h < 8; h++)
                p[h] += __shfl_xor_sync(0xffffffffu, p[h], off);
        if (lane < 8) {
            float out = p[0];
#pragma unroll
            for (int h = 1; h < 8; h++) if (lane == h) out = p[h];
            int i = idx >> 8, j = idx & 255;
            pb[((size_t)lane * NPn + i) * NPn + j] = out;
        }
    }
}

/* ---------------- host launcher ---------------- */
static inline void launch_gemm(bool tb, int mode, int M, int N, int K,
                               const float* A, int lda, long long sA,
                               const float* B, int ldb, long long sB,
                               float* C, int ldc, long long sC, int batch,
                               const float* bias, const float* pbias,
                               float* rsum, const float* rscale,
                               int ksplit = 1)
{
    dim3 g((N + 127) / 128, M / 128, batch * ksplit), b(256);
    if (tb) {
        if (mode == 3)      gemm_tc<true, 3, 4><<<g, b>>>(M, N, K, A, lda, sA, B, ldb, sB, C, ldc, sC, bias, pbias, rsum, rscale, 1);
        else if (mode == 4) gemm_tc<true, 4, 4><<<g, b>>>(M, N, K, A, lda, sA, B, ldb, sB, C, ldc, sC, bias, pbias, rsum, rscale, 1);
        else                gemm_tc<true, 0, 4><<<g, b>>>(M, N, K, A, lda, sA, B, ldb, sB, C, ldc, sC, bias, pbias, rsum, rscale, 1);
    } else {
        if (mode == 1)      gemm_tc<false, 1, 4><<<g, b>>>(M, N, K, A, lda, sA, B, ldb, sB, C, ldc, sC, bias, pbias, rsum, rscale, 1);
        else if (mode == 2) gemm_tc<false, 2, 4><<<g, b>>>(M, N, K, A, lda, sA, B, ldb, sB, C, ldc, sC, bias, pbias, rsum, rscale, 1);
        else if (mode == 5) gemm_tc<false, 5, 4><<<g, b>>>(M, N, K, A, lda, sA, B, ldb, sB, C, ldc, sC, bias, pbias, rsum, rscale, ksplit);
        else                gemm_tc<false, 0, 4><<<g, b>>>(M, N, K, A, lda, sA, B, ldb, sB, C, ldc, sC, bias, pbias, rsum, rscale, 1);
    }
}

extern "C" void kernel_launch(void* const* d_in, const int* in_sizes, int n_in,
                              void* d_out, int out_size)
{
    (void)in_sizes; (void)n_in; (void)out_size;
    const float* in_single = (const float*)d_in[0];
    const float* in_pair   = (const float*)d_in[1];
    const float* W_attn_pre  = (const float*)d_in[2];
    const float* W_attn_post = (const float*)d_in[3];
    const float* W_qkv  = (const float*)d_in[4];
    const float* W_qn   = (const float*)d_in[5];
    const float* W_kn   = (const float*)d_in[6];
    const float* W_vn   = (const float*)d_in[7];
    const float* W_brms = (const float*)d_in[8];
    const float* W_bproj= (const float*)d_in[9];
    const float* W_out  = (const float*)d_in[10];
    const float* W_ffpre = (const float*)d_in[11];
    const float* W_ffpost= (const float*)d_in[12];
    const float* W_ff1  = (const float*)d_in[13];
    const float* B_ff1  = (const float*)d_in[14];
    const float* W_ff2  = (const float*)d_in[15];
    const float* B_ff2  = (const float*)d_in[16];
    const float* W_ppre = (const float*)d_in[17];
    const float* W_pqk  = (const float*)d_in[18];
    const float* W_pv   = (const float*)d_in[19];
    const float* B_pv   = (const float*)d_in[20];
    const float* W_pffpre = (const float*)d_in[21];
    const float* W_pff1 = (const float*)d_in[22];
    const float* B_pff1 = (const float*)d_in[23];
    const float* W_pff2 = (const float*)d_in[24];
    const float* B_pff2 = (const float*)d_in[25];

    float *xn, *qkv, *q, *k, *v, *sim, *pb, *ao, *t1, *rsum;
    float *pxn, *pqk, *pv, *psim, *prsum, *pt;
    cudaGetSymbolAddress((void**)&xn, g_xn);
    cudaGetSymbolAddress((void**)&qkv, g_qkv);
    cudaGetSymbolAddress((void**)&q, g_q);
    cudaGetSymbolAddress((void**)&k, g_k);
    cudaGetSymbolAddress((void**)&v, g_v);
    cudaGetSymbolAddress((void**)&sim, g_sim);
    cudaGetSymbolAddress((void**)&pb, g_pb);
    cudaGetSymbolAddress((void**)&ao, g_ao);
    cudaGetSymbolAddress((void**)&t1, g_t1);
    cudaGetSymbolAddress((void**)&rsum, g_rsum);
    cudaGetSymbolAddress((void**)&pxn, g_pxn);
    cudaGetSymbolAddress((void**)&pqk, g_pqk);
    cudaGetSymbolAddress((void**)&pv, g_pv);
    cudaGetSymbolAddress((void**)&psim, g_psim);
    cudaGetSymbolAddress((void**)&prsum, g_prsum);
    cudaGetSymbolAddress((void**)&pt, g_pt);

    /* residual streams live directly in d_out: [single | pairwise] */
    float* single = (float*)d_out;
    float* pair   = (float*)d_out + (size_t)SEQn * Dn;
    cudaMemcpyAsync(single, in_single, (size_t)SEQn * Dn * 4, cudaMemcpyDeviceToDevice);
    cudaMemcpyAsync(pair, in_pair, (size_t)NPn * NPn * DPn * 4, cudaMemcpyDeviceToDevice);

    /* xn = rmsnorm(single, attn_pre[0]) for the first layer */
    rmsnorm_k<<<SEQn, 256>>>(single, W_attn_pre, xn, Dn);

    for (int i = 0; i < 4; i++) {
        /* ---- single-track attention ---- */
        /* qkv = xn @ W_qkv, split-K x2 (176 -> 352 CTAs) */
        zero_k<<<(SEQn * NQKVn + 255) / 256, 256>>>(qkv, SEQn * NQKVn);
        launch_gemm(false, 5, SEQn, NQKVn, Dn / 2, xn, Dn, 0,
                    W_qkv + (long long)i * Dn * NQKVn, NQKVn, 0, qkv, NQKVn, 0, 1,
                    nullptr, nullptr, nullptr, nullptr, 2);
        qkv_post_k<<<dim3(SEQn, 10), 192>>>(qkv, W_qn + i * DQKn, W_kn + i * DQKn,
                                            W_vn + i * DVn, q, k, v);
        pb_kernel<<<NPn * NPn / 64, 256>>>(pair, W_brms + i * DPn, W_bproj + i * DPn * Hn, pb);
        zero_k<<<(Hn * SEQn + 255) / 256, 256>>>(rsum, Hn * SEQn);
        /* P = exp(softclamp(qk^T + pb)), rowsums accumulated */
        launch_gemm(true, 3, SEQn, SEQn, DQKn, q, DQKn, (long long)SEQn * DQKn,
                    k, DQKn, 0, sim, SEQn, (long long)SEQn * SEQn, Hn,
                    nullptr, pb, rsum, nullptr);
        /* O = (P/rowsum) V  — NT=6: CTA 128x192, exact fit for DVn */
        {
            dim3 g(1, SEQn / 128, Hn), b(256);
            gemm_tc<false, 0, 6><<<g, b>>>(SEQn, DVn, SEQn,
                sim, SEQn, (long long)SEQn * SEQn,
                v, DVn, 0, ao, Hn * DVn, DVn,
                nullptr, nullptr, nullptr, rsum, 1);
        }
        /* t1 = ao @ W_out, split-K x3 (96 -> 288 CTAs) */
        zero_k<<<(SEQn * Dn + 255) / 256, 256>>>(t1, SEQn * Dn);
        launch_gemm(false, 5, SEQn, Dn, (Hn * DVn) / 3, ao, Hn * DVn, 0,
                    W_out + (long long)i * Hn * DVn * Dn, Dn, 0, t1, Dn, 0, 1,
                    nullptr, nullptr, nullptr, nullptr, 3);
        /* single += rms(t1)*attn_post; xn = rms(single)*ff_pre */
        rmsnorm_add_norm_k<<<SEQn, 256>>>(t1, W_attn_post + i * Dn, single,
                                          W_ffpre + i * Dn, xn);

        /* ---- single-track FF ---- */
        launch_gemm(false, 1, SEQn, FFIn, Dn, xn, Dn, 0,
                    W_ff1 + (long long)i * Dn * FFIn, FFIn, 0, ao, FFIn, 0, 1,
                    B_ff1 + i * FFIn, nullptr, nullptr, nullptr);
        /* t1 = ao @ W_ff2 + b, split-K x3 (96 -> 288 CTAs) */
        zero_k<<<(SEQn * Dn + 255) / 256, 256>>>(t1, SEQn * Dn);
        launch_gemm(false, 5, SEQn, Dn, FFIn / 3, ao, FFIn, 0,
                    W_ff2 + (long long)i * FFIn * Dn, Dn, 0, t1, Dn, 0, 1,
                    B_ff2 + i * Dn, nullptr, nullptr, nullptr, 3);
        /* single += rms(t1)*ff_post; xn = rms(single)*attn_pre[i+1] (if any) */
        rmsnorm_add_norm_k<<<SEQn, 256>>>(t1, W_ffpost + i * Dn, single,
                                          (i < 3) ? W_attn_pre + (i + 1) * Dn : nullptr, xn);

        /* ---- pairwise track (layers 0, 2) ---- */
        if ((i & 1) == 0) {
            int j = i / 2;
            rmsnorm_k<<<NPn * NPn, 128>>>(pair, W_ppre + j * DPn, pxn, DPn);
            launch_gemm(false, 0, NPn * NPn, 2 * DPn, DPn, pxn, DPn, 0,
                        W_pqk + (long long)j * DPn * 2 * DPn, 2 * DPn, 0,
                        pqk, 2 * DPn, 0, 1, nullptr, nullptr, nullptr, nullptr);
            launch_gemm(false, 0, NPn * NPn, DPn, DPn, pxn, DPn, 0,
                        W_pv + (long long)j * DPn * DPn, DPn, 0,
                        pv, DPn, 0, 1, B_pv + j * DPn, nullptr, nullptr, nullptr);
            zero_k<<<(NPn * NPn + 255) / 256, 256>>>(prsum, NPn * NPn);
            launch_gemm(true, 4, NPn, NPn, DPn, pqk, 2 * DPn, (long long)NPn * 2 * DPn,
                        pqk + DPn, 2 * DPn, (long long)NPn * 2 * DPn,
                        psim, NPn, (long long)NPn * NPn, NPn,
                        nullptr, nullptr, prsum, nullptr);
            /* pair += (P/rowsum) V */
            launch_gemm(false, 2, NPn, DPn, NPn, psim, NPn, (long long)NPn * NPn,
                        pv, DPn, (long long)NPn * DPn,
                        pair, DPn, (long long)NPn * DPn, NPn,
                        nullptr, nullptr, nullptr, prsum);
            rmsnorm_k<<<NPn * NPn, 128>>>(pair, W_pffpre + j * DPn, pxn, DPn);
            launch_gemm(false, 1, NPn * NPn, DPIn, DPn, pxn, DPn, 0,
                        W_pff1 + (long long)j * DPn * DPIn, DPIn, 0,
                        pt, DPIn, 0, 1, B_pff1 + j * DPIn, nullptr, nullptr, nullptr);
            /* pair += ff2(pt) */
            launch_gemm(false, 2, NPn * NPn, DPn, DPIn, pt, DPIn, 0,
                        W_pff2 + (long long)j * DPIn * DPn, DPn, 0,
                        pair, DPn, 0, 1, B_pff2 + j * DPn, nullptr, nullptr, nullptr);
        }
    }
}

// round 11
// speedup vs baseline: 1.6117x; 1.0367x over previous
#include <cuda_runtime.h>
#include <math.h>

#define SEQn 2048
#define Dn   768
#define Hn   8
#define DQKn 128
#define DVn  192
#define NQKVn 1344   /* 8*128 + 128 + 192 */
#define NPn  256
#define DPn  128
#define FFIn 1536
#define DPIn 256
#define EPS_RMS 1.1920929e-07f
#define EPS_LN  1e-5f

/* ---------------- scratch (device globals; no allocation) ---------------- */
__device__ float g_xn[SEQn * Dn];
__device__ float g_qkv[SEQn * NQKVn];
__device__ float g_q[Hn * SEQn * DQKn];
__device__ float g_k[SEQn * DQKn];
__device__ float g_v[SEQn * DVn];
__device__ float g_sim[(size_t)Hn * SEQn * SEQn];      /* 134 MB */
__device__ float g_pb[Hn * NPn * NPn];
__device__ float g_ao[SEQn * Hn * DVn];
__device__ float g_t1[SEQn * FFIn];
__device__ float g_rsum[Hn * SEQn];
__device__ float g_pxn[NPn * NPn * DPn];
__device__ float g_pqk[NPn * NPn * 2 * DPn];
__device__ float g_pv[NPn * NPn * DPn];
__device__ float g_psim[(size_t)NPn * NPn * NPn];      /* 67 MB */
__device__ float g_prsum[NPn * NPn];
__device__ float g_pt[NPn * NPn * DPIn];

/* ---------------- helpers ---------------- */
__device__ __forceinline__ unsigned f2tf32(float x) {
    unsigned r;
    asm("cvt.rna.tf32.f32 %0, %1;" : "=r"(r) : "f"(x));
    return r;
}

__device__ __forceinline__ void mma_tf32(float* c, const unsigned* a, const unsigned* b) {
    asm volatile(
        "mma.sync.aligned.m16n8k8.row.col.f32.tf32.tf32.f32 "
        "{%0,%1,%2,%3}, {%4,%5,%6,%7}, {%8,%9}, {%0,%1,%2,%3};\n"
        : "+f"(c[0]), "+f"(c[1]), "+f"(c[2]), "+f"(c[3])
        : "r"(a[0]), "r"(a[1]), "r"(a[2]), "r"(a[3]), "r"(b[0]), "r"(b[1]));
}

__device__ __forceinline__ float softclamp_exp(float x) {
    float t = __expf(-0.4f * fabsf(x));
    float th = __fdividef(1.f - t, 1.f + t);
    return __expf(copysignf(5.f * th, x));
}

template <int OP>
__device__ __forceinline__ float blockReduce(float v) {
    __shared__ float s[33];
    int lane = threadIdx.x & 31, wid = threadIdx.x >> 5;
#pragma unroll
    for (int o = 16; o > 0; o >>= 1) {
        float ov = __shfl_down_sync(0xffffffffu, v, o);
        v = (OP == 0) ? (v + ov) : fmaxf(v, ov);
    }
    if (lane == 0) s[wid] = v;
    __syncthreads();
    if (threadIdx.x == 0) {
        int nw = (blockDim.x + 31) >> 5;
        float r = s[0];
        for (int i = 1; i < nw; i++) r = (OP == 0) ? (r + s[i]) : fmaxf(r, s[i]);
        s[32] = r;
    }
    __syncthreads();
    float r = s[32];
    __syncthreads();
    return r;
}

__global__ void zero_k(float* p, int n)
{
    int i = blockIdx.x * blockDim.x + threadIdx.x;
    if (i < n) p[i] = 0.f;
}

/* ---------------- TF32 tensor-core GEMM, 128 x (NT*32) CTA, BK=16, dbl-buf.
   8 warps in 2 x 4 grid; warp tile 64 x (NT*8). NT=4 -> CTA 128x128 (std),
   NT=6 -> CTA 128x192 (AV exact fit).
   MODE: 0 plain(+bias), 1 relu(+bias), 2 accumulate into C(+bias),
         3 sim softmax: exp(softclamp(x+pb)) + atomic row sums,
         4 pair softmax: exp(x) + atomic row sums,
         5 split-K: atomicAdd into C (+bias only from kz==0 split).
   ksplit: blockIdx.z = batch*ksplit + kz; each split covers K columns
           starting at kz*K (K = per-split depth). !TB only for ksplit>1.
   rscale (optional): multiply output rows by 1/rscale[batch*M+m].
   Requires M % 128 == 0, K % 16 == 0 (N guarded). TB only with NT=4.       */
template <bool TB, int MODE, int NT>
__global__ __launch_bounds__(256) void gemm_tc(
    int M, int N, int K,
    const float* __restrict__ A, int lda, long long sA,
    const float* __restrict__ B, int ldb, long long sB,
    float* __restrict__ C, int ldc, long long sC,
    const float* __restrict__ bias,
    const float* __restrict__ pbias,
    float* __restrict__ rsum,
    const float* __restrict__ rscale,
    int ksplit)
{
    constexpr int BN = NT * 32;
    constexpr int BNP = BN + 8;          /* ≡ 8 mod 32: conflict-free frags */
    constexpr int NCH = NT / 2;          /* float4 staging chunks (!TB)     */
    __shared__ unsigned As[2][16][136];
    __shared__ unsigned Bs[2][16][BNP];
    const int zz = blockIdx.z;
    const int batch = zz / ksplit;
    const int kz = zz - batch * ksplit;
    A += (long long)batch * sA + (long long)kz * K;
    B += (long long)batch * sB;
    if (!TB) B += (long long)kz * K * ldb;
    C += (long long)batch * sC;
    const int bm = blockIdx.y * 128, bn = blockIdx.x * BN;
    const int tid = threadIdx.x;
    const int lane = tid & 31, warp = tid >> 5;
    const int g = lane >> 2, tg = lane & 3;
    const int warpM = warp & 1, warpN = warp >> 1;

    /* staging maps */
    const int arow = tid >> 1, ak8 = (tid & 1) * 8;          /* A: 128 rows x 16 k */
    const float* Aptr = A + (long long)(bm + arow) * lda + ak8;
    const int brow = tid >> 1, bk8 = (tid & 1) * 8;          /* TB:  n-row, k segment */
    const int bkr = tid >> 4, bnc = (tid & 15) * (2 * NT);   /* !TB: k-row, n segment */
    const bool bvt = TB ? (bn + brow < N) : true;
    bool bvn[NCH];
#pragma unroll
    for (int c = 0; c < NCH; c++) bvn[c] = TB ? true : (bn + bnc + 4 * c < N);
    const float4 f0 = make_float4(0.f, 0.f, 0.f, 0.f);

    float4 pa0, pa1, pbv[NCH];
    /* prefetch stage 0 */
    {
        pa0 = *(const float4*)(Aptr);
        pa1 = *(const float4*)(Aptr + 4);
        if (TB) {
            pbv[0] = bvt ? *(const float4*)(B + (long long)(bn + brow) * ldb + bk8) : f0;
            pbv[1] = bvt ? *(const float4*)(B + (long long)(bn + brow) * ldb + bk8 + 4) : f0;
        } else {
#pragma unroll
            for (int c = 0; c < NCH; c++)
                pbv[c] = bvn[c] ? *(const float4*)(B + (long long)bkr * ldb + bn + bnc + 4 * c) : f0;
        }
    }
    /* store stage 0 */
    {
        const float* af = (const float*)&pa0;
#pragma unroll
        for (int i = 0; i < 4; i++) As[0][ak8 + i][arow] = f2tf32(af[i]);
        af = (const float*)&pa1;
#pragma unroll
        for (int i = 0; i < 4; i++) As[0][ak8 + 4 + i][arow] = f2tf32(af[i]);
        if (TB) {
            const float* bf = (const float*)&pbv[0];
#pragma unroll
            for (int i = 0; i < 4; i++) Bs[0][bk8 + i][brow] = f2tf32(bf[i]);
            bf = (const float*)&pbv[1];
#pragma unroll
            for (int i = 0; i < 4; i++) Bs[0][bk8 + 4 + i][brow] = f2tf32(bf[i]);
        } else {
#pragma unroll
            for (int c = 0; c < NCH; c++) {
                const float* bf = (const float*)&pbv[c];
#pragma unroll
                for (int i = 0; i < 4; i++) Bs[0][bkr][bnc + 4 * c + i] = f2tf32(bf[i]);
            }
        }
    }
    __syncthreads();

    float acc[4][NT][4];
#pragma unroll
    for (int mt = 0; mt < 4; mt++)
#pragma unroll
        for (int nt = 0; nt < NT; nt++)
#pragma unroll
            for (int u = 0; u < 4; u++) acc[mt][nt][u] = 0.f;

    const int nst = K >> 4;
    for (int st = 0; st < nst; st++) {
        if (st + 1 < nst) {
            int kb = (st + 1) << 4;
            pa0 = *(const float4*)(Aptr + kb);
            pa1 = *(const float4*)(Aptr + kb + 4);
            if (TB) {
                pbv[0] = bvt ? *(const float4*)(B + (long long)(bn + brow) * ldb + kb + bk8) : f0;
                pbv[1] = bvt ? *(const float4*)(B + (long long)(bn + brow) * ldb + kb + bk8 + 4) : f0;
            } else {
#pragma unroll
                for (int c = 0; c < NCH; c++)
                    pbv[c] = bvn[c] ? *(const float4*)(B + (long long)(kb + bkr) * ldb + bn + bnc + 4 * c) : f0;
            }
        }
        const int buf = st & 1;
#pragma unroll
        for (int ks = 0; ks < 2; ks++) {
            const int k8 = ks * 8;
            unsigned af[4][4], bf[NT][2];
#pragma unroll
            for (int mt = 0; mt < 4; mt++) {
                int m = warpM * 64 + mt * 16 + g;
                af[mt][0] = As[buf][k8 + tg][m];
                af[mt][1] = As[buf][k8 + tg][m + 8];
                af[mt][2] = As[buf][k8 + tg + 4][m];
                af[mt][3] = As[buf][k8 + tg + 4][m + 8];
            }
#pragma unroll
            for (int nt = 0; nt < NT; nt++) {
                int n = warpN * (NT * 8) + nt * 8 + g;
                bf[nt][0] = Bs[buf][k8 + tg][n];
                bf[nt][1] = Bs[buf][k8 + tg + 4][n];
            }
#pragma unroll
            for (int mt = 0; mt < 4; mt++)
#pragma unroll
                for (int nt = 0; nt < NT; nt++)
                    mma_tf32(acc[mt][nt], af[mt], bf[nt]);
        }
        if (st + 1 < nst) {
            const int nb = (st + 1) & 1;
            const float* af = (const float*)&pa0;
#pragma unroll
            for (int i = 0; i < 4; i++) As[nb][ak8 + i][arow] = f2tf32(af[i]);
            af = (const float*)&pa1;
#pragma unroll
            for (int i = 0; i < 4; i++) As[nb][ak8 + 4 + i][arow] = f2tf32(af[i]);
            if (TB) {
                const float* bfp = (const float*)&pbv[0];
#pragma unroll
                for (int i = 0; i < 4; i++) Bs[nb][bk8 + i][brow] = f2tf32(bfp[i]);
                bfp = (const float*)&pbv[1];
#pragma unroll
                for (int i = 0; i < 4; i++) Bs[nb][bk8 + 4 + i][brow] = f2tf32(bfp[i]);
            } else {
#pragma unroll
                for (int c = 0; c < NCH; c++) {
                    const float* bfp = (const float*)&pbv[c];
#pragma unroll
                    for (int i = 0; i < 4; i++) Bs[nb][bkr][bnc + 4 * c + i] = f2tf32(bfp[i]);
                }
            }
        }
        __syncthreads();
    }

    /* ---- epilogue (mma fragment ownership: rows g/g+8, cols tg*2, tg*2+1) ---- */
#pragma unroll
    for (int mt = 0; mt < 4; mt++) {
        const int m0 = bm + warpM * 64 + mt * 16 + g;
        const int m1 = m0 + 8;
        float inv0 = 1.f, inv1 = 1.f;
        if (rscale) {
            inv0 = 1.f / rscale[(size_t)batch * M + m0];
            inv1 = 1.f / rscale[(size_t)batch * M + m1];
        }
        const float* pbr0 = nullptr;
        const float* pbr1 = nullptr;
        if (MODE == 3) {
            pbr0 = pbias + (size_t)batch * (NPn * NPn) + (size_t)(m0 >> 3) * NPn;
            pbr1 = pbias + (size_t)batch * (NPn * NPn) + (size_t)(m1 >> 3) * NPn;
        }
        float r0 = 0.f, r1 = 0.f;
#pragma unroll
        for (int nt = 0; nt < NT; nt++) {
            const int n = bn + warpN * (NT * 8) + nt * 8 + tg * 2;
            if (n < N) {
                float c0 = acc[mt][nt][0], c1 = acc[mt][nt][1];
                float c2 = acc[mt][nt][2], c3 = acc[mt][nt][3];
                if (bias && (MODE != 5 || kz == 0)) {
                    float2 bb = *(const float2*)&bias[n];
                    c0 += bb.x; c1 += bb.y; c2 += bb.x; c3 += bb.y;
                }
                if (MODE == 1) {
                    c0 = fmaxf(c0, 0.f); c1 = fmaxf(c1, 0.f);
                    c2 = fmaxf(c2, 0.f); c3 = fmaxf(c3, 0.f);
                }
                if (MODE == 3) {
                    float pb0v = pbr0[n >> 3], pb1v = pbr1[n >> 3];
                    c0 = softclamp_exp(c0 + pb0v);
                    c1 = softclamp_exp(c1 + pb0v);
                    c2 = softclamp_exp(c2 + pb1v);
                    c3 = softclamp_exp(c3 + pb1v);
                    r0 += c0 + c1; r1 += c2 + c3;
                }
                if (MODE == 4) {
                    c0 = __expf(c0); c1 = __expf(c1);
                    c2 = __expf(c2); c3 = __expf(c3);
                    r0 += c0 + c1; r1 += c2 + c3;
                }
                if (rscale) { c0 *= inv0; c1 *= inv0; c2 *= inv1; c3 *= inv1; }
                if (MODE == 5) {
                    float* p0 = &C[(long long)m0 * ldc + n];
                    float* p1 = &C[(long long)m1 * ldc + n];
                    atomicAdd(p0, c0); atomicAdd(p0 + 1, c1);
                    atomicAdd(p1, c2); atomicAdd(p1 + 1, c3);
                } else {
                    float2 w0, w1;
                    if (MODE == 2) {
                        float2 o0 = *(const float2*)&C[(long long)m0 * ldc + n];
                        float2 o1 = *(const float2*)&C[(long long)m1 * ldc + n];
                        w0.x = c0 + o0.x; w0.y = c1 + o0.y;
                        w1.x = c2 + o1.x; w1.y = c3 + o1.y;
                    } else {
                        w0.x = c0; w0.y = c1; w1.x = c2; w1.y = c3;
                    }
                    *(float2*)&C[(long long)m0 * ldc + n] = w0;
                    *(float2*)&C[(long long)m1 * ldc + n] = w1;
                }
            }
        }
        if (MODE == 3 || MODE == 4) {
            r0 += __shfl_xor_sync(0xffffffffu, r0, 1);
            r0 += __shfl_xor_sync(0xffffffffu, r0, 2);
            r1 += __shfl_xor_sync(0xffffffffu, r1, 1);
            r1 += __shfl_xor_sync(0xffffffffu, r1, 2);
            if (tg == 0) {
                atomicAdd(&rsum[(size_t)batch * M + m0], r0);
                atomicAdd(&rsum[(size_t)batch * M + m1], r1);
            }
        }
    }
}

/* ---------------- norms ---------------- */
__global__ void rmsnorm_k(const float* __restrict__ x, const float* __restrict__ w,
                          float* __restrict__ y, int cols)
{
    long long r = blockIdx.x;
    const float* xr = x + r * cols;
    float ss = 0.f;
    for (int c = threadIdx.x; c < cols; c += blockDim.x) { float v = xr[c]; ss += v * v; }
    ss = blockReduce<0>(ss);
    float inv = rsqrtf(ss / cols + EPS_RMS);
    for (int c = threadIdx.x; c < cols; c += blockDim.x)
        y[r * cols + c] = xr[c] * inv * w[c];
}

/* warp-per-row RMSNorm for 128-wide rows (pairwise track). 8 rows/block. */
__global__ __launch_bounds__(256) void rmsnorm128_k(
    const float* __restrict__ x, const float* __restrict__ w, float* __restrict__ y)
{
    const int row = blockIdx.x * 8 + (threadIdx.x >> 5);
    const int lane = threadIdx.x & 31;
    float4 v = *(const float4*)(x + (size_t)row * DPn + lane * 4);
    float ss = v.x * v.x + v.y * v.y + v.z * v.z + v.w * v.w;
#pragma unroll
    for (int o = 16; o > 0; o >>= 1)
        ss += __shfl_xor_sync(0xffffffffu, ss, o);
    float inv = rsqrtf(ss * (1.f / DPn) + EPS_RMS);
    float4 w4 = *(const float4*)(w + lane * 4);
    float4 out;
    out.x = v.x * inv * w4.x; out.y = v.y * inv * w4.y;
    out.z = v.z * inv * w4.z; out.w = v.w * inv * w4.w;
    *(float4*)(y + (size_t)row * DPn + lane * 4) = out;
}

/* res += rmsnorm(x)*w1; if (w2) out = rmsnorm(res)*w2.  cols=768, 256 thr. */
__global__ void rmsnorm_add_norm_k(const float* __restrict__ x, const float* __restrict__ w1,
                                   float* __restrict__ res, const float* __restrict__ w2,
                                   float* __restrict__ out)
{
    long long r = blockIdx.x;
    const int cols = Dn;
    const float* xr = x + r * cols;
    float xv[3], rv[3];
    float ss = 0.f;
#pragma unroll
    for (int u = 0; u < 3; u++) {
        xv[u] = xr[threadIdx.x + u * 256];
        ss += xv[u] * xv[u];
    }
    ss = blockReduce<0>(ss);
    float inv = rsqrtf(ss / cols + EPS_RMS);
    float ss2 = 0.f;
#pragma unroll
    for (int u = 0; u < 3; u++) {
        int c = threadIdx.x + u * 256;
        float v = res[r * cols + c] + xv[u] * inv * w1[c];
        res[r * cols + c] = v;
        rv[u] = v;
        ss2 += v * v;
    }
    if (w2) {
        ss2 = blockReduce<0>(ss2);
        float inv2 = rsqrtf(ss2 / cols + EPS_RMS);
#pragma unroll
        for (int u = 0; u < 3; u++) {
            int c = threadIdx.x + u * 256;
            out[r * cols + c] = rv[u] * inv2 * w2[c];
        }
    }
}

/* -------- qkv post: warp-per-segment LayerNorm + scale + rotary.
   grid SEQn x 320 threads: warp 0-7 = q heads, warp 8 = k, warp 9 = v. ---- */
__global__ __launch_bounds__(320) void qkv_post_k(
    const float* __restrict__ qkv,
    const float* __restrict__ qn, const float* __restrict__ kn,
    const float* __restrict__ vn,
    float* __restrict__ q, float* __restrict__ k, float* __restrict__ v)
{
    const int n = blockIdx.x;
    const int s = threadIdx.x >> 5;
    const int lane = threadIdx.x & 31;
    if (s < 9) {
        const int off = (s < 8) ? s * 128 : 1024;
        float4 x = *(const float4*)(qkv + (size_t)n * NQKVn + off + lane * 4);
        float sum = x.x + x.y + x.z + x.w;
        float sq = x.x * x.x + x.y * x.y + x.z * x.z + x.w * x.w;
#pragma unroll
        for (int o = 16; o > 0; o >>= 1) {
            sum += __shfl_xor_sync(0xffffffffu, sum, o);
            sq  += __shfl_xor_sync(0xffffffffu, sq, o);
        }
        float mu = sum * (1.f / 128.f);
        float var = sq * (1.f / 128.f) - mu * mu;
        float inv = rsqrtf(var + EPS_LN);
        const float* w = (s < 8) ? qn : kn;
        float4 w4 = *(const float4*)(w + lane * 4);
        float sc = (s < 8) ? 0.125f : 1.f;
        float y0 = (x.x - mu) * inv * w4.x * sc;
        float y1 = (x.y - mu) * inv * w4.y * sc;
        float y2 = (x.z - mu) * inv * w4.z * sc;
        float y3 = (x.w - mu) * inv * w4.w * sc;
        /* rotary: partner col = col ^ 64 -> lane ^ 16, same sub-index.
           fp32 inv_freq: only d2==0 (lane%16==0, j==0) has freq 0.1; else 0. */
        float p0 = __shfl_xor_sync(0xffffffffu, y0, 16);
        float sgn = (lane < 16) ? -1.f : 1.f;
        float invf = ((lane & 15) == 0) ? 0.1f : 0.f;
        float f = (float)n * invf;
        float c = cosf(f), si = sinf(f);
        float4 out = make_float4(y0 * c + sgn * p0 * si, y1, y2, y3);
        if (s < 8) *(float4*)(q + ((size_t)s * SEQn + n) * DQKn + lane * 4) = out;
        else       *(float4*)(k + (size_t)n * DQKn + lane * 4) = out;
    } else {
        const float* src = qkv + (size_t)n * NQKVn + 1152 + lane * 6;
        float2 a = *(const float2*)(src);
        float2 b = *(const float2*)(src + 2);
        float2 c2 = *(const float2*)(src + 4);
        float sum = a.x + a.y + b.x + b.y + c2.x + c2.y;
        float sq = a.x * a.x + a.y * a.y + b.x * b.x + b.y * b.y
                 + c2.x * c2.x + c2.y * c2.y;
#pragma unroll
        for (int o = 16; o > 0; o >>= 1) {
            sum += __shfl_xor_sync(0xffffffffu, sum, o);
            sq  += __shfl_xor_sync(0xffffffffu, sq, o);
        }
        float mu = sum * (1.f / 192.f);
        float var = sq * (1.f / 192.f) - mu * mu;
        float inv = rsqrtf(var + EPS_LN);
        const float* wv = vn + lane * 6;
        float2 wa = *(const float2*)(wv);
        float2 wb = *(const float2*)(wv + 2);
        float2 wc = *(const float2*)(wv + 4);
        float* dst = v + (size_t)n * DVn + lane * 6;
        float2 o0, o1, o2;
        o0.x = (a.x - mu) * inv * wa.x;  o0.y = (a.y - mu) * inv * wa.y;
        o1.x = (b.x - mu) * inv * wb.x;  o1.y = (b.y - mu) * inv * wb.y;
        o2.x = (c2.x - mu) * inv * wc.x; o2.y = (c2.y - mu) * inv * wc.y;
        *(float2*)(dst) = o0;
        *(float2*)(dst + 2) = o1;
        *(float2*)(dst + 4) = o2;
    }
}

/* ------------- pairwise bias: rms -> gelu -> [128->8].
   8 warps/block, 8 pairs per warp; proj preloaded; next-row prefetch. ------ */
__global__ __launch_bounds__(256) void pb_kernel(
    const float* __restrict__ pair, const float* __restrict__ rw,
    const float* __restrict__ proj, float* __restrict__ pb)
{
    const int lane = threadIdx.x & 31;
    const int warp = threadIdx.x >> 5;
    const int pair0 = (blockIdx.x * 8 + warp) * 8;
    float pr[4][8];
#pragma unroll
    for (int c = 0; c < 4; c++) {
        const float* p0 = proj + (size_t)(lane * 4 + c) * Hn;
        float4 a = *(const float4*)p0;
        float4 b = *(const float4*)(p0 + 4);
        pr[c][0] = a.x; pr[c][1] = a.y; pr[c][2] = a.z; pr[c][3] = a.w;
        pr[c][4] = b.x; pr[c][5] = b.y; pr[c][6] = b.z; pr[c][7] = b.w;
    }
    const float4 w4 = *(const float4*)(rw + lane * 4);

    float4 xnext = *(const float4*)(pair + (size_t)pair0 * DPn + lane * 4);
    for (int pp = 0; pp < 8; pp++) {
        const int idx = pair0 + pp;
        float4 x = xnext;
        if (pp < 7)
            xnext = *(const float4*)(pair + (size_t)(idx + 1) * DPn + lane * 4);
        float ss = x.x * x.x + x.y * x.y + x.z * x.z + x.w * x.w;
#pragma unroll
        for (int off = 16; off > 0; off >>= 1)
            ss += __shfl_xor_sync(0xffffffffu, ss, off);
        float inv = rsqrtf(ss * (1.f / DPn) + EPS_RMS);
        float gl[4];
        {
            float y0 = x.x * inv * w4.x, y1 = x.y * inv * w4.y;
            float y2 = x.z * inv * w4.z, y3 = x.w * inv * w4.w;
            gl[0] = 0.5f * y0 * (1.f + erff(y0 * 0.70710678118654752f));
            gl[1] = 0.5f * y1 * (1.f + erff(y1 * 0.70710678118654752f));
            gl[2] = 0.5f * y2 * (1.f + erff(y2 * 0.70710678118654752f));
            gl[3] = 0.5f * y3 * (1.f + erff(y3 * 0.70710678118654752f));
        }
        float p[8] = {0.f, 0.f, 0.f, 0.f, 0.f, 0.f, 0.f, 0.f};
#pragma unroll
        for (int c = 0; c < 4; c++)
#pragma unroll
            for (int h = 0; h < 8; h++)
                p[h] = fmaf(gl[c], pr[c][h], p[h]);
#pragma unroll
        for (int off = 16; off > 0; off >>= 1)
#pragma unroll
            for (int h = 0; h < 8; h++)
                p[h] += __shfl_xor_sync(0xffffffffu, p[h], off);
        if (lane < 8) {
            float out = p[0];
#pragma unroll
            for (int h = 1; h < 8; h++) if (lane == h) out = p[h];
            int i = idx >> 8, j = idx & 255;
            pb[((size_t)lane * NPn + i) * NPn + j] = out;
        }
    }
}

/* ---------------- host launcher ---------------- */
static inline void launch_gemm(bool tb, int mode, int M, int N, int K,
                               const float* A, int lda, long long sA,
                               const float* B, int ldb, long long sB,
                               float* C, int ldc, long long sC, int batch,
                               const float* bias, const float* pbias,
                               float* rsum, const float* rscale,
                               int ksplit = 1)
{
    dim3 g((N + 127) / 128, M / 128, batch * ksplit), b(256);
    if (tb) {
        if (mode == 3)      gemm_tc<true, 3, 4><<<g, b>>>(M, N, K, A, lda, sA, B, ldb, sB, C, ldc, sC, bias, pbias, rsum, rscale, 1);
        else if (mode == 4) gemm_tc<true, 4, 4><<<g, b>>>(M, N, K, A, lda, sA, B, ldb, sB, C, ldc, sC, bias, pbias, rsum, rscale, 1);
        else                gemm_tc<true, 0, 4><<<g, b>>>(M, N, K, A, lda, sA, B, ldb, sB, C, ldc, sC, bias, pbias, rsum, rscale, 1);
    } else {
        if (mode == 1)      gemm_tc<false, 1, 4><<<g, b>>>(M, N, K, A, lda, sA, B, ldb, sB, C, ldc, sC, bias, pbias, rsum, rscale, 1);
        else if (mode == 2) gemm_tc<false, 2, 4><<<g, b>>>(M, N, K, A, lda, sA, B, ldb, sB, C, ldc, sC, bias, pbias, rsum, rscale, 1);
        else if (mode == 5) gemm_tc<false, 5, 4><<<g, b>>>(M, N, K, A, lda, sA, B, ldb, sB, C, ldc, sC, bias, pbias, rsum, rscale, ksplit);
        else                gemm_tc<false, 0, 4><<<g, b>>>(M, N, K, A, lda, sA, B, ldb, sB, C, ldc, sC, bias, pbias, rsum, rscale, 1);
    }
}

extern "C" void kernel_launch(void* const* d_in, const int* in_sizes, int n_in,
                              void* d_out, int out_size)
{
    (void)in_sizes; (void)n_in; (void)out_size;
    const float* in_single = (const float*)d_in[0];
    const float* in_pair   = (const float*)d_in[1];
    const float* W_attn_pre  = (const float*)d_in[2];
    const float* W_attn_post = (const float*)d_in[3];
    const float* W_qkv  = (const float*)d_in[4];
    const float* W_qn   = (const float*)d_in[5];
    const float* W_kn   = (const float*)d_in[6];
    const float* W_vn   = (const float*)d_in[7];
    const float* W_brms = (const float*)d_in[8];
    const float* W_bproj= (const float*)d_in[9];
    const float* W_out  = (const float*)d_in[10];
    const float* W_ffpre = (const float*)d_in[11];
    const float* W_ffpost= (const float*)d_in[12];
    const float* W_ff1  = (const float*)d_in[13];
    const float* B_ff1  = (const float*)d_in[14];
    const float* W_ff2  = (const float*)d_in[15];
    const float* B_ff2  = (const float*)d_in[16];
    const float* W_ppre = (const float*)d_in[17];
    const float* W_pqk  = (const float*)d_in[18];
    const float* W_pv   = (const float*)d_in[19];
    const float* B_pv   = (const float*)d_in[20];
    const float* W_pffpre = (const float*)d_in[21];
    const float* W_pff1 = (const float*)d_in[22];
    const float* B_pff1 = (const float*)d_in[23];
    const float* W_pff2 = (const float*)d_in[24];
    const float* B_pff2 = (const float*)d_in[25];

    float *xn, *qkv, *q, *k, *v, *sim, *pb, *ao, *t1, *rsum;
    float *pxn, *pqk, *pv, *psim, *prsum, *pt;
    cudaGetSymbolAddress((void**)&xn, g_xn);
    cudaGetSymbolAddress((void**)&qkv, g_qkv);
    cudaGetSymbolAddress((void**)&q, g_q);
    cudaGetSymbolAddress((void**)&k, g_k);
    cudaGetSymbolAddress((void**)&v, g_v);
    cudaGetSymbolAddress((void**)&sim, g_sim);
    cudaGetSymbolAddress((void**)&pb, g_pb);
    cudaGetSymbolAddress((void**)&ao, g_ao);
    cudaGetSymbolAddress((void**)&t1, g_t1);
    cudaGetSymbolAddress((void**)&rsum, g_rsum);
    cudaGetSymbolAddress((void**)&pxn, g_pxn);
    cudaGetSymbolAddress((void**)&pqk, g_pqk);
    cudaGetSymbolAddress((void**)&pv, g_pv);
    cudaGetSymbolAddress((void**)&psim, g_psim);
    cudaGetSymbolAddress((void**)&prsum, g_prsum);
    cudaGetSymbolAddress((void**)&pt, g_pt);

    /* residual streams live directly in d_out: [single | pairwise] */
    float* single = (float*)d_out;
    float* pair   = (float*)d_out + (size_t)SEQn * Dn;
    cudaMemcpyAsync(single, in_single, (size_t)SEQn * Dn * 4, cudaMemcpyDeviceToDevice);
    cudaMemcpyAsync(pair, in_pair, (size_t)NPn * NPn * DPn * 4, cudaMemcpyDeviceToDevice);

    /* xn = rmsnorm(single, attn_pre[0]) for the first layer */
    rmsnorm_k<<<SEQn, 256>>>(single, W_attn_pre, xn, Dn);

    for (int i = 0; i < 4; i++) {
        /* ---- single-track attention ---- */
        /* qkv = xn @ W_qkv, split-K x2 (176 -> 352 CTAs) */
        zero_k<<<(SEQn * NQKVn + 255) / 256, 256>>>(qkv, SEQn * NQKVn);
        launch_gemm(false, 5, SEQn, NQKVn, Dn / 2, xn, Dn, 0,
                    W_qkv + (long long)i * Dn * NQKVn, NQKVn, 0, qkv, NQKVn, 0, 1,
                    nullptr, nullptr, nullptr, nullptr, 2);
        qkv_post_k<<<SEQn, 320>>>(qkv, W_qn + i * DQKn, W_kn + i * DQKn,
                                  W_vn + i * DVn, q, k, v);
        pb_kernel<<<NPn * NPn / 64, 256>>>(pair, W_brms + i * DPn, W_bproj + i * DPn * Hn, pb);
        zero_k<<<(Hn * SEQn + 255) / 256, 256>>>(rsum, Hn * SEQn);
        /* P = exp(softclamp(qk^T + pb)), rowsums accumulated */
        launch_gemm(true, 3, SEQn, SEQn, DQKn, q, DQKn, (long long)SEQn * DQKn,
                    k, DQKn, 0, sim, SEQn, (long long)SEQn * SEQn, Hn,
                    nullptr, pb, rsum, nullptr);
        /* O = (P/rowsum) V — NT=6 (CTA 128x192) + split-K x2 (128 -> 256 CTAs) */
        zero_k<<<(SEQn * Hn * DVn + 255) / 256, 256>>>(ao, SEQn * Hn * DVn);
        {
            dim3 g(1, SEQn / 128, Hn * 2), b(256);
            gemm_tc<false, 5, 6><<<g, b>>>(SEQn, DVn, SEQn / 2,
                sim, SEQn, (long long)SEQn * SEQn,
                v, DVn, 0, ao, Hn * DVn, DVn,
                nullptr, nullptr, nullptr, rsum, 2);
        }
        /* t1 = ao @ W_out, split-K x3 (96 -> 288 CTAs) */
        zero_k<<<(SEQn * Dn + 255) / 256, 256>>>(t1, SEQn * Dn);
        launch_gemm(false, 5, SEQn, Dn, (Hn * DVn) / 3, ao, Hn * DVn, 0,
                    W_out + (long long)i * Hn * DVn * Dn, Dn, 0, t1, Dn, 0, 1,
                    nullptr, nullptr, nullptr, nullptr, 3);
        /* single += rms(t1)*attn_post; xn = rms(single)*ff_pre */
        rmsnorm_add_norm_k<<<SEQn, 256>>>(t1, W_attn_post + i * Dn, single,
                                          W_ffpre + i * Dn, xn);

        /* ---- single-track FF ---- */
        launch_gemm(false, 1, SEQn, FFIn, Dn, xn, Dn, 0,
                    W_ff1 + (long long)i * Dn * FFIn, FFIn, 0, ao, FFIn, 0, 1,
                    B_ff1 + i * FFIn, nullptr, nullptr, nullptr);
        /* t1 = ao @ W_ff2 + b, split-K x3 (96 -> 288 CTAs) */
        zero_k<<<(SEQn * Dn + 255) / 256, 256>>>(t1, SEQn * Dn);
        launch_gemm(false, 5, SEQn, Dn, FFIn / 3, ao, FFIn, 0,
                    W_ff2 + (long long)i * FFIn * Dn, Dn, 0, t1, Dn, 0, 1,
                    B_ff2 + i * Dn, nullptr, nullptr, nullptr, 3);
        /* single += rms(t1)*ff_post; xn = rms(single)*attn_pre[i+1] (if any) */
        rmsnorm_add_norm_k<<<SEQn, 256>>>(t1, W_ffpost + i * Dn, single,
                                          (i < 3) ? W_attn_pre + (i + 1) * Dn : nullptr, xn);

        /* ---- pairwise track (layers 0, 2) ---- */
        if ((i & 1) == 0) {
            int j = i / 2;
            rmsnorm128_k<<<NPn * NPn / 8, 256>>>(pair, W_ppre + j * DPn, pxn);
            launch_gemm(false, 0, NPn * NPn, 2 * DPn, DPn, pxn, DPn, 0,
                        W_pqk + (long long)j * DPn * 2 * DPn, 2 * DPn, 0,
                        pqk, 2 * DPn, 0, 1, nullptr, nullptr, nullptr, nullptr);
            launch_gemm(false, 0, NPn * NPn, DPn, DPn, pxn, DPn, 0,
                        W_pv + (long long)j * DPn * DPn, DPn, 0,
                        pv, DPn, 0, 1, B_pv + j * DPn, nullptr, nullptr, nullptr);
            zero_k<<<(NPn * NPn + 255) / 256, 256>>>(prsum, NPn * NPn);
            launch_gemm(true, 4, NPn, NPn, DPn, pqk, 2 * DPn, (long long)NPn * 2 * DPn,
                        pqk + DPn, 2 * DPn, (long long)NPn * 2 * DPn,
                        psim, NPn, (long long)NPn * NPn, NPn,
                        nullptr, nullptr, prsum, nullptr);
            /* pair += (P/rowsum) V */
            launch_gemm(false, 2, NPn, DPn, NPn, psim, NPn, (long long)NPn * NPn,
                        pv, DPn, (long long)NPn * DPn,
                        pair, DPn, (long long)NPn * DPn, NPn,
                        nullptr, nullptr, nullptr, prsum);
            rmsnorm128_k<<<NPn * NPn / 8, 256>>>(pair, W_pffpre + j * DPn, pxn);
            launch_gemm(false, 1, NPn * NPn, DPIn, DPn, pxn, DPn, 0,
                        W_pff1 + (long long)j * DPn * DPIn, DPIn, 0,
                        pt, DPIn, 0, 1, B_pff1 + j * DPIn, nullptr, nullptr, nullptr);
            /* pair += ff2(pt) */
            launch_gemm(false, 2, NPn * NPn, DPn, DPIn, pt, DPIn, 0,
                        W_pff2 + (long long)j * DPIn * DPn, DPn, 0,
                        pair, DPn, 0, 1, B_pff2 + j * DPn, nullptr, nullptr, nullptr);
        }
    }
}

// round 13
// speedup vs baseline: 1.7235x; 1.0694x over previous
#include <cuda_runtime.h>
#include <math.h>

#define SEQn 2048
#define Dn   768
#define Hn   8
#define DQKn 128
#define DVn  192
#define NQKVn 1344   /* 8*128 + 128 + 192 */
#define NPn  256
#define DPn  128
#define FFIn 1536
#define DPIn 256
#define EPS_RMS 1.1920929e-07f
#define EPS_LN  1e-5f

/* ---------------- scratch (device globals; no allocation) ---------------- */
__device__ float g_xn[SEQn * Dn];
__device__ float g_qkv[SEQn * NQKVn];
__device__ float g_q[Hn * SEQn * DQKn];
__device__ float g_k[SEQn * DQKn];
__device__ float g_v[SEQn * DVn];                      /* holds fp16 (reinterpreted) */
__device__ float g_sim[(size_t)Hn * SEQn * SEQn / 2];  /* fp16 P, 67 MB */
__device__ float g_pb[Hn * NPn * NPn];
__device__ float g_ao[SEQn * Hn * DVn];
__device__ float g_t1[SEQn * FFIn];
__device__ float g_rsum[Hn * SEQn];
__device__ float g_pxn[NPn * NPn * DPn];
__device__ float g_pqk[NPn * NPn * 2 * DPn];
__device__ float g_pv[NPn * NPn * DPn];
__device__ float g_psim[(size_t)NPn * NPn * NPn];      /* 67 MB */
__device__ float g_prsum[NPn * NPn];
__device__ float g_pt[NPn * NPn * DPIn];

/* ---------------- helpers ---------------- */
__device__ __forceinline__ unsigned f2tf32(float x) {
    unsigned r;
    asm("cvt.rna.tf32.f32 %0, %1;" : "=r"(r) : "f"(x));
    return r;
}

__device__ __forceinline__ unsigned pack_f16(float lo, float hi) {
    unsigned r;
    asm("cvt.rn.f16x2.f32 %0, %1, %2;" : "=r"(r) : "f"(hi), "f"(lo));
    return r;
}

__device__ __forceinline__ void mma_tf32(float* c, const unsigned* a, const unsigned* b) {
    asm volatile(
        "mma.sync.aligned.m16n8k8.row.col.f32.tf32.tf32.f32 "
        "{%0,%1,%2,%3}, {%4,%5,%6,%7}, {%8,%9}, {%0,%1,%2,%3};\n"
        : "+f"(c[0]), "+f"(c[1]), "+f"(c[2]), "+f"(c[3])
        : "r"(a[0]), "r"(a[1]), "r"(a[2]), "r"(a[3]), "r"(b[0]), "r"(b[1]));
}

__device__ __forceinline__ void mma_f16(float* c, const unsigned* a, const unsigned* b) {
    asm volatile(
        "mma.sync.aligned.m16n8k16.row.col.f32.f16.f16.f32 "
        "{%0,%1,%2,%3}, {%4,%5,%6,%7}, {%8,%9}, {%0,%1,%2,%3};\n"
        : "+f"(c[0]), "+f"(c[1]), "+f"(c[2]), "+f"(c[3])
        : "r"(a[0]), "r"(a[1]), "r"(a[2]), "r"(a[3]), "r"(b[0]), "r"(b[1]));
}

__device__ __forceinline__ float softclamp_exp(float x) {
    float t = __expf(-0.4f * fabsf(x));
    float th = __fdividef(1.f - t, 1.f + t);
    return __expf(copysignf(5.f * th, x));
}

template <int OP>
__device__ __forceinline__ float blockReduce(float v) {
    __shared__ float s[33];
    int lane = threadIdx.x & 31, wid = threadIdx.x >> 5;
#pragma unroll
    for (int o = 16; o > 0; o >>= 1) {
        float ov = __shfl_down_sync(0xffffffffu, v, o);
        v = (OP == 0) ? (v + ov) : fmaxf(v, ov);
    }
    if (lane == 0) s[wid] = v;
    __syncthreads();
    if (threadIdx.x == 0) {
        int nw = (blockDim.x + 31) >> 5;
        float r = s[0];
        for (int i = 1; i < nw; i++) r = (OP == 0) ? (r + s[i]) : fmaxf(r, s[i]);
        s[32] = r;
    }
    __syncthreads();
    float r = s[32];
    __syncthreads();
    return r;
}

__global__ void zero_k(float* p, int n)
{
    int i = blockIdx.x * blockDim.x + threadIdx.x;
    if (i < n) p[i] = 0.f;
}

/* ---------------- TF32 tensor-core GEMM, 128 x (NT*32) CTA, BK=16, dbl-buf.
   8 warps in 2 x 4 grid; warp tile 64 x (NT*8).
   MODE: 0 plain(+bias), 1 relu(+bias), 2 accumulate into C(+bias),
         3 sim softmax: exp(softclamp(x+pb)) -> f16x2 C + atomic row sums,
         4 pair softmax: exp(x) + atomic row sums,
         5 split-K: atomicAdd into C (+bias only from kz==0 split).
   MODE3: C is fp16 storage; sC must be given in FLOAT units (= f16 elems/2).
   rscale (optional): multiply output rows by 1/rscale[batch*M+m].            */
template <bool TB, int MODE, int NT>
__global__ __launch_bounds__(256) void gemm_tc(
    int M, int N, int K,
    const float* __restrict__ A, int lda, long long sA,
    const float* __restrict__ B, int ldb, long long sB,
    float* __restrict__ C, int ldc, long long sC,
    const float* __restrict__ bias,
    const float* __restrict__ pbias,
    float* __restrict__ rsum,
    const float* __restrict__ rscale,
    int ksplit)
{
    constexpr int BN = NT * 32;
    constexpr int BNP = BN + 8;
    constexpr int NCH = NT / 2;
    __shared__ unsigned As[2][16][136];
    __shared__ unsigned Bs[2][16][BNP];
    const int zz = blockIdx.z;
    const int batch = zz / ksplit;
    const int kz = zz - batch * ksplit;
    A += (long long)batch * sA + (long long)kz * K;
    B += (long long)batch * sB;
    if (!TB) B += (long long)kz * K * ldb;
    C += (long long)batch * sC;
    const int bm = blockIdx.y * 128, bn = blockIdx.x * BN;
    const int tid = threadIdx.x;
    const int lane = tid & 31, warp = tid >> 5;
    const int g = lane >> 2, tg = lane & 3;
    const int warpM = warp & 1, warpN = warp >> 1;

    const int arow = tid >> 1, ak8 = (tid & 1) * 8;
    const float* Aptr = A + (long long)(bm + arow) * lda + ak8;
    const int brow = tid >> 1, bk8 = (tid & 1) * 8;
    const int bkr = tid >> 4, bnc = (tid & 15) * (2 * NT);
    const bool bvt = TB ? (bn + brow < N) : true;
    bool bvn[NCH];
#pragma unroll
    for (int c = 0; c < NCH; c++) bvn[c] = TB ? true : (bn + bnc + 4 * c < N);
    const float4 f0 = make_float4(0.f, 0.f, 0.f, 0.f);

    float4 pa0, pa1, pbv[NCH];
    {
        pa0 = *(const float4*)(Aptr);
        pa1 = *(const float4*)(Aptr + 4);
        if (TB) {
            pbv[0] = bvt ? *(const float4*)(B + (long long)(bn + brow) * ldb + bk8) : f0;
            pbv[1] = bvt ? *(const float4*)(B + (long long)(bn + brow) * ldb + bk8 + 4) : f0;
        } else {
#pragma unroll
            for (int c = 0; c < NCH; c++)
                pbv[c] = bvn[c] ? *(const float4*)(B + (long long)bkr * ldb + bn + bnc + 4 * c) : f0;
        }
    }
    {
        const float* af = (const float*)&pa0;
#pragma unroll
        for (int i = 0; i < 4; i++) As[0][ak8 + i][arow] = f2tf32(af[i]);
        af = (const float*)&pa1;
#pragma unroll
        for (int i = 0; i < 4; i++) As[0][ak8 + 4 + i][arow] = f2tf32(af[i]);
        if (TB) {
            const float* bf = (const float*)&pbv[0];
#pragma unroll
            for (int i = 0; i < 4; i++) Bs[0][bk8 + i][brow] = f2tf32(bf[i]);
            bf = (const float*)&pbv[1];
#pragma unroll
            for (int i = 0; i < 4; i++) Bs[0][bk8 + 4 + i][brow] = f2tf32(bf[i]);
        } else {
#pragma unroll
            for (int c = 0; c < NCH; c++) {
                const float* bf = (const float*)&pbv[c];
#pragma unroll
                for (int i = 0; i < 4; i++) Bs[0][bkr][bnc + 4 * c + i] = f2tf32(bf[i]);
            }
        }
    }
    __syncthreads();

    float acc[4][NT][4];
#pragma unroll
    for (int mt = 0; mt < 4; mt++)
#pragma unroll
        for (int nt = 0; nt < NT; nt++)
#pragma unroll
            for (int u = 0; u < 4; u++) acc[mt][nt][u] = 0.f;

    const int nst = K >> 4;
    for (int st = 0; st < nst; st++) {
        if (st + 1 < nst) {
            int kb = (st + 1) << 4;
            pa0 = *(const float4*)(Aptr + kb);
            pa1 = *(const float4*)(Aptr + kb + 4);
            if (TB) {
                pbv[0] = bvt ? *(const float4*)(B + (long long)(bn + brow) * ldb + kb + bk8) : f0;
                pbv[1] = bvt ? *(const float4*)(B + (long long)(bn + brow) * ldb + kb + bk8 + 4) : f0;
            } else {
#pragma unroll
                for (int c = 0; c < NCH; c++)
                    pbv[c] = bvn[c] ? *(const float4*)(B + (long long)(kb + bkr) * ldb + bn + bnc + 4 * c) : f0;
            }
        }
        const int buf = st & 1;
#pragma unroll
        for (int ks = 0; ks < 2; ks++) {
            const int k8 = ks * 8;
            unsigned af[4][4], bf[NT][2];
#pragma unroll
            for (int mt = 0; mt < 4; mt++) {
                int m = warpM * 64 + mt * 16 + g;
                af[mt][0] = As[buf][k8 + tg][m];
                af[mt][1] = As[buf][k8 + tg][m + 8];
                af[mt][2] = As[buf][k8 + tg + 4][m];
                af[mt][3] = As[buf][k8 + tg + 4][m + 8];
            }
#pragma unroll
            for (int nt = 0; nt < NT; nt++) {
                int n = warpN * (NT * 8) + nt * 8 + g;
                bf[nt][0] = Bs[buf][k8 + tg][n];
                bf[nt][1] = Bs[buf][k8 + tg + 4][n];
            }
#pragma unroll
            for (int mt = 0; mt < 4; mt++)
#pragma unroll
                for (int nt = 0; nt < NT; nt++)
                    mma_tf32(acc[mt][nt], af[mt], bf[nt]);
        }
        if (st + 1 < nst) {
            const int nb = (st + 1) & 1;
            const float* af = (const float*)&pa0;
#pragma unroll
            for (int i = 0; i < 4; i++) As[nb][ak8 + i][arow] = f2tf32(af[i]);
            af = (const float*)&pa1;
#pragma unroll
            for (int i = 0; i < 4; i++) As[nb][ak8 + 4 + i][arow] = f2tf32(af[i]);
            if (TB) {
                const float* bfp = (const float*)&pbv[0];
#pragma unroll
                for (int i = 0; i < 4; i++) Bs[nb][bk8 + i][brow] = f2tf32(bfp[i]);
                bfp = (const float*)&pbv[1];
#pragma unroll
                for (int i = 0; i < 4; i++) Bs[nb][bk8 + 4 + i][brow] = f2tf32(bfp[i]);
            } else {
#pragma unroll
                for (int c = 0; c < NCH; c++) {
                    const float* bfp = (const float*)&pbv[c];
#pragma unroll
                    for (int i = 0; i < 4; i++) Bs[nb][bkr][bnc + 4 * c + i] = f2tf32(bfp[i]);
                }
            }
        }
        __syncthreads();
    }

    /* ---- epilogue ---- */
#pragma unroll
    for (int mt = 0; mt < 4; mt++) {
        const int m0 = bm + warpM * 64 + mt * 16 + g;
        const int m1 = m0 + 8;
        float inv0 = 1.f, inv1 = 1.f;
        if (rscale) {
            inv0 = 1.f / rscale[(size_t)batch * M + m0];
            inv1 = 1.f / rscale[(size_t)batch * M + m1];
        }
        const float* pbr0 = nullptr;
        const float* pbr1 = nullptr;
        if (MODE == 3) {
            pbr0 = pbias + (size_t)batch * (NPn * NPn) + (size_t)(m0 >> 3) * NPn;
            pbr1 = pbias + (size_t)batch * (NPn * NPn) + (size_t)(m1 >> 3) * NPn;
        }
        float r0 = 0.f, r1 = 0.f;
#pragma unroll
        for (int nt = 0; nt < NT; nt++) {
            const int n = bn + warpN * (NT * 8) + nt * 8 + tg * 2;
            if (n < N) {
                float c0 = acc[mt][nt][0], c1 = acc[mt][nt][1];
                float c2 = acc[mt][nt][2], c3 = acc[mt][nt][3];
                if (bias && (MODE != 5 || kz == 0)) {
                    float2 bb = *(const float2*)&bias[n];
                    c0 += bb.x; c1 += bb.y; c2 += bb.x; c3 += bb.y;
                }
                if (MODE == 1) {
                    c0 = fmaxf(c0, 0.f); c1 = fmaxf(c1, 0.f);
                    c2 = fmaxf(c2, 0.f); c3 = fmaxf(c3, 0.f);
                }
                if (MODE == 3) {
                    float pb0v = pbr0[n >> 3], pb1v = pbr1[n >> 3];
                    c0 = softclamp_exp(c0 + pb0v);
                    c1 = softclamp_exp(c1 + pb0v);
                    c2 = softclamp_exp(c2 + pb1v);
                    c3 = softclamp_exp(c3 + pb1v);
                    r0 += c0 + c1; r1 += c2 + c3;
                    /* fp16 packed store (C reinterpreted as f16 rows of ldc) */
                    ((unsigned*)C)[(long long)m0 * (ldc >> 1) + (n >> 1)] = pack_f16(c0, c1);
                    ((unsigned*)C)[(long long)m1 * (ldc >> 1) + (n >> 1)] = pack_f16(c2, c3);
                } else {
                    if (MODE == 4) {
                        c0 = __expf(c0); c1 = __expf(c1);
                        c2 = __expf(c2); c3 = __expf(c3);
                        r0 += c0 + c1; r1 += c2 + c3;
                    }
                    if (rscale) { c0 *= inv0; c1 *= inv0; c2 *= inv1; c3 *= inv1; }
                    if (MODE == 5) {
                        float* p0 = &C[(long long)m0 * ldc + n];
                        float* p1 = &C[(long long)m1 * ldc + n];
                        atomicAdd(p0, c0); atomicAdd(p0 + 1, c1);
                        atomicAdd(p1, c2); atomicAdd(p1 + 1, c3);
                    } else {
                        float2 w0, w1;
                        if (MODE == 2) {
                            float2 o0 = *(const float2*)&C[(long long)m0 * ldc + n];
                            float2 o1 = *(const float2*)&C[(long long)m1 * ldc + n];
                            w0.x = c0 + o0.x; w0.y = c1 + o0.y;
                            w1.x = c2 + o1.x; w1.y = c3 + o1.y;
                        } else {
                            w0.x = c0; w0.y = c1; w1.x = c2; w1.y = c3;
                        }
                        *(float2*)&C[(long long)m0 * ldc + n] = w0;
                        *(float2*)&C[(long long)m1 * ldc + n] = w1;
                    }
                }
            }
        }
        if (MODE == 3 || MODE == 4) {
            r0 += __shfl_xor_sync(0xffffffffu, r0, 1);
            r0 += __shfl_xor_sync(0xffffffffu, r0, 2);
            r1 += __shfl_xor_sync(0xffffffffu, r1, 1);
            r1 += __shfl_xor_sync(0xffffffffu, r1, 2);
            if (tg == 0) {
                atomicAdd(&rsum[(size_t)batch * M + m0], r0);
                atomicAdd(&rsum[(size_t)batch * M + m1], r1);
            }
        }
    }
}

/* ---------------- fp16 AV GEMM: O = (P/rowsum) V, split-K x2 --------------
   P (sim) f16 [H][2048][2048], V f16 [2048][192], ao fp32 [2048][1536].
   CTA 128x192, 8 warps 2x4 (warp tile 64x48), BK=16 (1 f16 mma deep).
   grid (1, 16, H*2): z = head*2 + kz.  atomicAdd into zeroed ao.            */
__global__ __launch_bounds__(256) void gemm_av_f16(
    const unsigned* __restrict__ Aw,   /* f16 pairs, row = 1024 words */
    const unsigned* __restrict__ Bw,   /* v f16, row = 96 words */
    float* __restrict__ C,
    const float* __restrict__ rsum)
{
    __shared__ unsigned As[2][8][136];
    __shared__ unsigned Bs[2][8][200];
    const int head = blockIdx.z >> 1, kz = blockIdx.z & 1;
    const int bm = blockIdx.y * 128;
    const int tid = threadIdx.x;
    const int lane = tid & 31, warp = tid >> 5;
    const int g = lane >> 2, tg = lane & 3;
    const int warpM = warp & 1, warpN = warp >> 1;

    const unsigned* Ap = Aw + (size_t)head * (SEQn * (SEQn / 2))
                       + (size_t)(bm + (tid >> 1)) * (SEQn / 2)
                       + (size_t)kz * 512 + (tid & 1) * 4;
    const int k2r = tid >> 5;
    const unsigned* Bp = Bw + ((size_t)kz * 1024) * 96 + lane * 3;
    const int nb = lane * 6;

    uint4 pa;
    unsigned rb0[3], rb1[3];
    pa = *(const uint4*)(Ap);
    {
        const unsigned* p0 = Bp + (size_t)(2 * k2r) * 96;
        const unsigned* p1 = p0 + 96;
        rb0[0] = p0[0]; rb0[1] = p0[1]; rb0[2] = p0[2];
        rb1[0] = p1[0]; rb1[1] = p1[1]; rb1[2] = p1[2];
    }
    {
        const unsigned* u = (const unsigned*)&pa;
#pragma unroll
        for (int i = 0; i < 4; i++) As[0][(tid & 1) * 4 + i][tid >> 1] = u[i];
#pragma unroll
        for (int j = 0; j < 3; j++) {
            Bs[0][k2r][nb + 2 * j]     = __byte_perm(rb0[j], rb1[j], 0x5410);
            Bs[0][k2r][nb + 2 * j + 1] = __byte_perm(rb0[j], rb1[j], 0x7632);
        }
    }
    __syncthreads();

    float acc[4][6][4];
#pragma unroll
    for (int mt = 0; mt < 4; mt++)
#pragma unroll
        for (int nt = 0; nt < 6; nt++)
#pragma unroll
            for (int u = 0; u < 4; u++) acc[mt][nt][u] = 0.f;

    const int nst = 64;
    for (int st = 0; st < nst; st++) {
        if (st + 1 < nst) {
            pa = *(const uint4*)(Ap + (st + 1) * 8);
            const unsigned* p0 = Bp + (size_t)((st + 1) * 16 + 2 * k2r) * 96;
            const unsigned* p1 = p0 + 96;
            rb0[0] = p0[0]; rb0[1] = p0[1]; rb0[2] = p0[2];
            rb1[0] = p1[0]; rb1[1] = p1[1]; rb1[2] = p1[2];
        }
        const int buf = st & 1;
        {
            unsigned af[4][4], bf[6][2];
#pragma unroll
            for (int mt = 0; mt < 4; mt++) {
                int m = warpM * 64 + mt * 16 + g;
                af[mt][0] = As[buf][tg][m];
                af[mt][1] = As[buf][tg][m + 8];
                af[mt][2] = As[buf][tg + 4][m];
                af[mt][3] = As[buf][tg + 4][m + 8];
            }
#pragma unroll
            for (int nt = 0; nt < 6; nt++) {
                int n = warpN * 48 + nt * 8 + g;
                bf[nt][0] = Bs[buf][tg][n];
                bf[nt][1] = Bs[buf][tg + 4][n];
            }
#pragma unroll
            for (int mt = 0; mt < 4; mt++)
#pragma unroll
                for (int nt = 0; nt < 6; nt++)
                    mma_f16(acc[mt][nt], af[mt], bf[nt]);
        }
        if (st + 1 < nst) {
            const int nbuf = (st + 1) & 1;
            const unsigned* u = (const unsigned*)&pa;
#pragma unroll
            for (int i = 0; i < 4; i++) As[nbuf][(tid & 1) * 4 + i][tid >> 1] = u[i];
#pragma unroll
            for (int j = 0; j < 3; j++) {
                Bs[nbuf][k2r][nb + 2 * j]     = __byte_perm(rb0[j], rb1[j], 0x5410);
                Bs[nbuf][k2r][nb + 2 * j + 1] = __byte_perm(rb0[j], rb1[j], 0x7632);
            }
        }
        __syncthreads();
    }

#pragma unroll
    for (int mt = 0; mt < 4; mt++) {
        const int m0 = bm + warpM * 64 + mt * 16 + g;
        const int m1 = m0 + 8;
        float inv0 = 1.f / rsum[(size_t)head * SEQn + m0];
        float inv1 = 1.f / rsum[(size_t)head * SEQn + m1];
#pragma unroll
        for (int nt = 0; nt < 6; nt++) {
            const int n = head * DVn + warpN * 48 + nt * 8 + tg * 2;
            float* p0 = &C[(long long)m0 * (Hn * DVn) + n];
            float* p1 = &C[(long long)m1 * (Hn * DVn) + n];
            atomicAdd(p0,     acc[mt][nt][0] * inv0);
            atomicAdd(p0 + 1, acc[mt][nt][1] * inv0);
            atomicAdd(p1,     acc[mt][nt][2] * inv1);
            atomicAdd(p1 + 1, acc[mt][nt][3] * inv1);
        }
    }
}

/* ---------------- norms ---------------- */
__global__ void rmsnorm_k(const float* __restrict__ x, const float* __restrict__ w,
                          float* __restrict__ y, int cols)
{
    long long r = blockIdx.x;
    const float* xr = x + r * cols;
    float ss = 0.f;
    for (int c = threadIdx.x; c < cols; c += blockDim.x) { float v = xr[c]; ss += v * v; }
    ss = blockReduce<0>(ss);
    float inv = rsqrtf(ss / cols + EPS_RMS);
    for (int c = threadIdx.x; c < cols; c += blockDim.x)
        y[r * cols + c] = xr[c] * inv * w[c];
}

/* warp-per-row RMSNorm for 128-wide rows (pairwise track). 8 rows/block. */
__global__ __launch_bounds__(256) void rmsnorm128_k(
    const float* __restrict__ x, const float* __restrict__ w, float* __restrict__ y)
{
    const int row = blockIdx.x * 8 + (threadIdx.x >> 5);
    const int lane = threadIdx.x & 31;
    float4 v = *(const float4*)(x + (size_t)row * DPn + lane * 4);
    float ss = v.x * v.x + v.y * v.y + v.z * v.z + v.w * v.w;
#pragma unroll
    for (int o = 16; o > 0; o >>= 1)
        ss += __shfl_xor_sync(0xffffffffu, ss, o);
    float inv = rsqrtf(ss * (1.f / DPn) + EPS_RMS);
    float4 w4 = *(const float4*)(w + lane * 4);
    float4 out;
    out.x = v.x * inv * w4.x; out.y = v.y * inv * w4.y;
    out.z = v.z * inv * w4.z; out.w = v.w * inv * w4.w;
    *(float4*)(y + (size_t)row * DPn + lane * 4) = out;
}

/* res += rmsnorm(x)*w1; if (w2) out = rmsnorm(res)*w2.  cols=768, 256 thr. */
__global__ void rmsnorm_add_norm_k(const float* __restrict__ x, const float* __restrict__ w1,
                                   float* __restrict__ res, const float* __restrict__ w2,
                                   float* __restrict__ out)
{
    long long r = blockIdx.x;
    const int cols = Dn;
    const float* xr = x + r * cols;
    float xv[3], rv[3];
    float ss = 0.f;
#pragma unroll
    for (int u = 0; u < 3; u++) {
        xv[u] = xr[threadIdx.x + u * 256];
        ss += xv[u] * xv[u];
    }
    ss = blockReduce<0>(ss);
    float inv = rsqrtf(ss / cols + EPS_RMS);
    float ss2 = 0.f;
#pragma unroll
    for (int u = 0; u < 3; u++) {
        int c = threadIdx.x + u * 256;
        float v = res[r * cols + c] + xv[u] * inv * w1[c];
        res[r * cols + c] = v;
        rv[u] = v;
        ss2 += v * v;
    }
    if (w2) {
        ss2 = blockReduce<0>(ss2);
        float inv2 = rsqrtf(ss2 / cols + EPS_RMS);
#pragma unroll
        for (int u = 0; u < 3; u++) {
            int c = threadIdx.x + u * 256;
            out[r * cols + c] = rv[u] * inv2 * w2[c];
        }
    }
}

/* -------- qkv post: warp-per-segment LayerNorm + scale + rotary.
   warp 0-7 = q heads, warp 8 = k, warp 9 = v (v written as fp16). ---- */
__global__ __launch_bounds__(320) void qkv_post_k(
    const float* __restrict__ qkv,
    const float* __restrict__ qn, const float* __restrict__ kn,
    const float* __restrict__ vn,
    float* __restrict__ q, float* __restrict__ k, float* __restrict__ v)
{
    const int n = blockIdx.x;
    const int s = threadIdx.x >> 5;
    const int lane = threadIdx.x & 31;
    if (s < 9) {
        const int off = (s < 8) ? s * 128 : 1024;
        float4 x = *(const float4*)(qkv + (size_t)n * NQKVn + off + lane * 4);
        float sum = x.x + x.y + x.z + x.w;
        float sq = x.x * x.x + x.y * x.y + x.z * x.z + x.w * x.w;
#pragma unroll
        for (int o = 16; o > 0; o >>= 1) {
            sum += __shfl_xor_sync(0xffffffffu, sum, o);
            sq  += __shfl_xor_sync(0xffffffffu, sq, o);
        }
        float mu = sum * (1.f / 128.f);
        float var = sq * (1.f / 128.f) - mu * mu;
        float inv = rsqrtf(var + EPS_LN);
        const float* w = (s < 8) ? qn : kn;
        float4 w4 = *(const float4*)(w + lane * 4);
        float sc = (s < 8) ? 0.125f : 1.f;
        float y0 = (x.x - mu) * inv * w4.x * sc;
        float y1 = (x.y - mu) * inv * w4.y * sc;
        float y2 = (x.z - mu) * inv * w4.z * sc;
        float y3 = (x.w - mu) * inv * w4.w * sc;
        float p0 = __shfl_xor_sync(0xffffffffu, y0, 16);
        float sgn = (lane < 16) ? -1.f : 1.f;
        float invf = ((lane & 15) == 0) ? 0.1f : 0.f;
        float f = (float)n * invf;
        float c = cosf(f), si = sinf(f);
        float4 out = make_float4(y0 * c + sgn * p0 * si, y1, y2, y3);
        if (s < 8) *(float4*)(q + ((size_t)s * SEQn + n) * DQKn + lane * 4) = out;
        else       *(float4*)(k + (size_t)n * DQKn + lane * 4) = out;
    } else {
        const float* src = qkv + (size_t)n * NQKVn + 1152 + lane * 6;
        float2 a = *(const float2*)(src);
        float2 b = *(const float2*)(src + 2);
        float2 c2 = *(const float2*)(src + 4);
        float sum = a.x + a.y + b.x + b.y + c2.x + c2.y;
        float sq = a.x * a.x + a.y * a.y + b.x * b.x + b.y * b.y
                 + c2.x * c2.x + c2.y * c2.y;
#pragma unroll
        for (int o = 16; o > 0; o >>= 1) {
            sum += __shfl_xor_sync(0xffffffffu, sum, o);
            sq  += __shfl_xor_sync(0xffffffffu, sq, o);
        }
        float mu = sum * (1.f / 192.f);
        float var = sq * (1.f / 192.f) - mu * mu;
        float inv = rsqrtf(var + EPS_LN);
        const float* wv = vn + lane * 6;
        float2 wa = *(const float2*)(wv);
        float2 wb = *(const float2*)(wv + 2);
        float2 wc = *(const float2*)(wv + 4);
        unsigned* dst = (unsigned*)v + (size_t)n * (DVn / 2) + lane * 3;
        dst[0] = pack_f16((a.x - mu) * inv * wa.x,  (a.y - mu) * inv * wa.y);
        dst[1] = pack_f16((b.x - mu) * inv * wb.x,  (b.y - mu) * inv * wb.y);
        dst[2] = pack_f16((c2.x - mu) * inv * wc.x, (c2.y - mu) * inv * wc.y);
    }
}

/* ------------- pairwise bias: rms -> gelu -> [128->8]. ------------- */
__global__ __launch_bounds__(256) void pb_kernel(
    const float* __restrict__ pair, const float* __restrict__ rw,
    const float* __restrict__ proj, float* __restrict__ pb)
{
    const int lane = threadIdx.x & 31;
    const int warp = threadIdx.x >> 5;
    const int pair0 = (blockIdx.x * 8 + warp) * 8;
    float pr[4][8];
#pragma unroll
    for (int c = 0; c < 4; c++) {
        const float* p0 = proj + (size_t)(lane * 4 + c) * Hn;
        float4 a = *(const float4*)p0;
        float4 b = *(const float4*)(p0 + 4);
        pr[c][0] = a.x; pr[c][1] = a.y; pr[c][2] = a.z; pr[c][3] = a.w;
        pr[c][4] = b.x; pr[c][5] = b.y; pr[c][6] = b.z; pr[c][7] = b.w;
    }
    const float4 w4 = *(const float4*)(rw + lane * 4);

    float4 xnext = *(const float4*)(pair + (size_t)pair0 * DPn + lane * 4);
    for (int pp = 0; pp < 8; pp++) {
        const int idx = pair0 + pp;
        float4 x = xnext;
        if (pp < 7)
            xnext = *(const float4*)(pair + (size_t)(idx + 1) * DPn + lane * 4);
        float ss = x.x * x.x + x.y * x.y + x.z * x.z + x.w * x.w;
#pragma unroll
        for (int off = 16; off > 0; off >>= 1)
            ss += __shfl_xor_sync(0xffffffffu, ss, off);
        float inv = rsqrtf(ss * (1.f / DPn) + EPS_RMS);
        float gl[4];
        {
            float y0 = x.x * inv * w4.x, y1 = x.y * inv * w4.y;
            float y2 = x.z * inv * w4.z, y3 = x.w * inv * w4.w;
            gl[0] = 0.5f * y0 * (1.f + erff(y0 * 0.70710678118654752f));
            gl[1] = 0.5f * y1 * (1.f + erff(y1 * 0.70710678118654752f));
            gl[2] = 0.5f * y2 * (1.f + erff(y2 * 0.70710678118654752f));
            gl[3] = 0.5f * y3 * (1.f + erff(y3 * 0.70710678118654752f));
        }
        float p[8] = {0.f, 0.f, 0.f, 0.f, 0.f, 0.f, 0.f, 0.f};
#pragma unroll
        for (int c = 0; c < 4; c++)
#pragma unroll
            for (int h = 0; h < 8; h++)
                p[h] = fmaf(gl[c], pr[c][h], p[h]);
#pragma unroll
        for (int off = 16; off > 0; off >>= 1)
#pragma unroll
            for (int h = 0; h < 8; h++)
                p[h] += __shfl_xor_sync(0xffffffffu, p[h], off);
        if (lane < 8) {
            float out = p[0];
#pragma unroll
            for (int h = 1; h < 8; h++) if (lane == h) out = p[h];
            int i = idx >> 8, j = idx & 255;
            pb[((size_t)lane * NPn + i) * NPn + j] = out;
        }
    }
}

/* ---------------- host launcher ---------------- */
static inline void launch_gemm(bool tb, int mode, int M, int N, int K,
                               const float* A, int lda, long long sA,
                               const float* B, int ldb, long long sB,
                               float* C, int ldc, long long sC, int batch,
                               const float* bias, const float* pbias,
                               float* rsum, const float* rscale,
                               int ksplit = 1)
{
    dim3 g((N + 127) / 128, M / 128, batch * ksplit), b(256);
    if (tb) {
        if (mode == 3)      gemm_tc<true, 3, 4><<<g, b>>>(M, N, K, A, lda, sA, B, ldb, sB, C, ldc, sC, bias, pbias, rsum, rscale, 1);
        else if (mode == 4) gemm_tc<true, 4, 4><<<g, b>>>(M, N, K, A, lda, sA, B, ldb, sB, C, ldc, sC, bias, pbias, rsum, rscale, 1);
        else                gemm_tc<true, 0, 4><<<g, b>>>(M, N, K, A, lda, sA, B, ldb, sB, C, ldc, sC, bias, pbias, rsum, rscale, 1);
    } else {
        if (mode == 1)      gemm_tc<false, 1, 4><<<g, b>>>(M, N, K, A, lda, sA, B, ldb, sB, C, ldc, sC, bias, pbias, rsum, rscale, 1);
        else if (mode == 2) gemm_tc<false, 2, 4><<<g, b>>>(M, N, K, A, lda, sA, B, ldb, sB, C, ldc, sC, bias, pbias, rsum, rscale, 1);
        else if (mode == 5) gemm_tc<false, 5, 4><<<g, b>>>(M, N, K, A, lda, sA, B, ldb, sB, C, ldc, sC, bias, pbias, rsum, rscale, ksplit);
        else                gemm_tc<false, 0, 4><<<g, b>>>(M, N, K, A, lda, sA, B, ldb, sB, C, ldc, sC, bias, pbias, rsum, rscale, 1);
    }
}

extern "C" void kernel_launch(void* const* d_in, const int* in_sizes, int n_in,
                              void* d_out, int out_size)
{
    (void)in_sizes; (void)n_in; (void)out_size;
    const float* in_single = (const float*)d_in[0];
    const float* in_pair   = (const float*)d_in[1];
    const float* W_attn_pre  = (const float*)d_in[2];
    const float* W_attn_post = (const float*)d_in[3];
    const float* W_qkv  = (const float*)d_in[4];
    const float* W_qn   = (const float*)d_in[5];
    const float* W_kn   = (const float*)d_in[6];
    const float* W_vn   = (const float*)d_in[7];
    const float* W_brms = (const float*)d_in[8];
    const float* W_bproj= (const float*)d_in[9];
    const float* W_out  = (const float*)d_in[10];
    const float* W_ffpre = (const float*)d_in[11];
    const float* W_ffpost= (const float*)d_in[12];
    const float* W_ff1  = (const float*)d_in[13];
    const float* B_ff1  = (const float*)d_in[14];
    const float* W_ff2  = (const float*)d_in[15];
    const float* B_ff2  = (const float*)d_in[16];
    const float* W_ppre = (const float*)d_in[17];
    const float* W_pqk  = (const float*)d_in[18];
    const float* W_pv   = (const float*)d_in[19];
    const float* B_pv   = (const float*)d_in[20];
    const float* W_pffpre = (const float*)d_in[21];
    const float* W_pff1 = (const float*)d_in[22];
    const float* B_pff1 = (const float*)d_in[23];
    const float* W_pff2 = (const float*)d_in[24];
    const float* B_pff2 = (const float*)d_in[25];

    float *xn, *qkv, *q, *k, *v, *sim, *pb, *ao, *t1, *rsum;
    float *pxn, *pqk, *pv, *psim, *prsum, *pt;
    cudaGetSymbolAddress((void**)&xn, g_xn);
    cudaGetSymbolAddress((void**)&qkv, g_qkv);
    cudaGetSymbolAddress((void**)&q, g_q);
    cudaGetSymbolAddress((void**)&k, g_k);
    cudaGetSymbolAddress((void**)&v, g_v);
    cudaGetSymbolAddress((void**)&sim, g_sim);
    cudaGetSymbolAddress((void**)&pb, g_pb);
    cudaGetSymbolAddress((void**)&ao, g_ao);
    cudaGetSymbolAddress((void**)&t1, g_t1);
    cudaGetSymbolAddress((void**)&rsum, g_rsum);
    cudaGetSymbolAddress((void**)&pxn, g_pxn);
    cudaGetSymbolAddress((void**)&pqk, g_pqk);
    cudaGetSymbolAddress((void**)&pv, g_pv);
    cudaGetSymbolAddress((void**)&psim, g_psim);
    cudaGetSymbolAddress((void**)&prsum, g_prsum);
    cudaGetSymbolAddress((void**)&pt, g_pt);

    /* residual streams live directly in d_out: [single | pairwise] */
    float* single = (float*)d_out;
    float* pair   = (float*)d_out + (size_t)SEQn * Dn;
    cudaMemcpyAsync(single, in_single, (size_t)SEQn * Dn * 4, cudaMemcpyDeviceToDevice);
    cudaMemcpyAsync(pair, in_pair, (size_t)NPn * NPn * DPn * 4, cudaMemcpyDeviceToDevice);

    /* xn = rmsnorm(single, attn_pre[0]) for the first layer */
    rmsnorm_k<<<SEQn, 256>>>(single, W_attn_pre, xn, Dn);

    for (int i = 0; i < 4; i++) {
        /* ---- single-track attention ---- */
        zero_k<<<(SEQn * NQKVn + 255) / 256, 256>>>(qkv, SEQn * NQKVn);
        launch_gemm(false, 5, SEQn, NQKVn, Dn / 2, xn, Dn, 0,
                    W_qkv + (long long)i * Dn * NQKVn, NQKVn, 0, qkv, NQKVn, 0, 1,
                    nullptr, nullptr, nullptr, nullptr, 2);
        qkv_post_k<<<SEQn, 320>>>(qkv, W_qn + i * DQKn, W_kn + i * DQKn,
                                  W_vn + i * DVn, q, k, v);
        pb_kernel<<<NPn * NPn / 64, 256>>>(pair, W_brms + i * DPn, W_bproj + i * DPn * Hn, pb);
        zero_k<<<(Hn * SEQn + 255) / 256, 256>>>(rsum, Hn * SEQn);
        /* P = exp(softclamp(qk^T + pb)) -> f16 sim + rowsums (head stride in floats = S*S/2) */
        launch_gemm(true, 3, SEQn, SEQn, DQKn, q, DQKn, (long long)SEQn * DQKn,
                    k, DQKn, 0, sim, SEQn, (long long)SEQn * SEQn / 2, Hn,
                    nullptr, pb, rsum, nullptr);
        /* O = (P/rowsum) V — f16 mma, split-K x2 */
        zero_k<<<(SEQn * Hn * DVn + 255) / 256, 256>>>(ao, SEQn * Hn * DVn);
        gemm_av_f16<<<dim3(1, SEQn / 128, Hn * 2), 256>>>(
            (const unsigned*)sim, (const unsigned*)v, ao, rsum);
        /* t1 = ao @ W_out, split-K x3 */
        zero_k<<<(SEQn * Dn + 255) / 256, 256>>>(t1, SEQn * Dn);
        launch_gemm(false, 5, SEQn, Dn, (Hn * DVn) / 3, ao, Hn * DVn, 0,
                    W_out + (long long)i * Hn * DVn * Dn, Dn, 0, t1, Dn, 0, 1,
                    nullptr, nullptr, nullptr, nullptr, 3);
        rmsnorm_add_norm_k<<<SEQn, 256>>>(t1, W_attn_post + i * Dn, single,
                                          W_ffpre + i * Dn, xn);

        /* ---- single-track FF ---- */
        launch_gemm(false, 1, SEQn, FFIn, Dn, xn, Dn, 0,
                    W_ff1 + (long long)i * Dn * FFIn, FFIn, 0, ao, FFIn, 0, 1,
                    B_ff1 + i * FFIn, nullptr, nullptr, nullptr);
        zero_k<<<(SEQn * Dn + 255) / 256, 256>>>(t1, SEQn * Dn);
        launch_gemm(false, 5, SEQn, Dn, FFIn / 3, ao, FFIn, 0,
                    W_ff2 + (long long)i * FFIn * Dn, Dn, 0, t1, Dn, 0, 1,
                    B_ff2 + i * Dn, nullptr, nullptr, nullptr, 3);
        rmsnorm_add_norm_k<<<SEQn, 256>>>(t1, W_ffpost + i * Dn, single,
                                          (i < 3) ? W_attn_pre + (i + 1) * Dn : nullptr, xn);

        /* ---- pairwise track (layers 0, 2) ---- */
        if ((i & 1) == 0) {
            int j = i / 2;
            rmsnorm128_k<<<NPn * NPn / 8, 256>>>(pair, W_ppre + j * DPn, pxn);
            launch_gemm(false, 0, NPn * NPn, 2 * DPn, DPn, pxn, DPn, 0,
                        W_pqk + (long long)j * DPn * 2 * DPn, 2 * DPn, 0,
                        pqk, 2 * DPn, 0, 1, nullptr, nullptr, nullptr, nullptr);
            launch_gemm(false, 0, NPn * NPn, DPn, DPn, pxn, DPn, 0,
                        W_pv + (long long)j * DPn * DPn, DPn, 0,
                        pv, DPn, 0, 1, B_pv + j * DPn, nullptr, nullptr, nullptr);
            zero_k<<<(NPn * NPn + 255) / 256, 256>>>(prsum, NPn * NPn);
            launch_gemm(true, 4, NPn, NPn, DPn, pqk, 2 * DPn, (long long)NPn * 2 * DPn,
                        pqk + DPn, 2 * DPn, (long long)NPn * 2 * DPn,
                        psim, NPn, (long long)NPn * NPn, NPn,
                        nullptr, nullptr, prsum, nullptr);
            launch_gemm(false, 2, NPn, DPn, NPn, psim, NPn, (long long)NPn * NPn,
                        pv, DPn, (long long)NPn * DPn,
                        pair, DPn, (long long)NPn * DPn, NPn,
                        nullptr, nullptr, nullptr, prsum);
            rmsnorm128_k<<<NPn * NPn / 8, 256>>>(pair, W_pffpre + j * DPn, pxn);
            launch_gemm(false, 1, NPn * NPn, DPIn, DPn, pxn, DPn, 0,
                        W_pff1 + (long long)j * DPn * DPIn, DPIn, 0,
                        pt, DPIn, 0, 1, B_pff1 + j * DPIn, nullptr, nullptr, nullptr);
            launch_gemm(false, 2, NPn * NPn, DPn, DPIn, pt, DPIn, 0,
                        W_pff2 + (long long)j * DPIn * DPn, DPn, 0,
                        pair, DPn, 0, 1, B_pff2 + j * DPn, nullptr, nullptr, nullptr);
        }
    }
}

// round 14
// speedup vs baseline: 2.1450x; 1.2446x over previous
#include <cuda_runtime.h>
#include <math.h>

#define SEQn 2048
#define Dn   768
#define Hn   8
#define DQKn 128
#define DVn  192
#define NQKVn 1344   /* 8*128 + 128 + 192 */
#define NPn  256
#define DPn  128
#define FFIn 1536
#define DPIn 256
#define EPS_RMS 1.1920929e-07f
#define EPS_LN  1e-5f

/* ---------------- scratch (device globals; no allocation) ---------------- */
__device__ float g_xn[SEQn * Dn];
__device__ float g_qkv[SEQn * NQKVn];
__device__ float g_q[Hn * SEQn * DQKn];
__device__ float g_k[SEQn * DQKn];
__device__ float g_v[SEQn * DVn];                      /* holds fp16 (reinterpreted) */
__device__ float g_sim[(size_t)Hn * SEQn * SEQn / 2];  /* fp16 P, 67 MB */
__device__ float g_pb[Hn * NPn * NPn];
__device__ float g_ao[SEQn * Hn * DVn];
__device__ float g_t1[SEQn * FFIn];
__device__ float g_rsum[Hn * SEQn];
__device__ float g_pxn[NPn * NPn * DPn];
__device__ float g_pqk[NPn * NPn * 2 * DPn];
__device__ float g_pv[NPn * NPn * DPn];
__device__ float g_psim[(size_t)NPn * NPn * NPn];      /* 67 MB */
__device__ float g_prsum[NPn * NPn];
__device__ float g_pt[NPn * NPn * DPIn];

/* ---------------- helpers ---------------- */
__device__ __forceinline__ unsigned pack_f16(float lo, float hi) {
    unsigned r;
    asm("cvt.rn.f16x2.f32 %0, %1, %2;" : "=r"(r) : "f"(hi), "f"(lo));
    return r;
}

__device__ __forceinline__ void mma_f16(float* c, const unsigned* a, const unsigned* b) {
    asm volatile(
        "mma.sync.aligned.m16n8k16.row.col.f32.f16.f16.f32 "
        "{%0,%1,%2,%3}, {%4,%5,%6,%7}, {%8,%9}, {%0,%1,%2,%3};\n"
        : "+f"(c[0]), "+f"(c[1]), "+f"(c[2]), "+f"(c[3])
        : "r"(a[0]), "r"(a[1]), "r"(a[2]), "r"(a[3]), "r"(b[0]), "r"(b[1]));
}

__device__ __forceinline__ float softclamp_exp(float x) {
    float t = __expf(-0.4f * fabsf(x));
    float th = __fdividef(1.f - t, 1.f + t);
    return __expf(copysignf(5.f * th, x));
}

template <int OP>
__device__ __forceinline__ float blockReduce(float v) {
    __shared__ float s[33];
    int lane = threadIdx.x & 31, wid = threadIdx.x >> 5;
#pragma unroll
    for (int o = 16; o > 0; o >>= 1) {
        float ov = __shfl_down_sync(0xffffffffu, v, o);
        v = (OP == 0) ? (v + ov) : fmaxf(v, ov);
    }
    if (lane == 0) s[wid] = v;
    __syncthreads();
    if (threadIdx.x == 0) {
        int nw = (blockDim.x + 31) >> 5;
        float r = s[0];
        for (int i = 1; i < nw; i++) r = (OP == 0) ? (r + s[i]) : fmaxf(r, s[i]);
        s[32] = r;
    }
    __syncthreads();
    float r = s[32];
    __syncthreads();
    return r;
}

__global__ void zero_k(float* p, int n)
{
    int i = blockIdx.x * blockDim.x + threadIdx.x;
    if (i < n) p[i] = 0.f;
}

/* ---------------- FP16 tensor-core GEMM, 128x128 CTA, BK=16, dbl-buf.
   8 warps in 2x4 grid; warp tile 64x32. fp32 inputs converted to f16 at
   staging, packed as k-pairs per smem word (validated AV fragment layout).
   MODE: 0 plain(+bias), 1 relu(+bias), 2 accumulate into C(+bias),
         3 sim softmax: exp(softclamp(x+pb)) -> f16x2 C + atomic row sums,
         4 pair softmax: exp(x) + atomic row sums,
         5 split-K: atomicAdd into C (+bias only from kz==0 split).
   MODE3: C is fp16 storage; sC given in FLOAT units (= f16 elems/2).
   rscale (optional): multiply output rows by 1/rscale[batch*M+m].
   Requires M%128==0, K%16==0, N%4==0 (N tile-edge guarded).                 */
template <bool TB, int MODE>
__global__ __launch_bounds__(256) void gemm_tc(
    int M, int N, int K,
    const float* __restrict__ A, int lda, long long sA,
    const float* __restrict__ B, int ldb, long long sB,
    float* __restrict__ C, int ldc, long long sC,
    const float* __restrict__ bias,
    const float* __restrict__ pbias,
    float* __restrict__ rsum,
    const float* __restrict__ rscale,
    int ksplit)
{
    __shared__ unsigned As[2][8][136];   /* [k-pair 0..7][128 rows + pad] */
    __shared__ unsigned Bs[2][8][136];
    const int zz = blockIdx.z;
    const int batch = zz / ksplit;
    const int kz = zz - batch * ksplit;
    A += (long long)batch * sA + (long long)kz * K;
    B += (long long)batch * sB;
    if (!TB) B += (long long)kz * K * ldb;
    C += (long long)batch * sC;
    const int bm = blockIdx.y * 128, bn = blockIdx.x * 128;
    const int tid = threadIdx.x;
    const int lane = tid & 31, warp = tid >> 5;
    const int g = lane >> 2, tg = lane & 3;
    const int warpM = warp & 1, warpN = warp >> 1;   /* 2 x 4 warps -> 64x32 tiles */

    /* A staging: row = tid>>1, k segment (tid&1)*8 (8 floats -> 4 pair-words) */
    const int arow = tid >> 1, ap4 = (tid & 1) * 4;
    const float* Aptr = A + (long long)(bm + arow) * lda + (tid & 1) * 8;
    /* B TB: n-row = tid>>1, k segment (tid&1)*8 — same packing as A */
    const bool bvt = TB ? (bn + arow < N) : true;
    /* B !TB: k-pair row k2r = tid>>5 (0..7), n quad (tid&31)*4 */
    const int k2r = tid >> 5, bn4 = (lane) * 4;
    const bool bvn = TB ? true : (bn + bn4 < N);
    const float4 f0 = make_float4(0.f, 0.f, 0.f, 0.f);

    float4 pa0, pa1, pb0, pb1;
    /* prefetch stage 0 */
    {
        pa0 = *(const float4*)(Aptr);
        pa1 = *(const float4*)(Aptr + 4);
        if (TB) {
            pb0 = bvt ? *(const float4*)(B + (long long)(bn + arow) * ldb + (tid & 1) * 8) : f0;
            pb1 = bvt ? *(const float4*)(B + (long long)(bn + arow) * ldb + (tid & 1) * 8 + 4) : f0;
        } else {
            pb0 = bvn ? *(const float4*)(B + (long long)(2 * k2r) * ldb + bn + bn4) : f0;
            pb1 = bvn ? *(const float4*)(B + (long long)(2 * k2r + 1) * ldb + bn + bn4) : f0;
        }
    }
    /* store stage 0 */
    {
        As[0][ap4 + 0][arow] = pack_f16(pa0.x, pa0.y);
        As[0][ap4 + 1][arow] = pack_f16(pa0.z, pa0.w);
        As[0][ap4 + 2][arow] = pack_f16(pa1.x, pa1.y);
        As[0][ap4 + 3][arow] = pack_f16(pa1.z, pa1.w);
        if (TB) {
            Bs[0][ap4 + 0][arow] = pack_f16(pb0.x, pb0.y);
            Bs[0][ap4 + 1][arow] = pack_f16(pb0.z, pb0.w);
            Bs[0][ap4 + 2][arow] = pack_f16(pb1.x, pb1.y);
            Bs[0][ap4 + 3][arow] = pack_f16(pb1.z, pb1.w);
        } else {
            Bs[0][k2r][bn4 + 0] = pack_f16(pb0.x, pb1.x);
            Bs[0][k2r][bn4 + 1] = pack_f16(pb0.y, pb1.y);
            Bs[0][k2r][bn4 + 2] = pack_f16(pb0.z, pb1.z);
            Bs[0][k2r][bn4 + 3] = pack_f16(pb0.w, pb1.w);
        }
    }
    __syncthreads();

    float acc[4][4][4];
#pragma unroll
    for (int mt = 0; mt < 4; mt++)
#pragma unroll
        for (int nt = 0; nt < 4; nt++)
#pragma unroll
            for (int u = 0; u < 4; u++) acc[mt][nt][u] = 0.f;

    const int nst = K >> 4;
    for (int st = 0; st < nst; st++) {
        if (st + 1 < nst) {
            int kb = (st + 1) << 4;
            pa0 = *(const float4*)(Aptr + kb);
            pa1 = *(const float4*)(Aptr + kb + 4);
            if (TB) {
                pb0 = bvt ? *(const float4*)(B + (long long)(bn + arow) * ldb + kb + (tid & 1) * 8) : f0;
                pb1 = bvt ? *(const float4*)(B + (long long)(bn + arow) * ldb + kb + (tid & 1) * 8 + 4) : f0;
            } else {
                pb0 = bvn ? *(const float4*)(B + (long long)(kb + 2 * k2r) * ldb + bn + bn4) : f0;
                pb1 = bvn ? *(const float4*)(B + (long long)(kb + 2 * k2r + 1) * ldb + bn + bn4) : f0;
            }
        }
        const int buf = st & 1;
        {
            unsigned af[4][4], bf[4][2];
#pragma unroll
            for (int mt = 0; mt < 4; mt++) {
                int m = warpM * 64 + mt * 16 + g;
                af[mt][0] = As[buf][tg][m];
                af[mt][1] = As[buf][tg][m + 8];
                af[mt][2] = As[buf][tg + 4][m];
                af[mt][3] = As[buf][tg + 4][m + 8];
            }
#pragma unroll
            for (int nt = 0; nt < 4; nt++) {
                int n = warpN * 32 + nt * 8 + g;
                bf[nt][0] = Bs[buf][tg][n];
                bf[nt][1] = Bs[buf][tg + 4][n];
            }
#pragma unroll
            for (int mt = 0; mt < 4; mt++)
#pragma unroll
                for (int nt = 0; nt < 4; nt++)
                    mma_f16(acc[mt][nt], af[mt], bf[nt]);
        }
        if (st + 1 < nst) {
            const int nb = (st + 1) & 1;
            As[nb][ap4 + 0][arow] = pack_f16(pa0.x, pa0.y);
            As[nb][ap4 + 1][arow] = pack_f16(pa0.z, pa0.w);
            As[nb][ap4 + 2][arow] = pack_f16(pa1.x, pa1.y);
            As[nb][ap4 + 3][arow] = pack_f16(pa1.z, pa1.w);
            if (TB) {
                Bs[nb][ap4 + 0][arow] = pack_f16(pb0.x, pb0.y);
                Bs[nb][ap4 + 1][arow] = pack_f16(pb0.z, pb0.w);
                Bs[nb][ap4 + 2][arow] = pack_f16(pb1.x, pb1.y);
                Bs[nb][ap4 + 3][arow] = pack_f16(pb1.z, pb1.w);
            } else {
                Bs[nb][k2r][bn4 + 0] = pack_f16(pb0.x, pb1.x);
                Bs[nb][k2r][bn4 + 1] = pack_f16(pb0.y, pb1.y);
                Bs[nb][k2r][bn4 + 2] = pack_f16(pb0.z, pb1.z);
                Bs[nb][k2r][bn4 + 3] = pack_f16(pb0.w, pb1.w);
            }
        }
        __syncthreads();
    }

    /* ---- epilogue (fragment ownership: rows g/g+8, cols tg*2, tg*2+1) ---- */
#pragma unroll
    for (int mt = 0; mt < 4; mt++) {
        const int m0 = bm + warpM * 64 + mt * 16 + g;
        const int m1 = m0 + 8;
        float inv0 = 1.f, inv1 = 1.f;
        if (rscale) {
            inv0 = 1.f / rscale[(size_t)batch * M + m0];
            inv1 = 1.f / rscale[(size_t)batch * M + m1];
        }
        const float* pbr0 = nullptr;
        const float* pbr1 = nullptr;
        if (MODE == 3) {
            pbr0 = pbias + (size_t)batch * (NPn * NPn) + (size_t)(m0 >> 3) * NPn;
            pbr1 = pbias + (size_t)batch * (NPn * NPn) + (size_t)(m1 >> 3) * NPn;
        }
        float r0 = 0.f, r1 = 0.f;
#pragma unroll
        for (int nt = 0; nt < 4; nt++) {
            const int n = bn + warpN * 32 + nt * 8 + tg * 2;
            if (n < N) {
                float c0 = acc[mt][nt][0], c1 = acc[mt][nt][1];
                float c2 = acc[mt][nt][2], c3 = acc[mt][nt][3];
                if (bias && (MODE != 5 || kz == 0)) {
                    float2 bb = *(const float2*)&bias[n];
                    c0 += bb.x; c1 += bb.y; c2 += bb.x; c3 += bb.y;
                }
                if (MODE == 1) {
                    c0 = fmaxf(c0, 0.f); c1 = fmaxf(c1, 0.f);
                    c2 = fmaxf(c2, 0.f); c3 = fmaxf(c3, 0.f);
                }
                if (MODE == 3) {
                    float pb0v = pbr0[n >> 3], pb1v = pbr1[n >> 3];
                    c0 = softclamp_exp(c0 + pb0v);
                    c1 = softclamp_exp(c1 + pb0v);
                    c2 = softclamp_exp(c2 + pb1v);
                    c3 = softclamp_exp(c3 + pb1v);
                    r0 += c0 + c1; r1 += c2 + c3;
                    ((unsigned*)C)[(long long)m0 * (ldc >> 1) + (n >> 1)] = pack_f16(c0, c1);
                    ((unsigned*)C)[(long long)m1 * (ldc >> 1) + (n >> 1)] = pack_f16(c2, c3);
                } else {
                    if (MODE == 4) {
                        c0 = __expf(c0); c1 = __expf(c1);
                        c2 = __expf(c2); c3 = __expf(c3);
                        r0 += c0 + c1; r1 += c2 + c3;
                    }
                    if (rscale) { c0 *= inv0; c1 *= inv0; c2 *= inv1; c3 *= inv1; }
                    if (MODE == 5) {
                        float* p0 = &C[(long long)m0 * ldc + n];
                        float* p1 = &C[(long long)m1 * ldc + n];
                        atomicAdd(p0, c0); atomicAdd(p0 + 1, c1);
                        atomicAdd(p1, c2); atomicAdd(p1 + 1, c3);
                    } else {
                        float2 w0, w1;
                        if (MODE == 2) {
                            float2 o0 = *(const float2*)&C[(long long)m0 * ldc + n];
                            float2 o1 = *(const float2*)&C[(long long)m1 * ldc + n];
                            w0.x = c0 + o0.x; w0.y = c1 + o0.y;
                            w1.x = c2 + o1.x; w1.y = c3 + o1.y;
                        } else {
                            w0.x = c0; w0.y = c1; w1.x = c2; w1.y = c3;
                        }
                        *(float2*)&C[(long long)m0 * ldc + n] = w0;
                        *(float2*)&C[(long long)m1 * ldc + n] = w1;
                    }
                }
            }
        }
        if (MODE == 3 || MODE == 4) {
            r0 += __shfl_xor_sync(0xffffffffu, r0, 1);
            r0 += __shfl_xor_sync(0xffffffffu, r0, 2);
            r1 += __shfl_xor_sync(0xffffffffu, r1, 1);
            r1 += __shfl_xor_sync(0xffffffffu, r1, 2);
            if (tg == 0) {
                atomicAdd(&rsum[(size_t)batch * M + m0], r0);
                atomicAdd(&rsum[(size_t)batch * M + m1], r1);
            }
        }
    }
}

/* ---------------- fp16 AV GEMM: O = (P/rowsum) V, split-K x2 --------------
   P (sim) f16 [H][2048][2048], V f16 [2048][192], ao fp32 [2048][1536].
   CTA 128x192, 8 warps 2x4 (warp tile 64x48), BK=16.
   grid (1, 16, H*2): z = head*2 + kz.  atomicAdd into zeroed ao.            */
__global__ __launch_bounds__(256) void gemm_av_f16(
    const unsigned* __restrict__ Aw,   /* f16 pairs, row = 1024 words */
    const unsigned* __restrict__ Bw,   /* v f16, row = 96 words */
    float* __restrict__ C,
    const float* __restrict__ rsum)
{
    __shared__ unsigned As[2][8][136];
    __shared__ unsigned Bs[2][8][200];
    const int head = blockIdx.z >> 1, kz = blockIdx.z & 1;
    const int bm = blockIdx.y * 128;
    const int tid = threadIdx.x;
    const int lane = tid & 31, warp = tid >> 5;
    const int g = lane >> 2, tg = lane & 3;
    const int warpM = warp & 1, warpN = warp >> 1;

    const unsigned* Ap = Aw + (size_t)head * (SEQn * (SEQn / 2))
                       + (size_t)(bm + (tid >> 1)) * (SEQn / 2)
                       + (size_t)kz * 512 + (tid & 1) * 4;
    const int k2r = tid >> 5;
    const unsigned* Bp = Bw + ((size_t)kz * 1024) * 96 + lane * 3;
    const int nb = lane * 6;

    uint4 pa;
    unsigned rb0[3], rb1[3];
    pa = *(const uint4*)(Ap);
    {
        const unsigned* p0 = Bp + (size_t)(2 * k2r) * 96;
        const unsigned* p1 = p0 + 96;
        rb0[0] = p0[0]; rb0[1] = p0[1]; rb0[2] = p0[2];
        rb1[0] = p1[0]; rb1[1] = p1[1]; rb1[2] = p1[2];
    }
    {
        const unsigned* u = (const unsigned*)&pa;
#pragma unroll
        for (int i = 0; i < 4; i++) As[0][(tid & 1) * 4 + i][tid >> 1] = u[i];
#pragma unroll
        for (int j = 0; j < 3; j++) {
            Bs[0][k2r][nb + 2 * j]     = __byte_perm(rb0[j], rb1[j], 0x5410);
            Bs[0][k2r][nb + 2 * j + 1] = __byte_perm(rb0[j], rb1[j], 0x7632);
        }
    }
    __syncthreads();

    float acc[4][6][4];
#pragma unroll
    for (int mt = 0; mt < 4; mt++)
#pragma unroll
        for (int nt = 0; nt < 6; nt++)
#pragma unroll
            for (int u = 0; u < 4; u++) acc[mt][nt][u] = 0.f;

    const int nst = 64;
    for (int st = 0; st < nst; st++) {
        if (st + 1 < nst) {
            pa = *(const uint4*)(Ap + (st + 1) * 8);
            const unsigned* p0 = Bp + (size_t)((st + 1) * 16 + 2 * k2r) * 96;
            const unsigned* p1 = p0 + 96;
            rb0[0] = p0[0]; rb0[1] = p0[1]; rb0[2] = p0[2];
            rb1[0] = p1[0]; rb1[1] = p1[1]; rb1[2] = p1[2];
        }
        const int buf = st & 1;
        {
            unsigned af[4][4], bf[6][2];
#pragma unroll
            for (int mt = 0; mt < 4; mt++) {
                int m = warpM * 64 + mt * 16 + g;
                af[mt][0] = As[buf][tg][m];
                af[mt][1] = As[buf][tg][m + 8];
                af[mt][2] = As[buf][tg + 4][m];
                af[mt][3] = As[buf][tg + 4][m + 8];
            }
#pragma unroll
            for (int nt = 0; nt < 6; nt++) {
                int n = warpN * 48 + nt * 8 + g;
                bf[nt][0] = Bs[buf][tg][n];
                bf[nt][1] = Bs[buf][tg + 4][n];
            }
#pragma unroll
            for (int mt = 0; mt < 4; mt++)
#pragma unroll
                for (int nt = 0; nt < 6; nt++)
                    mma_f16(acc[mt][nt], af[mt], bf[nt]);
        }
        if (st + 1 < nst) {
            const int nbuf = (st + 1) & 1;
            const unsigned* u = (const unsigned*)&pa;
#pragma unroll
            for (int i = 0; i < 4; i++) As[nbuf][(tid & 1) * 4 + i][tid >> 1] = u[i];
#pragma unroll
            for (int j = 0; j < 3; j++) {
                Bs[nbuf][k2r][nb + 2 * j]     = __byte_perm(rb0[j], rb1[j], 0x5410);
                Bs[nbuf][k2r][nb + 2 * j + 1] = __byte_perm(rb0[j], rb1[j], 0x7632);
            }
        }
        __syncthreads();
    }

#pragma unroll
    for (int mt = 0; mt < 4; mt++) {
        const int m0 = bm + warpM * 64 + mt * 16 + g;
        const int m1 = m0 + 8;
        float inv0 = 1.f / rsum[(size_t)head * SEQn + m0];
        float inv1 = 1.f / rsum[(size_t)head * SEQn + m1];
#pragma unroll
        for (int nt = 0; nt < 6; nt++) {
            const int n = head * DVn + warpN * 48 + nt * 8 + tg * 2;
            float* p0 = &C[(long long)m0 * (Hn * DVn) + n];
            float* p1 = &C[(long long)m1 * (Hn * DVn) + n];
            atomicAdd(p0,     acc[mt][nt][0] * inv0);
            atomicAdd(p0 + 1, acc[mt][nt][1] * inv0);
            atomicAdd(p1,     acc[mt][nt][2] * inv1);
            atomicAdd(p1 + 1, acc[mt][nt][3] * inv1);
        }
    }
}

/* ---------------- norms ---------------- */
__global__ void rmsnorm_k(const float* __restrict__ x, const float* __restrict__ w,
                          float* __restrict__ y, int cols)
{
    long long r = blockIdx.x;
    const float* xr = x + r * cols;
    float ss = 0.f;
    for (int c = threadIdx.x; c < cols; c += blockDim.x) { float v = xr[c]; ss += v * v; }
    ss = blockReduce<0>(ss);
    float inv = rsqrtf(ss / cols + EPS_RMS);
    for (int c = threadIdx.x; c < cols; c += blockDim.x)
        y[r * cols + c] = xr[c] * inv * w[c];
}

/* warp-per-row RMSNorm for 128-wide rows (pairwise track). 8 rows/block. */
__global__ __launch_bounds__(256) void rmsnorm128_k(
    const float* __restrict__ x, const float* __restrict__ w, float* __restrict__ y)
{
    const int row = blockIdx.x * 8 + (threadIdx.x >> 5);
    const int lane = threadIdx.x & 31;
    float4 v = *(const float4*)(x + (size_t)row * DPn + lane * 4);
    float ss = v.x * v.x + v.y * v.y + v.z * v.z + v.w * v.w;
#pragma unroll
    for (int o = 16; o > 0; o >>= 1)
        ss += __shfl_xor_sync(0xffffffffu, ss, o);
    float inv = rsqrtf(ss * (1.f / DPn) + EPS_RMS);
    float4 w4 = *(const float4*)(w + lane * 4);
    float4 out;
    out.x = v.x * inv * w4.x; out.y = v.y * inv * w4.y;
    out.z = v.z * inv * w4.z; out.w = v.w * inv * w4.w;
    *(float4*)(y + (size_t)row * DPn + lane * 4) = out;
}

/* res += rmsnorm(x)*w1; if (w2) out = rmsnorm(res)*w2.  cols=768, 256 thr. */
__global__ void rmsnorm_add_norm_k(const float* __restrict__ x, const float* __restrict__ w1,
                                   float* __restrict__ res, const float* __restrict__ w2,
                                   float* __restrict__ out)
{
    long long r = blockIdx.x;
    const int cols = Dn;
    const float* xr = x + r * cols;
    float xv[3], rv[3];
    float ss = 0.f;
#pragma unroll
    for (int u = 0; u < 3; u++) {
        xv[u] = xr[threadIdx.x + u * 256];
        ss += xv[u] * xv[u];
    }
    ss = blockReduce<0>(ss);
    float inv = rsqrtf(ss / cols + EPS_RMS);
    float ss2 = 0.f;
#pragma unroll
    for (int u = 0; u < 3; u++) {
        int c = threadIdx.x + u * 256;
        float v = res[r * cols + c] + xv[u] * inv * w1[c];
        res[r * cols + c] = v;
        rv[u] = v;
        ss2 += v * v;
    }
    if (w2) {
        ss2 = blockReduce<0>(ss2);
        float inv2 = rsqrtf(ss2 / cols + EPS_RMS);
#pragma unroll
        for (int u = 0; u < 3; u++) {
            int c = threadIdx.x + u * 256;
            out[r * cols + c] = rv[u] * inv2 * w2[c];
        }
    }
}

/* -------- qkv post: warp-per-segment LayerNorm + scale + rotary.
   warp 0-7 = q heads, warp 8 = k, warp 9 = v (v written as fp16). ---- */
__global__ __launch_bounds__(320) void qkv_post_k(
    const float* __restrict__ qkv,
    const float* __restrict__ qn, const float* __restrict__ kn,
    const float* __restrict__ vn,
    float* __restrict__ q, float* __restrict__ k, float* __restrict__ v)
{
    const int n = blockIdx.x;
    const int s = threadIdx.x >> 5;
    const int lane = threadIdx.x & 31;
    if (s < 9) {
        const int off = (s < 8) ? s * 128 : 1024;
        float4 x = *(const float4*)(qkv + (size_t)n * NQKVn + off + lane * 4);
        float sum = x.x + x.y + x.z + x.w;
        float sq = x.x * x.x + x.y * x.y + x.z * x.z + x.w * x.w;
#pragma unroll
        for (int o = 16; o > 0; o >>= 1) {
            sum += __shfl_xor_sync(0xffffffffu, sum, o);
            sq  += __shfl_xor_sync(0xffffffffu, sq, o);
        }
        float mu = sum * (1.f / 128.f);
        float var = sq * (1.f / 128.f) - mu * mu;
        float inv = rsqrtf(var + EPS_LN);
        const float* w = (s < 8) ? qn : kn;
        float4 w4 = *(const float4*)(w + lane * 4);
        float sc = (s < 8) ? 0.125f : 1.f;
        float y0 = (x.x - mu) * inv * w4.x * sc;
        float y1 = (x.y - mu) * inv * w4.y * sc;
        float y2 = (x.z - mu) * inv * w4.z * sc;
        float y3 = (x.w - mu) * inv * w4.w * sc;
        float p0 = __shfl_xor_sync(0xffffffffu, y0, 16);
        float sgn = (lane < 16) ? -1.f : 1.f;
        float invf = ((lane & 15) == 0) ? 0.1f : 0.f;
        float f = (float)n * invf;
        float c = cosf(f), si = sinf(f);
        float4 out = make_float4(y0 * c + sgn * p0 * si, y1, y2, y3);
        if (s < 8) *(float4*)(q + ((size_t)s * SEQn + n) * DQKn + lane * 4) = out;
        else       *(float4*)(k + (size_t)n * DQKn + lane * 4) = out;
    } else {
        const float* src = qkv + (size_t)n * NQKVn + 1152 + lane * 6;
        float2 a = *(const float2*)(src);
        float2 b = *(const float2*)(src + 2);
        float2 c2 = *(const float2*)(src + 4);
        float sum = a.x + a.y + b.x + b.y + c2.x + c2.y;
        float sq = a.x * a.x + a.y * a.y + b.x * b.x + b.y * b.y
                 + c2.x * c2.x + c2.y * c2.y;
#pragma unroll
        for (int o = 16; o > 0; o >>= 1) {
            sum += __shfl_xor_sync(0xffffffffu, sum, o);
            sq  += __shfl_xor_sync(0xffffffffu, sq, o);
        }
        float mu = sum * (1.f / 192.f);
        float var = sq * (1.f / 192.f) - mu * mu;
        float inv = rsqrtf(var + EPS_LN);
        const float* wv = vn + lane * 6;
        float2 wa = *(const float2*)(wv);
        float2 wb = *(const float2*)(wv + 2);
        float2 wc = *(const float2*)(wv + 4);
        unsigned* dst = (unsigned*)v + (size_t)n * (DVn / 2) + lane * 3;
        dst[0] = pack_f16((a.x - mu) * inv * wa.x,  (a.y - mu) * inv * wa.y);
        dst[1] = pack_f16((b.x - mu) * inv * wb.x,  (b.y - mu) * inv * wb.y);
        dst[2] = pack_f16((c2.x - mu) * inv * wc.x, (c2.y - mu) * inv * wc.y);
    }
}

/* ------------- pairwise bias: rms -> gelu -> [128->8]. ------------- */
__global__ __launch_bounds__(256) void pb_kernel(
    const float* __restrict__ pair, const float* __restrict__ rw,
    const float* __restrict__ proj, float* __restrict__ pb)
{
    const int lane = threadIdx.x & 31;
    const int warp = threadIdx.x >> 5;
    const int pair0 = (blockIdx.x * 8 + warp) * 8;
    float pr[4][8];
#pragma unroll
    for (int c = 0; c < 4; c++) {
        const float* p0 = proj + (size_t)(lane * 4 + c) * Hn;
        float4 a = *(const float4*)p0;
        float4 b = *(const float4*)(p0 + 4);
        pr[c][0] = a.x; pr[c][1] = a.y; pr[c][2] = a.z; pr[c][3] = a.w;
        pr[c][4] = b.x; pr[c][5] = b.y; pr[c][6] = b.z; pr[c][7] = b.w;
    }
    const float4 w4 = *(const float4*)(rw + lane * 4);

    float4 xnext = *(const float4*)(pair + (size_t)pair0 * DPn + lane * 4);
    for (int pp = 0; pp < 8; pp++) {
        const int idx = pair0 + pp;
        float4 x = xnext;
        if (pp < 7)
            xnext = *(const float4*)(pair + (size_t)(idx + 1) * DPn + lane * 4);
        float ss = x.x * x.x + x.y * x.y + x.z * x.z + x.w * x.w;
#pragma unroll
        for (int off = 16; off > 0; off >>= 1)
            ss += __shfl_xor_sync(0xffffffffu, ss, off);
        float inv = rsqrtf(ss * (1.f / DPn) + EPS_RMS);
        float gl[4];
        {
            float y0 = x.x * inv * w4.x, y1 = x.y * inv * w4.y;
            float y2 = x.z * inv * w4.z, y3 = x.w * inv * w4.w;
            gl[0] = 0.5f * y0 * (1.f + erff(y0 * 0.70710678118654752f));
            gl[1] = 0.5f * y1 * (1.f + erff(y1 * 0.70710678118654752f));
            gl[2] = 0.5f * y2 * (1.f + erff(y2 * 0.70710678118654752f));
            gl[3] = 0.5f * y3 * (1.f + erff(y3 * 0.70710678118654752f));
        }
        float p[8] = {0.f, 0.f, 0.f, 0.f, 0.f, 0.f, 0.f, 0.f};
#pragma unroll
        for (int c = 0; c < 4; c++)
#pragma unroll
            for (int h = 0; h < 8; h++)
                p[h] = fmaf(gl[c], pr[c][h], p[h]);
#pragma unroll
        for (int off = 16; off > 0; off >>= 1)
#pragma unroll
            for (int h = 0; h < 8; h++)
                p[h] += __shfl_xor_sync(0xffffffffu, p[h], off);
        if (lane < 8) {
            float out = p[0];
#pragma unroll
            for (int h = 1; h < 8; h++) if (lane == h) out = p[h];
            int i = idx >> 8, j = idx & 255;
            pb[((size_t)lane * NPn + i) * NPn + j] = out;
        }
    }
}

/* ---------------- host launcher ---------------- */
static inline void launch_gemm(bool tb, int mode, int M, int N, int K,
                               const float* A, int lda, long long sA,
                               const float* B, int ldb, long long sB,
                               float* C, int ldc, long long sC, int batch,
                               const float* bias, const float* pbias,
                               float* rsum, const float* rscale,
                               int ksplit = 1)
{
    dim3 g((N + 127) / 128, M / 128, batch * ksplit), b(256);
    if (tb) {
        if (mode == 3)      gemm_tc<true, 3><<<g, b>>>(M, N, K, A, lda, sA, B, ldb, sB, C, ldc, sC, bias, pbias, rsum, rscale, 1);
        else if (mode == 4) gemm_tc<true, 4><<<g, b>>>(M, N, K, A, lda, sA, B, ldb, sB, C, ldc, sC, bias, pbias, rsum, rscale, 1);
        else                gemm_tc<true, 0><<<g, b>>>(M, N, K, A, lda, sA, B, ldb, sB, C, ldc, sC, bias, pbias, rsum, rscale, 1);
    } else {
        if (mode == 1)      gemm_tc<false, 1><<<g, b>>>(M, N, K, A, lda, sA, B, ldb, sB, C, ldc, sC, bias, pbias, rsum, rscale, 1);
        else if (mode == 2) gemm_tc<false, 2><<<g, b>>>(M, N, K, A, lda, sA, B, ldb, sB, C, ldc, sC, bias, pbias, rsum, rscale, 1);
        else if (mode == 5) gemm_tc<false, 5><<<g, b>>>(M, N, K, A, lda, sA, B, ldb, sB, C, ldc, sC, bias, pbias, rsum, rscale, ksplit);
        else                gemm_tc<false, 0><<<g, b>>>(M, N, K, A, lda, sA, B, ldb, sB, C, ldc, sC, bias, pbias, rsum, rscale, 1);
    }
}

extern "C" void kernel_launch(void* const* d_in, const int* in_sizes, int n_in,
                              void* d_out, int out_size)
{
    (void)in_sizes; (void)n_in; (void)out_size;
    const float* in_single = (const float*)d_in[0];
    const float* in_pair   = (const float*)d_in[1];
    const float* W_attn_pre  = (const float*)d_in[2];
    const float* W_attn_post = (const float*)d_in[3];
    const float* W_qkv  = (const float*)d_in[4];
    const float* W_qn   = (const float*)d_in[5];
    const float* W_kn   = (const float*)d_in[6];
    const float* W_vn   = (const float*)d_in[7];
    const float* W_brms = (const float*)d_in[8];
    const float* W_bproj= (const float*)d_in[9];
    const float* W_out  = (const float*)d_in[10];
    const float* W_ffpre = (const float*)d_in[11];
    const float* W_ffpost= (const float*)d_in[12];
    const float* W_ff1  = (const float*)d_in[13];
    const float* B_ff1  = (const float*)d_in[14];
    const float* W_ff2  = (const float*)d_in[15];
    const float* B_ff2  = (const float*)d_in[16];
    const float* W_ppre = (const float*)d_in[17];
    const float* W_pqk  = (const float*)d_in[18];
    const float* W_pv   = (const float*)d_in[19];
    const float* B_pv   = (const float*)d_in[20];
    const float* W_pffpre = (const float*)d_in[21];
    const float* W_pff1 = (const float*)d_in[22];
    const float* B_pff1 = (const float*)d_in[23];
    const float* W_pff2 = (const float*)d_in[24];
    const float* B_pff2 = (const float*)d_in[25];

    float *xn, *qkv, *q, *k, *v, *sim, *pb, *ao, *t1, *rsum;
    float *pxn, *pqk, *pv, *psim, *prsum, *pt;
    cudaGetSymbolAddress((void**)&xn, g_xn);
    cudaGetSymbolAddress((void**)&qkv, g_qkv);
    cudaGetSymbolAddress((void**)&q, g_q);
    cudaGetSymbolAddress((void**)&k, g_k);
    cudaGetSymbolAddress((void**)&v, g_v);
    cudaGetSymbolAddress((void**)&sim, g_sim);
    cudaGetSymbolAddress((void**)&pb, g_pb);
    cudaGetSymbolAddress((void**)&ao, g_ao);
    cudaGetSymbolAddress((void**)&t1, g_t1);
    cudaGetSymbolAddress((void**)&rsum, g_rsum);
    cudaGetSymbolAddress((void**)&pxn, g_pxn);
    cudaGetSymbolAddress((void**)&pqk, g_pqk);
    cudaGetSymbolAddress((void**)&pv, g_pv);
    cudaGetSymbolAddress((void**)&psim, g_psim);
    cudaGetSymbolAddress((void**)&prsum, g_prsum);
    cudaGetSymbolAddress((void**)&pt, g_pt);

    /* residual streams live directly in d_out: [single | pairwise] */
    float* single = (float*)d_out;
    float* pair   = (float*)d_out + (size_t)SEQn * Dn;
    cudaMemcpyAsync(single, in_single, (size_t)SEQn * Dn * 4, cudaMemcpyDeviceToDevice);
    cudaMemcpyAsync(pair, in_pair, (size_t)NPn * NPn * DPn * 4, cudaMemcpyDeviceToDevice);

    /* xn = rmsnorm(single, attn_pre[0]) for the first layer */
    rmsnorm_k<<<SEQn, 256>>>(single, W_attn_pre, xn, Dn);

    for (int i = 0; i < 4; i++) {
        /* ---- single-track attention ---- */
        zero_k<<<(SEQn * NQKVn + 255) / 256, 256>>>(qkv, SEQn * NQKVn);
        launch_gemm(false, 5, SEQn, NQKVn, Dn / 2, xn, Dn, 0,
                    W_qkv + (long long)i * Dn * NQKVn, NQKVn, 0, qkv, NQKVn, 0, 1,
                    nullptr, nullptr, nullptr, nullptr, 2);
        qkv_post_k<<<SEQn, 320>>>(qkv, W_qn + i * DQKn, W_kn + i * DQKn,
                                  W_vn + i * DVn, q, k, v);
        pb_kernel<<<NPn * NPn / 64, 256>>>(pair, W_brms + i * DPn, W_bproj + i * DPn * Hn, pb);
        zero_k<<<(Hn * SEQn + 255) / 256, 256>>>(rsum, Hn * SEQn);
        /* P = exp(softclamp(qk^T + pb)) -> f16 sim + rowsums */
        launch_gemm(true, 3, SEQn, SEQn, DQKn, q, DQKn, (long long)SEQn * DQKn,
                    k, DQKn, 0, sim, SEQn, (long long)SEQn * SEQn / 2, Hn,
                    nullptr, pb, rsum, nullptr);
        /* O = (P/rowsum) V — f16 mma, split-K x2 */
        zero_k<<<(SEQn * Hn * DVn + 255) / 256, 256>>>(ao, SEQn * Hn * DVn);
        gemm_av_f16<<<dim3(1, SEQn / 128, Hn * 2), 256>>>(
            (const unsigned*)sim, (const unsigned*)v, ao, rsum);
        /* t1 = ao @ W_out, split-K x3 */
        zero_k<<<(SEQn * Dn + 255) / 256, 256>>>(t1, SEQn * Dn);
        launch_gemm(false, 5, SEQn, Dn, (Hn * DVn) / 3, ao, Hn * DVn, 0,
                    W_out + (long long)i * Hn * DVn * Dn, Dn, 0, t1, Dn, 0, 1,
                    nullptr, nullptr, nullptr, nullptr, 3);
        rmsnorm_add_norm_k<<<SEQn, 256>>>(t1, W_attn_post + i * Dn, single,
                                          W_ffpre + i * Dn, xn);

        /* ---- single-track FF ---- */
        launch_gemm(false, 1, SEQn, FFIn, Dn, xn, Dn, 0,
                    W_ff1 + (long long)i * Dn * FFIn, FFIn, 0, ao, FFIn, 0, 1,
                    B_ff1 + i * FFIn, nullptr, nullptr, nullptr);
        zero_k<<<(SEQn * Dn + 255) / 256, 256>>>(t1, SEQn * Dn);
        launch_gemm(false, 5, SEQn, Dn, FFIn / 3, ao, FFIn, 0,
                    W_ff2 + (long long)i * FFIn * Dn, Dn, 0, t1, Dn, 0, 1,
                    B_ff2 + i * Dn, nullptr, nullptr, nullptr, 3);
        rmsnorm_add_norm_k<<<SEQn, 256>>>(t1, W_ffpost + i * Dn, single,
                                          (i < 3) ? W_attn_pre + (i + 1) * Dn : nullptr, xn);

        /* ---- pairwise track (layers 0, 2) ---- */
        if ((i & 1) == 0) {
            int j = i / 2;
            rmsnorm128_k<<<NPn * NPn / 8, 256>>>(pair, W_ppre + j * DPn, pxn);
            launch_gemm(false, 0, NPn * NPn, 2 * DPn, DPn, pxn, DPn, 0,
                        W_pqk + (long long)j * DPn * 2 * DPn, 2 * DPn, 0,
                        pqk, 2 * DPn, 0, 1, nullptr, nullptr, nullptr, nullptr);
            launch_gemm(false, 0, NPn * NPn, DPn, DPn, pxn, DPn, 0,
                        W_pv + (long long)j * DPn * DPn, DPn, 0,
                        pv, DPn, 0, 1, B_pv + j * DPn, nullptr, nullptr, nullptr);
            zero_k<<<(NPn * NPn + 255) / 256, 256>>>(prsum, NPn * NPn);
            launch_gemm(true, 4, NPn, NPn, DPn, pqk, 2 * DPn, (long long)NPn * 2 * DPn,
                        pqk + DPn, 2 * DPn, (long long)NPn * 2 * DPn,
                        psim, NPn, (long long)NPn * NPn, NPn,
                        nullptr, nullptr, prsum, nullptr);
            launch_gemm(false, 2, NPn, DPn, NPn, psim, NPn, (long long)NPn * NPn,
                        pv, DPn, (long long)NPn * DPn,
                        pair, DPn, (long long)NPn * DPn, NPn,
                        nullptr, nullptr, nullptr, prsum);
            rmsnorm128_k<<<NPn * NPn / 8, 256>>>(pair, W_pffpre + j * DPn, pxn);
            launch_gemm(false, 1, NPn * NPn, DPIn, DPn, pxn, DPn, 0,
                        W_pff1 + (long long)j * DPn * DPIn, DPIn, 0,
                        pt, DPIn, 0, 1, B_pff1 + j * DPIn, nullptr, nullptr, nullptr);
            launch_gemm(false, 2, NPn * NPn, DPn, DPIn, pt, DPIn, 0,
                        W_pff2 + (long long)j * DPIn * DPn, DPn, 0,
                        pair, DPn, 0, 1, B_pff2 + j * DPn, nullptr, nullptr, nullptr);
        }
    }
}

// round 16
// speedup vs baseline: 2.1662x; 1.0099x over previous
#include <cuda_runtime.h>
#include <math.h>

#define SEQn 2048
#define Dn   768
#define Hn   8
#define DQKn 128
#define DVn  192
#define NQKVn 1344   /* 8*128 + 128 + 192 */
#define NPn  256
#define DPn  128
#define FFIn 1536
#define DPIn 256
#define EPS_RMS 1.1920929e-07f
#define EPS_LN  1e-5f

/* ---------------- scratch (device globals; no allocation) ---------------- */
__device__ float g_xn[SEQn * Dn];
__device__ float g_qkv[SEQn * NQKVn];
__device__ float g_q[Hn * SEQn * DQKn];
__device__ float g_k[SEQn * DQKn];
__device__ float g_v[SEQn * DVn];                      /* holds fp16 (reinterpreted) */
__device__ float g_sim[(size_t)Hn * SEQn * SEQn / 2];  /* fp16 P, 67 MB */
__device__ float g_pb[Hn * NPn * NPn];
__device__ float g_ao[SEQn * Hn * DVn];
__device__ float g_t1[SEQn * FFIn];
__device__ float g_rsum[Hn * SEQn];
__device__ float g_pxn[NPn * NPn * DPn];
__device__ float g_pqk[NPn * NPn * 2 * DPn];
__device__ float g_pv[NPn * NPn * DPn];
__device__ float g_psim[(size_t)NPn * NPn * NPn];      /* 67 MB */
__device__ float g_prsum[NPn * NPn];
__device__ float g_pt[NPn * NPn * DPIn];

/* ---------------- helpers ---------------- */
__device__ __forceinline__ unsigned pack_f16(float lo, float hi) {
    unsigned r;
    asm("cvt.rn.f16x2.f32 %0, %1, %2;" : "=r"(r) : "f"(hi), "f"(lo));
    return r;
}

__device__ __forceinline__ void mma_f16(float* c, const unsigned* a, const unsigned* b) {
    asm volatile(
        "mma.sync.aligned.m16n8k16.row.col.f32.f16.f16.f32 "
        "{%0,%1,%2,%3}, {%4,%5,%6,%7}, {%8,%9}, {%0,%1,%2,%3};\n"
        : "+f"(c[0]), "+f"(c[1]), "+f"(c[2]), "+f"(c[3])
        : "r"(a[0]), "r"(a[1]), "r"(a[2]), "r"(a[3]), "r"(b[0]), "r"(b[1]));
}

/* exp(5*tanh(x/5)) via single-MUFU tanh.approx (rel err ~2^-11, below fp16
   storage quantization of the result) */
__device__ __forceinline__ float softclamp_exp(float x) {
    float th;
    asm("tanh.approx.f32 %0, %1;" : "=f"(th) : "f"(x * 0.2f));
    return __expf(5.f * th);
}

template <int OP>
__device__ __forceinline__ float blockReduce(float v) {
    __shared__ float s[33];
    int lane = threadIdx.x & 31, wid = threadIdx.x >> 5;
#pragma unroll
    for (int o = 16; o > 0; o >>= 1) {
        float ov = __shfl_down_sync(0xffffffffu, v, o);
        v = (OP == 0) ? (v + ov) : fmaxf(v, ov);
    }
    if (lane == 0) s[wid] = v;
    __syncthreads();
    if (threadIdx.x == 0) {
        int nw = (blockDim.x + 31) >> 5;
        float r = s[0];
        for (int i = 1; i < nw; i++) r = (OP == 0) ? (r + s[i]) : fmaxf(r, s[i]);
        s[32] = r;
    }
    __syncthreads();
    float r = s[32];
    __syncthreads();
    return r;
}

__global__ void zero_k(float* p, int n)
{
    int i = blockIdx.x * blockDim.x + threadIdx.x;
    if (i < n) p[i] = 0.f;
}

/* fused zero of three buffers in one launch */
__global__ void zero3_k(float* a, int na, float* b, int nb, float* c, int nc)
{
    int i = blockIdx.x * blockDim.x + threadIdx.x;
    if (i < na) { a[i] = 0.f; return; }
    i -= na;
    if (i < nb) { b[i] = 0.f; return; }
    i -= nb;
    if (i < nc) c[i] = 0.f;
}

/* ---------------- FP16 tensor-core GEMM, 128x128 CTA, BK=16, dbl-buf.
   8 warps in 2x4 grid; warp tile 64x32. fp32 inputs converted to f16 at
   staging, packed as k-pairs per smem word.
   MODE: 0 plain(+bias), 1 relu(+bias), 2 accumulate into C(+bias),
         3 sim softmax: exp(softclamp(x+pb)) -> f16x2 C + atomic row sums,
         4 pair softmax: exp(x) + atomic row sums,
         5 split-K: atomicAdd into C (+bias only from kz==0 split).
   MODE3: C is fp16 storage; sC given in FLOAT units (= f16 elems/2).
   rscale (optional): multiply output rows by 1/rscale[batch*M+m].
   Requires M%128==0, K%16==0, N%4==0 (N tile-edge guarded).                 */
template <bool TB, int MODE>
__global__ __launch_bounds__(256) void gemm_tc(
    int M, int N, int K,
    const float* __restrict__ A, int lda, long long sA,
    const float* __restrict__ B, int ldb, long long sB,
    float* __restrict__ C, int ldc, long long sC,
    const float* __restrict__ bias,
    const float* __restrict__ pbias,
    float* __restrict__ rsum,
    const float* __restrict__ rscale,
    int ksplit)
{
    __shared__ unsigned As[2][8][136];   /* [k-pair 0..7][128 rows + pad] */
    __shared__ unsigned Bs[2][8][136];
    const int zz = blockIdx.z;
    const int batch = zz / ksplit;
    const int kz = zz - batch * ksplit;
    A += (long long)batch * sA + (long long)kz * K;
    B += (long long)batch * sB;
    if (!TB) B += (long long)kz * K * ldb;
    C += (long long)batch * sC;
    const int bm = blockIdx.y * 128, bn = blockIdx.x * 128;
    const int tid = threadIdx.x;
    const int lane = tid & 31, warp = tid >> 5;
    const int g = lane >> 2, tg = lane & 3;
    const int warpM = warp & 1, warpN = warp >> 1;

    const int arow = tid >> 1, ap4 = (tid & 1) * 4;
    const float* Aptr = A + (long long)(bm + arow) * lda + (tid & 1) * 8;
    const bool bvt = TB ? (bn + arow < N) : true;
    const int k2r = tid >> 5, bn4 = (lane) * 4;
    const bool bvn = TB ? true : (bn + bn4 < N);
    const float4 f0 = make_float4(0.f, 0.f, 0.f, 0.f);

    float4 pa0, pa1, pb0, pb1;
    {
        pa0 = *(const float4*)(Aptr);
        pa1 = *(const float4*)(Aptr + 4);
        if (TB) {
            pb0 = bvt ? *(const float4*)(B + (long long)(bn + arow) * ldb + (tid & 1) * 8) : f0;
            pb1 = bvt ? *(const float4*)(B + (long long)(bn + arow) * ldb + (tid & 1) * 8 + 4) : f0;
        } else {
            pb0 = bvn ? *(const float4*)(B + (long long)(2 * k2r) * ldb + bn + bn4) : f0;
            pb1 = bvn ? *(const float4*)(B + (long long)(2 * k2r + 1) * ldb + bn + bn4) : f0;
        }
    }
    {
        As[0][ap4 + 0][arow] = pack_f16(pa0.x, pa0.y);
        As[0][ap4 + 1][arow] = pack_f16(pa0.z, pa0.w);
        As[0][ap4 + 2][arow] = pack_f16(pa1.x, pa1.y);
        As[0][ap4 + 3][arow] = pack_f16(pa1.z, pa1.w);
        if (TB) {
            Bs[0][ap4 + 0][arow] = pack_f16(pb0.x, pb0.y);
            Bs[0][ap4 + 1][arow] = pack_f16(pb0.z, pb0.w);
            Bs[0][ap4 + 2][arow] = pack_f16(pb1.x, pb1.y);
            Bs[0][ap4 + 3][arow] = pack_f16(pb1.z, pb1.w);
        } else {
            Bs[0][k2r][bn4 + 0] = pack_f16(pb0.x, pb1.x);
            Bs[0][k2r][bn4 + 1] = pack_f16(pb0.y, pb1.y);
            Bs[0][k2r][bn4 + 2] = pack_f16(pb0.z, pb1.z);
            Bs[0][k2r][bn4 + 3] = pack_f16(pb0.w, pb1.w);
        }
    }
    __syncthreads();

    float acc[4][4][4];
#pragma unroll
    for (int mt = 0; mt < 4; mt++)
#pragma unroll
        for (int nt = 0; nt < 4; nt++)
#pragma unroll
            for (int u = 0; u < 4; u++) acc[mt][nt][u] = 0.f;

    const int nst = K >> 4;
    for (int st = 0; st < nst; st++) {
        if (st + 1 < nst) {
            int kb = (st + 1) << 4;
            pa0 = *(const float4*)(Aptr + kb);
            pa1 = *(const float4*)(Aptr + kb + 4);
            if (TB) {
                pb0 = bvt ? *(const float4*)(B + (long long)(bn + arow) * ldb + kb + (tid & 1) * 8) : f0;
                pb1 = bvt ? *(const float4*)(B + (long long)(bn + arow) * ldb + kb + (tid & 1) * 8 + 4) : f0;
            } else {
                pb0 = bvn ? *(const float4*)(B + (long long)(kb + 2 * k2r) * ldb + bn + bn4) : f0;
                pb1 = bvn ? *(const float4*)(B + (long long)(kb + 2 * k2r + 1) * ldb + bn + bn4) : f0;
            }
        }
        const int buf = st & 1;
        {
            unsigned af[4][4], bf[4][2];
#pragma unroll
            for (int mt = 0; mt < 4; mt++) {
                int m = warpM * 64 + mt * 16 + g;
                af[mt][0] = As[buf][tg][m];
                af[mt][1] = As[buf][tg][m + 8];
                af[mt][2] = As[buf][tg + 4][m];
                af[mt][3] = As[buf][tg + 4][m + 8];
            }
#pragma unroll
            for (int nt = 0; nt < 4; nt++) {
                int n = warpN * 32 + nt * 8 + g;
                bf[nt][0] = Bs[buf][tg][n];
                bf[nt][1] = Bs[buf][tg + 4][n];
            }
#pragma unroll
            for (int mt = 0; mt < 4; mt++)
#pragma unroll
                for (int nt = 0; nt < 4; nt++)
                    mma_f16(acc[mt][nt], af[mt], bf[nt]);
        }
        if (st + 1 < nst) {
            const int nb = (st + 1) & 1;
            As[nb][ap4 + 0][arow] = pack_f16(pa0.x, pa0.y);
            As[nb][ap4 + 1][arow] = pack_f16(pa0.z, pa0.w);
            As[nb][ap4 + 2][arow] = pack_f16(pa1.x, pa1.y);
            As[nb][ap4 + 3][arow] = pack_f16(pa1.z, pa1.w);
            if (TB) {
                Bs[nb][ap4 + 0][arow] = pack_f16(pb0.x, pb0.y);
                Bs[nb][ap4 + 1][arow] = pack_f16(pb0.z, pb0.w);
                Bs[nb][ap4 + 2][arow] = pack_f16(pb1.x, pb1.y);
                Bs[nb][ap4 + 3][arow] = pack_f16(pb1.z, pb1.w);
            } else {
                Bs[nb][k2r][bn4 + 0] = pack_f16(pb0.x, pb1.x);
                Bs[nb][k2r][bn4 + 1] = pack_f16(pb0.y, pb1.y);
                Bs[nb][k2r][bn4 + 2] = pack_f16(pb0.z, pb1.z);
                Bs[nb][k2r][bn4 + 3] = pack_f16(pb0.w, pb1.w);
            }
        }
        __syncthreads();
    }

    /* ---- epilogue (fragment ownership: rows g/g+8, cols tg*2, tg*2+1) ---- */
#pragma unroll
    for (int mt = 0; mt < 4; mt++) {
        const int m0 = bm + warpM * 64 + mt * 16 + g;
        const int m1 = m0 + 8;
        float inv0 = 1.f, inv1 = 1.f;
        if (rscale) {
            inv0 = 1.f / rscale[(size_t)batch * M + m0];
            inv1 = 1.f / rscale[(size_t)batch * M + m1];
        }
        const float* pbr0 = nullptr;
        const float* pbr1 = nullptr;
        if (MODE == 3) {
            pbr0 = pbias + (size_t)batch * (NPn * NPn) + (size_t)(m0 >> 3) * NPn;
            pbr1 = pbias + (size_t)batch * (NPn * NPn) + (size_t)(m1 >> 3) * NPn;
        }
        float r0 = 0.f, r1 = 0.f;
#pragma unroll
        for (int nt = 0; nt < 4; nt++) {
            const int n = bn + warpN * 32 + nt * 8 + tg * 2;
            if (n < N) {
                float c0 = acc[mt][nt][0], c1 = acc[mt][nt][1];
                float c2 = acc[mt][nt][2], c3 = acc[mt][nt][3];
                if (bias && (MODE != 5 || kz == 0)) {
                    float2 bb = *(const float2*)&bias[n];
                    c0 += bb.x; c1 += bb.y; c2 += bb.x; c3 += bb.y;
                }
                if (MODE == 1) {
                    c0 = fmaxf(c0, 0.f); c1 = fmaxf(c1, 0.f);
                    c2 = fmaxf(c2, 0.f); c3 = fmaxf(c3, 0.f);
                }
                if (MODE == 3) {
                    float pb0v = pbr0[n >> 3], pb1v = pbr1[n >> 3];
                    c0 = softclamp_exp(c0 + pb0v);
                    c1 = softclamp_exp(c1 + pb0v);
                    c2 = softclamp_exp(c2 + pb1v);
                    c3 = softclamp_exp(c3 + pb1v);
                    r0 += c0 + c1; r1 += c2 + c3;
                    ((unsigned*)C)[(long long)m0 * (ldc >> 1) + (n >> 1)] = pack_f16(c0, c1);
                    ((unsigned*)C)[(long long)m1 * (ldc >> 1) + (n >> 1)] = pack_f16(c2, c3);
                } else {
                    if (MODE == 4) {
                        c0 = __expf(c0); c1 = __expf(c1);
                        c2 = __expf(c2); c3 = __expf(c3);
                        r0 += c0 + c1; r1 += c2 + c3;
                    }
                    if (rscale) { c0 *= inv0; c1 *= inv0; c2 *= inv1; c3 *= inv1; }
                    if (MODE == 5) {
                        float* p0 = &C[(long long)m0 * ldc + n];
                        float* p1 = &C[(long long)m1 * ldc + n];
                        atomicAdd(p0, c0); atomicAdd(p0 + 1, c1);
                        atomicAdd(p1, c2); atomicAdd(p1 + 1, c3);
                    } else {
                        float2 w0, w1;
                        if (MODE == 2) {
                            float2 o0 = *(const float2*)&C[(long long)m0 * ldc + n];
                            float2 o1 = *(const float2*)&C[(long long)m1 * ldc + n];
                            w0.x = c0 + o0.x; w0.y = c1 + o0.y;
                            w1.x = c2 + o1.x; w1.y = c3 + o1.y;
                        } else {
                            w0.x = c0; w0.y = c1; w1.x = c2; w1.y = c3;
                        }
                        *(float2*)&C[(long long)m0 * ldc + n] = w0;
                        *(float2*)&C[(long long)m1 * ldc + n] = w1;
                    }
                }
            }
        }
        if (MODE == 3 || MODE == 4) {
            r0 += __shfl_xor_sync(0xffffffffu, r0, 1);
            r0 += __shfl_xor_sync(0xffffffffu, r0, 2);
            r1 += __shfl_xor_sync(0xffffffffu, r1, 1);
            r1 += __shfl_xor_sync(0xffffffffu, r1, 2);
            if (tg == 0) {
                atomicAdd(&rsum[(size_t)batch * M + m0], r0);
                atomicAdd(&rsum[(size_t)batch * M + m1], r1);
            }
        }
    }
}

/* ---------------- fp16 AV GEMM: O = (P/rowsum) V, split-K x2 -------------- */
__global__ __launch_bounds__(256) void gemm_av_f16(
    const unsigned* __restrict__ Aw,   /* f16 pairs, row = 1024 words */
    const unsigned* __restrict__ Bw,   /* v f16, row = 96 words */
    float* __restrict__ C,
    const float* __restrict__ rsum)
{
    __shared__ unsigned As[2][8][136];
    __shared__ unsigned Bs[2][8][200];
    const int head = blockIdx.z >> 1, kz = blockIdx.z & 1;
    const int bm = blockIdx.y * 128;
    const int tid = threadIdx.x;
    const int lane = tid & 31, warp = tid >> 5;
    const int g = lane >> 2, tg = lane & 3;
    const int warpM = warp & 1, warpN = warp >> 1;

    const unsigned* Ap = Aw + (size_t)head * (SEQn * (SEQn / 2))
                       + (size_t)(bm + (tid >> 1)) * (SEQn / 2)
                       + (size_t)kz * 512 + (tid & 1) * 4;
    const int k2r = tid >> 5;
    const unsigned* Bp = Bw + ((size_t)kz * 1024) * 96 + lane * 3;
    const int nb = lane * 6;

    uint4 pa;
    unsigned rb0[3], rb1[3];
    pa = *(const uint4*)(Ap);
    {
        const unsigned* p0 = Bp + (size_t)(2 * k2r) * 96;
        const unsigned* p1 = p0 + 96;
        rb0[0] = p0[0]; rb0[1] = p0[1]; rb0[2] = p0[2];
        rb1[0] = p1[0]; rb1[1] = p1[1]; rb1[2] = p1[2];
    }
    {
        const unsigned* u = (const unsigned*)&pa;
#pragma unroll
        for (int i = 0; i < 4; i++) As[0][(tid & 1) * 4 + i][tid >> 1] = u[i];
#pragma unroll
        for (int j = 0; j < 3; j++) {
            Bs[0][k2r][nb + 2 * j]     = __byte_perm(rb0[j], rb1[j], 0x5410);
            Bs[0][k2r][nb + 2 * j + 1] = __byte_perm(rb0[j], rb1[j], 0x7632);
        }
    }
    __syncthreads();

    float acc[4][6][4];
#pragma unroll
    for (int mt = 0; mt < 4; mt++)
#pragma unroll
        for (int nt = 0; nt < 6; nt++)
#pragma unroll
            for (int u = 0; u < 4; u++) acc[mt][nt][u] = 0.f;

    const int nst = 64;
    for (int st = 0; st < nst; st++) {
        if (st + 1 < nst) {
            pa = *(const uint4*)(Ap + (st + 1) * 8);
            const unsigned* p0 = Bp + (size_t)((st + 1) * 16 + 2 * k2r) * 96;
            const unsigned* p1 = p0 + 96;
            rb0[0] = p0[0]; rb0[1] = p0[1]; rb0[2] = p0[2];
            rb1[0] = p1[0]; rb1[1] = p1[1]; rb1[2] = p1[2];
        }
        const int buf = st & 1;
        {
            unsigned af[4][4], bf[6][2];
#pragma unroll
            for (int mt = 0; mt < 4; mt++) {
                int m = warpM * 64 + mt * 16 + g;
                af[mt][0] = As[buf][tg][m];
                af[mt][1] = As[buf][tg][m + 8];
                af[mt][2] = As[buf][tg + 4][m];
                af[mt][3] = As[buf][tg + 4][m + 8];
            }
#pragma unroll
            for (int nt = 0; nt < 6; nt++) {
                int n = warpN * 48 + nt * 8 + g;
                bf[nt][0] = Bs[buf][tg][n];
                bf[nt][1] = Bs[buf][tg + 4][n];
            }
#pragma unroll
            for (int mt = 0; mt < 4; mt++)
#pragma unroll
                for (int nt = 0; nt < 6; nt++)
                    mma_f16(acc[mt][nt], af[mt], bf[nt]);
        }
        if (st + 1 < nst) {
            const int nbuf = (st + 1) & 1;
            const unsigned* u = (const unsigned*)&pa;
#pragma unroll
            for (int i = 0; i < 4; i++) As[nbuf][(tid & 1) * 4 + i][tid >> 1] = u[i];
#pragma unroll
            for (int j = 0; j < 3; j++) {
                Bs[nbuf][k2r][nb + 2 * j]     = __byte_perm(rb0[j], rb1[j], 0x5410);
                Bs[nbuf][k2r][nb + 2 * j + 1] = __byte_perm(rb0[j], rb1[j], 0x7632);
            }
        }
        __syncthreads();
    }

#pragma unroll
    for (int mt = 0; mt < 4; mt++) {
        const int m0 = bm + warpM * 64 + mt * 16 + g;
        const int m1 = m0 + 8;
        float inv0 = 1.f / rsum[(size_t)head * SEQn + m0];
        float inv1 = 1.f / rsum[(size_t)head * SEQn + m1];
#pragma unroll
        for (int nt = 0; nt < 6; nt++) {
            const int n = head * DVn + warpN * 48 + nt * 8 + tg * 2;
            float* p0 = &C[(long long)m0 * (Hn * DVn) + n];
            float* p1 = &C[(long long)m1 * (Hn * DVn) + n];
            atomicAdd(p0,     acc[mt][nt][0] * inv0);
            atomicAdd(p0 + 1, acc[mt][nt][1] * inv0);
            atomicAdd(p1,     acc[mt][nt][2] * inv1);
            atomicAdd(p1 + 1, acc[mt][nt][3] * inv1);
        }
    }
}

/* ---------------- norms ---------------- */
__global__ void rmsnorm_k(const float* __restrict__ x, const float* __restrict__ w,
                          float* __restrict__ y, int cols)
{
    long long r = blockIdx.x;
    const float* xr = x + r * cols;
    float ss = 0.f;
    for (int c = threadIdx.x; c < cols; c += blockDim.x) { float v = xr[c]; ss += v * v; }
    ss = blockReduce<0>(ss);
    float inv = rsqrtf(ss / cols + EPS_RMS);
    for (int c = threadIdx.x; c < cols; c += blockDim.x)
        y[r * cols + c] = xr[c] * inv * w[c];
}

/* warp-per-row RMSNorm for 128-wide rows (pairwise track). 8 rows/block. */
__global__ __launch_bounds__(256) void rmsnorm128_k(
    const float* __restrict__ x, const float* __restrict__ w, float* __restrict__ y)
{
    const int row = blockIdx.x * 8 + (threadIdx.x >> 5);
    const int lane = threadIdx.x & 31;
    float4 v = *(const float4*)(x + (size_t)row * DPn + lane * 4);
    float ss = v.x * v.x + v.y * v.y + v.z * v.z + v.w * v.w;
#pragma unroll
    for (int o = 16; o > 0; o >>= 1)
        ss += __shfl_xor_sync(0xffffffffu, ss, o);
    float inv = rsqrtf(ss * (1.f / DPn) + EPS_RMS);
    float4 w4 = *(const float4*)(w + lane * 4);
    float4 out;
    out.x = v.x * inv * w4.x; out.y = v.y * inv * w4.y;
    out.z = v.z * inv * w4.z; out.w = v.w * inv * w4.w;
    *(float4*)(y + (size_t)row * DPn + lane * 4) = out;
}

/* res += rmsnorm(x)*w1; if (w2) out = rmsnorm(res)*w2.  cols=768, 256 thr. */
__global__ void rmsnorm_add_norm_k(const float* __restrict__ x, const float* __restrict__ w1,
                                   float* __restrict__ res, const float* __restrict__ w2,
                                   float* __restrict__ out)
{
    long long r = blockIdx.x;
    const int cols = Dn;
    const float* xr = x + r * cols;
    float xv[3], rv[3];
    float ss = 0.f;
#pragma unroll
    for (int u = 0; u < 3; u++) {
        xv[u] = xr[threadIdx.x + u * 256];
        ss += xv[u] * xv[u];
    }
    ss = blockReduce<0>(ss);
    float inv = rsqrtf(ss / cols + EPS_RMS);
    float ss2 = 0.f;
#pragma unroll
    for (int u = 0; u < 3; u++) {
        int c = threadIdx.x + u * 256;
        float v = res[r * cols + c] + xv[u] * inv * w1[c];
        res[r * cols + c] = v;
        rv[u] = v;
        ss2 += v * v;
    }
    if (w2) {
        ss2 = blockReduce<0>(ss2);
        float inv2 = rsqrtf(ss2 / cols + EPS_RMS);
#pragma unroll
        for (int u = 0; u < 3; u++) {
            int c = threadIdx.x + u * 256;
            out[r * cols + c] = rv[u] * inv2 * w2[c];
        }
    }
}

/* -------- qkv post: warp-per-segment LayerNorm + scale + rotary.
   warp 0-7 = q heads, warp 8 = k, warp 9 = v (v written as fp16). ---- */
__global__ __launch_bounds__(320) void qkv_post_k(
    const float* __restrict__ qkv,
    const float* __restrict__ qn, const float* __restrict__ kn,
    const float* __restrict__ vn,
    float* __restrict__ q, float* __restrict__ k, float* __restrict__ v)
{
    const int n = blockIdx.x;
    const int s = threadIdx.x >> 5;
    const int lane = threadIdx.x & 31;
    if (s < 9) {
        const int off = (s < 8) ? s * 128 : 1024;
        float4 x = *(const float4*)(qkv + (size_t)n * NQKVn + off + lane * 4);
        float sum = x.x + x.y + x.z + x.w;
        float sq = x.x * x.x + x.y * x.y + x.z * x.z + x.w * x.w;
#pragma unroll
        for (int o = 16; o > 0; o >>= 1) {
            sum += __shfl_xor_sync(0xffffffffu, sum, o);
            sq  += __shfl_xor_sync(0xffffffffu, sq, o);
        }
        float mu = sum * (1.f / 128.f);
        float var = sq * (1.f / 128.f) - mu * mu;
        float inv = rsqrtf(var + EPS_LN);
        const float* w = (s < 8) ? qn : kn;
        float4 w4 = *(const float4*)(w + lane * 4);
        float sc = (s < 8) ? 0.125f : 1.f;
        float y0 = (x.x - mu) * inv * w4.x * sc;
        float y1 = (x.y - mu) * inv * w4.y * sc;
        float y2 = (x.z - mu) * inv * w4.z * sc;
        float y3 = (x.w - mu) * inv * w4.w * sc;
        float p0 = __shfl_xor_sync(0xffffffffu, y0, 16);
        float sgn = (lane < 16) ? -1.f : 1.f;
        float invf = ((lane & 15) == 0) ? 0.1f : 0.f;
        float f = (float)n * invf;
        float c = cosf(f), si = sinf(f);
        float4 out = make_float4(y0 * c + sgn * p0 * si, y1, y2, y3);
        if (s < 8) *(float4*)(q + ((size_t)s * SEQn + n) * DQKn + lane * 4) = out;
        else       *(float4*)(k + (size_t)n * DQKn + lane * 4) = out;
    } else {
        const float* src = qkv + (size_t)n * NQKVn + 1152 + lane * 6;
        float2 a = *(const float2*)(src);
        float2 b = *(const float2*)(src + 2);
        float2 c2 = *(const float2*)(src + 4);
        float sum = a.x + a.y + b.x + b.y + c2.x + c2.y;
        float sq = a.x * a.x + a.y * a.y + b.x * b.x + b.y * b.y
                 + c2.x * c2.x + c2.y * c2.y;
#pragma unroll
        for (int o = 16; o > 0; o >>= 1) {
            sum += __shfl_xor_sync(0xffffffffu, sum, o);
            sq  += __shfl_xor_sync(0xffffffffu, sq, o);
        }
        float mu = sum * (1.f / 192.f);
        float var = sq * (1.f / 192.f) - mu * mu;
        float inv = rsqrtf(var + EPS_LN);
        const float* wv = vn + lane * 6;
        float2 wa = *(const float2*)(wv);
        float2 wb = *(const float2*)(wv + 2);
        float2 wc = *(const float2*)(wv + 4);
        unsigned* dst = (unsigned*)v + (size_t)n * (DVn / 2) + lane * 3;
        dst[0] = pack_f16((a.x - mu) * inv * wa.x,  (a.y - mu) * inv * wa.y);
        dst[1] = pack_f16((b.x - mu) * inv * wb.x,  (b.y - mu) * inv * wb.y);
        dst[2] = pack_f16((c2.x - mu) * inv * wc.x, (c2.y - mu) * inv * wc.y);
    }
}

/* ------------- pairwise bias: rms -> gelu -> [128->8]. ------------- */
__global__ __launch_bounds__(256) void pb_kernel(
    const float* __restrict__ pair, const float* __restrict__ rw,
    const float* __restrict__ proj, float* __restrict__ pb)
{
    const int lane = threadIdx.x & 31;
    const int warp = threadIdx.x >> 5;
    const int pair0 = (blockIdx.x * 8 + warp) * 8;
    float pr[4][8];
#pragma unroll
    for (int c = 0; c < 4; c++) {
        const float* p0 = proj + (size_t)(lane * 4 + c) * Hn;
        float4 a = *(const float4*)p0;
        float4 b = *(const float4*)(p0 + 4);
        pr[c][0] = a.x; pr[c][1] = a.y; pr[c][2] = a.z; pr[c][3] = a.w;
        pr[c][4] = b.x; pr[c][5] = b.y; pr[c][6] = b.z; pr[c][7] = b.w;
    }
    const float4 w4 = *(const float4*)(rw + lane * 4);

    float4 xnext = *(const float4*)(pair + (size_t)pair0 * DPn + lane * 4);
    for (int pp = 0; pp < 8; pp++) {
        const int idx = pair0 + pp;
        float4 x = xnext;
        if (pp < 7)
            xnext = *(const float4*)(pair + (size_t)(idx + 1) * DPn + lane * 4);
        float ss = x.x * x.x + x.y * x.y + x.z * x.z + x.w * x.w;
#pragma unroll
        for (int off = 16; off > 0; off >>= 1)
            ss += __shfl_xor_sync(0xffffffffu, ss, off);
        float inv = rsqrtf(ss * (1.f / DPn) + EPS_RMS);
        float gl[4];
        {
            float y0 = x.x * inv * w4.x, y1 = x.y * inv * w4.y;
            float y2 = x.z * inv * w4.z, y3 = x.w * inv * w4.w;
            gl[0] = 0.5f * y0 * (1.f + erff(y0 * 0.70710678118654752f));
            gl[1] = 0.5f * y1 * (1.f + erff(y1 * 0.70710678118654752f));
            gl[2] = 0.5f * y2 * (1.f + erff(y2 * 0.70710678118654752f));
            gl[3] = 0.5f * y3 * (1.f + erff(y3 * 0.70710678118654752f));
        }
        float p[8] = {0.f, 0.f, 0.f, 0.f, 0.f, 0.f, 0.f, 0.f};
#pragma unroll
        for (int c = 0; c < 4; c++)
#pragma unroll
            for (int h = 0; h < 8; h++)
                p[h] = fmaf(gl[c], pr[c][h], p[h]);
#pragma unroll
        for (int off = 16; off > 0; off >>= 1)
#pragma unroll
            for (int h = 0; h < 8; h++)
                p[h] += __shfl_xor_sync(0xffffffffu, p[h], off);
        if (lane < 8) {
            float out = p[0];
#pragma unroll
            for (int h = 1; h < 8; h++) if (lane == h) out = p[h];
            int i = idx >> 8, j = idx & 255;
            pb[((size_t)lane * NPn + i) * NPn + j] = out;
        }
    }
}

/* ---------------- host launcher ---------------- */
static inline void launch_gemm(bool tb, int mode, int M, int N, int K,
                               const float* A, int lda, long long sA,
                               const float* B, int ldb, long long sB,
                               float* C, int ldc, long long sC, int batch,
                               const float* bias, const float* pbias,
                               float* rsum, const float* rscale,
                               int ksplit = 1)
{
    dim3 g((N + 127) / 128, M / 128, batch * ksplit), b(256);
    if (tb) {
        if (mode == 3)      gemm_tc<true, 3><<<g, b>>>(M, N, K, A, lda, sA, B, ldb, sB, C, ldc, sC, bias, pbias, rsum, rscale, 1);
        else if (mode == 4) gemm_tc<true, 4><<<g, b>>>(M, N, K, A, lda, sA, B, ldb, sB, C, ldc, sC, bias, pbias, rsum, rscale, 1);
        else                gemm_tc<true, 0><<<g, b>>>(M, N, K, A, lda, sA, B, ldb, sB, C, ldc, sC, bias, pbias, rsum, rscale, 1);
    } else {
        if (mode == 1)      gemm_tc<false, 1><<<g, b>>>(M, N, K, A, lda, sA, B, ldb, sB, C, ldc, sC, bias, pbias, rsum, rscale, 1);
        else if (mode == 2) gemm_tc<false, 2><<<g, b>>>(M, N, K, A, lda, sA, B, ldb, sB, C, ldc, sC, bias, pbias, rsum, rscale, 1);
        else if (mode == 5) gemm_tc<false, 5><<<g, b>>>(M, N, K, A, lda, sA, B, ldb, sB, C, ldc, sC, bias, pbias, rsum, rscale, ksplit);
        else                gemm_tc<false, 0><<<g, b>>>(M, N, K, A, lda, sA, B, ldb, sB, C, ldc, sC, bias, pbias, rsum, rscale, 1);
    }
}

extern "C" void kernel_launch(void* const* d_in, const int* in_sizes, int n_in,
                              void* d_out, int out_size)
{
    (void)in_sizes; (void)n_in; (void)out_size;
    const float* in_single = (const float*)d_in[0];
    const float* in_pair   = (const float*)d_in[1];
    const float* W_attn_pre  = (const float*)d_in[2];
    const float* W_attn_post = (const float*)d_in[3];
    const float* W_qkv  = (const float*)d_in[4];
    const float* W_qn   = (const float*)d_in[5];
    const float* W_kn   = (const float*)d_in[6];
    const float* W_vn   = (const float*)d_in[7];
    const float* W_brms = (const float*)d_in[8];
    const float* W_bproj= (const float*)d_in[9];
    const float* W_out  = (const float*)d_in[10];
    const float* W_ffpre = (const float*)d_in[11];
    const float* W_ffpost= (const float*)d_in[12];
    const float* W_ff1  = (const float*)d_in[13];
    const float* B_ff1  = (const float*)d_in[14];
    const float* W_ff2  = (const float*)d_in[15];
    const float* B_ff2  = (const float*)d_in[16];
    const float* W_ppre = (const float*)d_in[17];
    const float* W_pqk  = (const float*)d_in[18];
    const float* W_pv   = (const float*)d_in[19];
    const float* B_pv   = (const float*)d_in[20];
    const float* W_pffpre = (const float*)d_in[21];
    const float* W_pff1 = (const float*)d_in[22];
    const float* B_pff1 = (const float*)d_in[23];
    const float* W_pff2 = (const float*)d_in[24];
    const float* B_pff2 = (const float*)d_in[25];

    float *xn, *qkv, *q, *k, *v, *sim, *pb, *ao, *t1, *rsum;
    float *pxn, *pqk, *pv, *psim, *prsum, *pt;
    cudaGetSymbolAddress((void**)&xn, g_xn);
    cudaGetSymbolAddress((void**)&qkv, g_qkv);
    cudaGetSymbolAddress((void**)&q, g_q);
    cudaGetSymbolAddress((void**)&k, g_k);
    cudaGetSymbolAddress((void**)&v, g_v);
    cudaGetSymbolAddress((void**)&sim, g_sim);
    cudaGetSymbolAddress((void**)&pb, g_pb);
    cudaGetSymbolAddress((void**)&ao, g_ao);
    cudaGetSymbolAddress((void**)&t1, g_t1);
    cudaGetSymbolAddress((void**)&rsum, g_rsum);
    cudaGetSymbolAddress((void**)&pxn, g_pxn);
    cudaGetSymbolAddress((void**)&pqk, g_pqk);
    cudaGetSymbolAddress((void**)&pv, g_pv);
    cudaGetSymbolAddress((void**)&psim, g_psim);
    cudaGetSymbolAddress((void**)&prsum, g_prsum);
    cudaGetSymbolAddress((void**)&pt, g_pt);

    /* residual streams live directly in d_out: [single | pairwise] */
    float* single = (float*)d_out;
    float* pair   = (float*)d_out + (size_t)SEQn * Dn;
    cudaMemcpyAsync(single, in_single, (size_t)SEQn * Dn * 4, cudaMemcpyDeviceToDevice);
    cudaMemcpyAsync(pair, in_pair, (size_t)NPn * NPn * DPn * 4, cudaMemcpyDeviceToDevice);

    /* xn = rmsnorm(single, attn_pre[0]) for the first layer */
    rmsnorm_k<<<SEQn, 256>>>(single, W_attn_pre, xn, Dn);

    for (int i = 0; i < 4; i++) {
        /* ---- single-track attention ---- */
        /* fused zero of qkv + rsum + ao */
        {
            int na = SEQn * NQKVn, nb2 = Hn * SEQn, nc = SEQn * Hn * DVn;
            zero3_k<<<(na + nb2 + nc + 255) / 256, 256>>>(qkv, na, rsum, nb2, ao, nc);
        }
        launch_gemm(false, 5, SEQn, NQKVn, Dn / 2, xn, Dn, 0,
                    W_qkv + (long long)i * Dn * NQKVn, NQKVn, 0, qkv, NQKVn, 0, 1,
                    nullptr, nullptr, nullptr, nullptr, 2);
        qkv_post_k<<<SEQn, 320>>>(qkv, W_qn + i * DQKn, W_kn + i * DQKn,
                                  W_vn + i * DVn, q, k, v);
        pb_kernel<<<NPn * NPn / 64, 256>>>(pair, W_brms + i * DPn, W_bproj + i * DPn * Hn, pb);
        /* P = exp(softclamp(qk^T + pb)) -> f16 sim + rowsums */
        launch_gemm(true, 3, SEQn, SEQn, DQKn, q, DQKn, (long long)SEQn * DQKn,
                    k, DQKn, 0, sim, SEQn, (long long)SEQn * SEQn / 2, Hn,
                    nullptr, pb, rsum, nullptr);
        /* O = (P/rowsum) V — f16 mma, split-K x2 */
        gemm_av_f16<<<dim3(1, SEQn / 128, Hn * 2), 256>>>(
            (const unsigned*)sim, (const unsigned*)v, ao, rsum);
        /* t1 = ao @ W_out, split-K x3 */
        zero_k<<<(SEQn * Dn + 255) / 256, 256>>>(t1, SEQn * Dn);
        launch_gemm(false, 5, SEQn, Dn, (Hn * DVn) / 3, ao, Hn * DVn, 0,
                    W_out + (long long)i * Hn * DVn * Dn, Dn, 0, t1, Dn, 0, 1,
                    nullptr, nullptr, nullptr, nullptr, 3);
        rmsnorm_add_norm_k<<<SEQn, 256>>>(t1, W_attn_post + i * Dn, single,
                                          W_ffpre + i * Dn, xn);

        /* ---- single-track FF ---- */
        launch_gemm(false, 1, SEQn, FFIn, Dn, xn, Dn, 0,
                    W_ff1 + (long long)i * Dn * FFIn, FFIn, 0, ao, FFIn, 0, 1,
                    B_ff1 + i * FFIn, nullptr, nullptr, nullptr);
        zero_k<<<(SEQn * Dn + 255) / 256, 256>>>(t1, SEQn * Dn);
        launch_gemm(false, 5, SEQn, Dn, FFIn / 3, ao, FFIn, 0,
                    W_ff2 + (long long)i * FFIn * Dn, Dn, 0, t1, Dn, 0, 1,
                    B_ff2 + i * Dn, nullptr, nullptr, nullptr, 3);
        rmsnorm_add_norm_k<<<SEQn, 256>>>(t1, W_ffpost + i * Dn, single,
                                          (i < 3) ? W_attn_pre + (i + 1) * Dn : nullptr, xn);

        /* ---- pairwise track (layers 0, 2) ---- */
        if ((i & 1) == 0) {
            int j = i / 2;
            rmsnorm128_k<<<NPn * NPn / 8, 256>>>(pair, W_ppre + j * DPn, pxn);
            launch_gemm(false, 0, NPn * NPn, 2 * DPn, DPn, pxn, DPn, 0,
                        W_pqk + (long long)j * DPn * 2 * DPn, 2 * DPn, 0,
                        pqk, 2 * DPn, 0, 1, nullptr, nullptr, nullptr, nullptr);
            launch_gemm(false, 0, NPn * NPn, DPn, DPn, pxn, DPn, 0,
                        W_pv + (long long)j * DPn * DPn, DPn, 0,
                        pv, DPn, 0, 1, B_pv + j * DPn, nullptr, nullptr, nullptr);
            zero_k<<<(NPn * NPn + 255) / 256, 256>>>(prsum, NPn * NPn);
            launch_gemm(true, 4, NPn, NPn, DPn, pqk, 2 * DPn, (long long)NPn * 2 * DPn,
                        pqk + DPn, 2 * DPn, (long long)NPn * 2 * DPn,
                        psim, NPn, (long long)NPn * NPn, NPn,
                        nullptr, nullptr, prsum, nullptr);
            launch_gemm(false, 2, NPn, DPn, NPn, psim, NPn, (long long)NPn * NPn,
                        pv, DPn, (long long)NPn * DPn,
                        pair, DPn, (long long)NPn * DPn, NPn,
                        nullptr, nullptr, nullptr, prsum);
            rmsnorm128_k<<<NPn * NPn / 8, 256>>>(pair, W_pffpre + j * DPn, pxn);
            launch_gemm(false, 1, NPn * NPn, DPIn, DPn, pxn, DPn, 0,
                        W_pff1 + (long long)j * DPn * DPIn, DPIn, 0,
                        pt, DPIn, 0, 1, B_pff1 + j * DPIn, nullptr, nullptr, nullptr);
            launch_gemm(false, 2, NPn * NPn, DPn, DPIn, pt, DPIn, 0,
                        W_pff2 + (long long)j * DPIn * DPn, DPn, 0,
                        pair, DPn, 0, 1, B_pff2 + j * DPn, nullptr, nullptr, nullptr);
        }
    }
}

// round 17
// speedup vs baseline: 2.2020x; 1.0165x over previous
#include <cuda_runtime.h>
#include <math.h>

#define SEQn 2048
#define Dn   768
#define Hn   8
#define DQKn 128
#define DVn  192
#define NQKVn 1344   /* 8*128 + 128 + 192 */
#define NPn  256
#define DPn  128
#define FFIn 1536
#define DPIn 256
#define EPS_RMS 1.1920929e-07f
#define EPS_LN  1e-5f

/* ---------------- scratch (device globals; no allocation) ---------------- */
__device__ float g_xn[SEQn * Dn];
__device__ float g_qkv[SEQn * NQKVn];
__device__ float g_q[Hn * SEQn * DQKn];
__device__ float g_k[SEQn * DQKn];
__device__ float g_v[SEQn * DVn];                      /* fp16 (reinterpreted) */
__device__ float g_sim[(size_t)Hn * SEQn * SEQn / 2];  /* fp16 P, 67 MB */
__device__ float g_pb[Hn * NPn * NPn];
__device__ float g_ao[SEQn * Hn * DVn];                /* fp32 attn out; f16 scratch for ff1 */
__device__ float g_t1[SEQn * FFIn];
__device__ float g_rsum[Hn * SEQn];
__device__ float g_pxn[NPn * NPn * DPn];
__device__ float g_pqk[NPn * NPn * 2 * DPn];
__device__ float g_pv[NPn * NPn * DPn];
__device__ float g_psim[(size_t)NPn * NPn * NPn / 2];  /* fp16 P, 33.5 MB */
__device__ float g_prsum[NPn * NPn];
__device__ float g_pt[NPn * NPn * DPIn];

/* ---------------- helpers ---------------- */
__device__ __forceinline__ unsigned pack_f16(float lo, float hi) {
    unsigned r;
    asm("cvt.rn.f16x2.f32 %0, %1, %2;" : "=r"(r) : "f"(hi), "f"(lo));
    return r;
}

__device__ __forceinline__ void mma_f16(float* c, const unsigned* a, const unsigned* b) {
    asm volatile(
        "mma.sync.aligned.m16n8k16.row.col.f32.f16.f16.f32 "
        "{%0,%1,%2,%3}, {%4,%5,%6,%7}, {%8,%9}, {%0,%1,%2,%3};\n"
        : "+f"(c[0]), "+f"(c[1]), "+f"(c[2]), "+f"(c[3])
        : "r"(a[0]), "r"(a[1]), "r"(a[2]), "r"(a[3]), "r"(b[0]), "r"(b[1]));
}

/* exp(5*tanh(x/5)) via single-MUFU tanh.approx */
__device__ __forceinline__ float softclamp_exp(float x) {
    float th;
    asm("tanh.approx.f32 %0, %1;" : "=f"(th) : "f"(x * 0.2f));
    return __expf(5.f * th);
}

template <int OP>
__device__ __forceinline__ float blockReduce(float v) {
    __shared__ float s[33];
    int lane = threadIdx.x & 31, wid = threadIdx.x >> 5;
#pragma unroll
    for (int o = 16; o > 0; o >>= 1) {
        float ov = __shfl_down_sync(0xffffffffu, v, o);
        v = (OP == 0) ? (v + ov) : fmaxf(v, ov);
    }
    if (lane == 0) s[wid] = v;
    __syncthreads();
    if (threadIdx.x == 0) {
        int nw = (blockDim.x + 31) >> 5;
        float r = s[0];
        for (int i = 1; i < nw; i++) r = (OP == 0) ? (r + s[i]) : fmaxf(r, s[i]);
        s[32] = r;
    }
    __syncthreads();
    float r = s[32];
    __syncthreads();
    return r;
}

__global__ void zero_k(float* p, int n)
{
    int i = blockIdx.x * blockDim.x + threadIdx.x;
    if (i < n) p[i] = 0.f;
}

__global__ void zero3_k(float* a, int na, float* b, int nb, float* c, int nc)
{
    int i = blockIdx.x * blockDim.x + threadIdx.x;
    if (i < na) { a[i] = 0.f; return; }
    i -= na;
    if (i < nb) { b[i] = 0.f; return; }
    i -= nb;
    if (i < nc) c[i] = 0.f;
}

/* ---------------- FP16 tensor-core GEMM, 128x128 CTA, BK=16, dbl-buf.
   8 warps in 2x4 grid; warp tile 64x32. Inputs converted to f16 at staging
   (or, with AF16=true, A is already f16 k-pair-packed and staged raw).
   MODE: 0 plain(+bias), 1 relu(+bias), 2 accumulate into C(+bias),
         3 sim softmax: exp(softclamp(x+pb)) -> f16x2 C + atomic row sums,
         4 pair softmax: exp(x) -> f16x2 C + atomic row sums,
         5 split-K: atomicAdd into C (+bias only from kz==0 split),
         6 relu(+bias) -> f16x2 C.
   MODE3/4/6: C is fp16 storage; ldc/sC given so that word row = ldc>>1,
   sC in FLOAT units (= f16 elems/2).
   AF16: A is f16, lda/sA/K in f16-element units (even); !TB only.
   rscale (optional): multiply output rows by 1/rscale[batch*M+m].
   Requires M%128==0, K%16==0 (N tile-edge guarded, N%2==0).                 */
template <bool TB, int MODE, bool AF16>
__global__ __launch_bounds__(256) void gemm_tc(
    int M, int N, int K,
    const float* __restrict__ A, int lda, long long sA,
    const float* __restrict__ B, int ldb, long long sB,
    float* __restrict__ C, int ldc, long long sC,
    const float* __restrict__ bias,
    const float* __restrict__ pbias,
    float* __restrict__ rsum,
    const float* __restrict__ rscale,
    int ksplit)
{
    __shared__ unsigned As[2][8][136];   /* [k-pair 0..7][128 rows + pad] */
    __shared__ unsigned Bs[2][8][136];
    const int zz = blockIdx.z;
    const int batch = zz / ksplit;
    const int kz = zz - batch * ksplit;
    const long long aoff = (long long)batch * sA + (long long)kz * K;
    const float* Af = A + aoff;                      /* fp32 path */
    const unsigned* Awb = (const unsigned*)A + (aoff >> 1);  /* f16 path */
    B += (long long)batch * sB;
    if (!TB) B += (long long)kz * K * ldb;
    C += (long long)batch * sC;
    const int bm = blockIdx.y * 128, bn = blockIdx.x * 128;
    const int tid = threadIdx.x;
    const int lane = tid & 31, warp = tid >> 5;
    const int g = lane >> 2, tg = lane & 3;
    const int warpM = warp & 1, warpN = warp >> 1;

    const int arow = tid >> 1, ap4 = (tid & 1) * 4;
    const float* Aptr = Af + (long long)(bm + arow) * lda + (tid & 1) * 8;
    const unsigned* Apw = Awb + (long long)(bm + arow) * (lda >> 1) + (tid & 1) * 4;
    const bool bvt = TB ? (bn + arow < N) : true;
    const int k2r = tid >> 5, bn4 = (lane) * 4;
    const bool bvn = TB ? true : (bn + bn4 < N);
    const float4 f0 = make_float4(0.f, 0.f, 0.f, 0.f);

    float4 pa0, pa1, pb0, pb1;
    uint4 pw;
    /* prefetch stage 0 */
    {
        if (AF16) pw = *(const uint4*)(Apw);
        else {
            pa0 = *(const float4*)(Aptr);
            pa1 = *(const float4*)(Aptr + 4);
        }
        if (TB) {
            pb0 = bvt ? *(const float4*)(B + (long long)(bn + arow) * ldb + (tid & 1) * 8) : f0;
            pb1 = bvt ? *(const float4*)(B + (long long)(bn + arow) * ldb + (tid & 1) * 8 + 4) : f0;
        } else {
            pb0 = bvn ? *(const float4*)(B + (long long)(2 * k2r) * ldb + bn + bn4) : f0;
            pb1 = bvn ? *(const float4*)(B + (long long)(2 * k2r + 1) * ldb + bn + bn4) : f0;
        }
    }
    /* store stage 0 */
    {
        if (AF16) {
            As[0][ap4 + 0][arow] = pw.x;
            As[0][ap4 + 1][arow] = pw.y;
            As[0][ap4 + 2][arow] = pw.z;
            As[0][ap4 + 3][arow] = pw.w;
        } else {
            As[0][ap4 + 0][arow] = pack_f16(pa0.x, pa0.y);
            As[0][ap4 + 1][arow] = pack_f16(pa0.z, pa0.w);
            As[0][ap4 + 2][arow] = pack_f16(pa1.x, pa1.y);
            As[0][ap4 + 3][arow] = pack_f16(pa1.z, pa1.w);
        }
        if (TB) {
            Bs[0][ap4 + 0][arow] = pack_f16(pb0.x, pb0.y);
            Bs[0][ap4 + 1][arow] = pack_f16(pb0.z, pb0.w);
            Bs[0][ap4 + 2][arow] = pack_f16(pb1.x, pb1.y);
            Bs[0][ap4 + 3][arow] = pack_f16(pb1.z, pb1.w);
        } else {
            Bs[0][k2r][bn4 + 0] = pack_f16(pb0.x, pb1.x);
            Bs[0][k2r][bn4 + 1] = pack_f16(pb0.y, pb1.y);
            Bs[0][k2r][bn4 + 2] = pack_f16(pb0.z, pb1.z);
            Bs[0][k2r][bn4 + 3] = pack_f16(pb0.w, pb1.w);
        }
    }
    __syncthreads();

    float acc[4][4][4];
#pragma unroll
    for (int mt = 0; mt < 4; mt++)
#pragma unroll
        for (int nt = 0; nt < 4; nt++)
#pragma unroll
            for (int u = 0; u < 4; u++) acc[mt][nt][u] = 0.f;

    const int nst = K >> 4;
    for (int st = 0; st < nst; st++) {
        if (st + 1 < nst) {
            int kb = (st + 1) << 4;
            if (AF16) pw = *(const uint4*)(Apw + (st + 1) * 8);
            else {
                pa0 = *(const float4*)(Aptr + kb);
                pa1 = *(const float4*)(Aptr + kb + 4);
            }
            if (TB) {
                pb0 = bvt ? *(const float4*)(B + (long long)(bn + arow) * ldb + kb + (tid & 1) * 8) : f0;
                pb1 = bvt ? *(const float4*)(B + (long long)(bn + arow) * ldb + kb + (tid & 1) * 8 + 4) : f0;
            } else {
                pb0 = bvn ? *(const float4*)(B + (long long)(kb + 2 * k2r) * ldb + bn + bn4) : f0;
                pb1 = bvn ? *(const float4*)(B + (long long)(kb + 2 * k2r + 1) * ldb + bn + bn4) : f0;
            }
        }
        const int buf = st & 1;
        {
            unsigned af[4][4], bf[4][2];
#pragma unroll
            for (int mt = 0; mt < 4; mt++) {
                int m = warpM * 64 + mt * 16 + g;
                af[mt][0] = As[buf][tg][m];
                af[mt][1] = As[buf][tg][m + 8];
                af[mt][2] = As[buf][tg + 4][m];
                af[mt][3] = As[buf][tg + 4][m + 8];
            }
#pragma unroll
            for (int nt = 0; nt < 4; nt++) {
                int n = warpN * 32 + nt * 8 + g;
                bf[nt][0] = Bs[buf][tg][n];
                bf[nt][1] = Bs[buf][tg + 4][n];
            }
#pragma unroll
            for (int mt = 0; mt < 4; mt++)
#pragma unroll
                for (int nt = 0; nt < 4; nt++)
                    mma_f16(acc[mt][nt], af[mt], bf[nt]);
        }
        if (st + 1 < nst) {
            const int nb = (st + 1) & 1;
            if (AF16) {
                As[nb][ap4 + 0][arow] = pw.x;
                As[nb][ap4 + 1][arow] = pw.y;
                As[nb][ap4 + 2][arow] = pw.z;
                As[nb][ap4 + 3][arow] = pw.w;
            } else {
                As[nb][ap4 + 0][arow] = pack_f16(pa0.x, pa0.y);
                As[nb][ap4 + 1][arow] = pack_f16(pa0.z, pa0.w);
                As[nb][ap4 + 2][arow] = pack_f16(pa1.x, pa1.y);
                As[nb][ap4 + 3][arow] = pack_f16(pa1.z, pa1.w);
            }
            if (TB) {
                Bs[nb][ap4 + 0][arow] = pack_f16(pb0.x, pb0.y);
                Bs[nb][ap4 + 1][arow] = pack_f16(pb0.z, pb0.w);
                Bs[nb][ap4 + 2][arow] = pack_f16(pb1.x, pb1.y);
                Bs[nb][ap4 + 3][arow] = pack_f16(pb1.z, pb1.w);
            } else {
                Bs[nb][k2r][bn4 + 0] = pack_f16(pb0.x, pb1.x);
                Bs[nb][k2r][bn4 + 1] = pack_f16(pb0.y, pb1.y);
                Bs[nb][k2r][bn4 + 2] = pack_f16(pb0.z, pb1.z);
                Bs[nb][k2r][bn4 + 3] = pack_f16(pb0.w, pb1.w);
            }
        }
        __syncthreads();
    }

    /* ---- epilogue (fragment ownership: rows g/g+8, cols tg*2, tg*2+1) ---- */
#pragma unroll
    for (int mt = 0; mt < 4; mt++) {
        const int m0 = bm + warpM * 64 + mt * 16 + g;
        const int m1 = m0 + 8;
        float inv0 = 1.f, inv1 = 1.f;
        if (rscale) {
            inv0 = 1.f / rscale[(size_t)batch * M + m0];
            inv1 = 1.f / rscale[(size_t)batch * M + m1];
        }
        const float* pbr0 = nullptr;
        const float* pbr1 = nullptr;
        if (MODE == 3) {
            pbr0 = pbias + (size_t)batch * (NPn * NPn) + (size_t)(m0 >> 3) * NPn;
            pbr1 = pbias + (size_t)batch * (NPn * NPn) + (size_t)(m1 >> 3) * NPn;
        }
        float r0 = 0.f, r1 = 0.f;
#pragma unroll
        for (int nt = 0; nt < 4; nt++) {
            const int n = bn + warpN * 32 + nt * 8 + tg * 2;
            if (n < N) {
                float c0 = acc[mt][nt][0], c1 = acc[mt][nt][1];
                float c2 = acc[mt][nt][2], c3 = acc[mt][nt][3];
                if (bias && (MODE != 5 || kz == 0)) {
                    float2 bb = *(const float2*)&bias[n];
                    c0 += bb.x; c1 += bb.y; c2 += bb.x; c3 += bb.y;
                }
                if (MODE == 1 || MODE == 6) {
                    c0 = fmaxf(c0, 0.f); c1 = fmaxf(c1, 0.f);
                    c2 = fmaxf(c2, 0.f); c3 = fmaxf(c3, 0.f);
                }
                if (MODE == 3) {
                    float pb0v = pbr0[n >> 3], pb1v = pbr1[n >> 3];
                    c0 = softclamp_exp(c0 + pb0v);
                    c1 = softclamp_exp(c1 + pb0v);
                    c2 = softclamp_exp(c2 + pb1v);
                    c3 = softclamp_exp(c3 + pb1v);
                    r0 += c0 + c1; r1 += c2 + c3;
                    ((unsigned*)C)[(long long)m0 * (ldc >> 1) + (n >> 1)] = pack_f16(c0, c1);
                    ((unsigned*)C)[(long long)m1 * (ldc >> 1) + (n >> 1)] = pack_f16(c2, c3);
                } else if (MODE == 4) {
                    c0 = __expf(c0); c1 = __expf(c1);
                    c2 = __expf(c2); c3 = __expf(c3);
                    r0 += c0 + c1; r1 += c2 + c3;
                    ((unsigned*)C)[(long long)m0 * (ldc >> 1) + (n >> 1)] = pack_f16(c0, c1);
                    ((unsigned*)C)[(long long)m1 * (ldc >> 1) + (n >> 1)] = pack_f16(c2, c3);
                } else if (MODE == 6) {
                    ((unsigned*)C)[(long long)m0 * (ldc >> 1) + (n >> 1)] = pack_f16(c0, c1);
                    ((unsigned*)C)[(long long)m1 * (ldc >> 1) + (n >> 1)] = pack_f16(c2, c3);
                } else {
                    if (rscale) { c0 *= inv0; c1 *= inv0; c2 *= inv1; c3 *= inv1; }
                    if (MODE == 5) {
                        float* p0 = &C[(long long)m0 * ldc + n];
                        float* p1 = &C[(long long)m1 * ldc + n];
                        atomicAdd(p0, c0); atomicAdd(p0 + 1, c1);
                        atomicAdd(p1, c2); atomicAdd(p1 + 1, c3);
                    } else {
                        float2 w0, w1;
                        if (MODE == 2) {
                            float2 o0 = *(const float2*)&C[(long long)m0 * ldc + n];
                            float2 o1 = *(const float2*)&C[(long long)m1 * ldc + n];
                            w0.x = c0 + o0.x; w0.y = c1 + o0.y;
                            w1.x = c2 + o1.x; w1.y = c3 + o1.y;
                        } else {
                            w0.x = c0; w0.y = c1; w1.x = c2; w1.y = c3;
                        }
                        *(float2*)&C[(long long)m0 * ldc + n] = w0;
                        *(float2*)&C[(long long)m1 * ldc + n] = w1;
                    }
                }
            }
        }
        if (MODE == 3 || MODE == 4) {
            r0 += __shfl_xor_sync(0xffffffffu, r0, 1);
            r0 += __shfl_xor_sync(0xffffffffu, r0, 2);
            r1 += __shfl_xor_sync(0xffffffffu, r1, 1);
            r1 += __shfl_xor_sync(0xffffffffu, r1, 2);
            if (tg == 0) {
                atomicAdd(&rsum[(size_t)batch * M + m0], r0);
                atomicAdd(&rsum[(size_t)batch * M + m1], r1);
            }
        }
    }
}

/* ---------------- fp16 AV GEMM: O = (P/rowsum) V, split-K x2 -------------- */
__global__ __launch_bounds__(256) void gemm_av_f16(
    const unsigned* __restrict__ Aw,   /* f16 pairs, row = 1024 words */
    const unsigned* __restrict__ Bw,   /* v f16, row = 96 words */
    float* __restrict__ C,
    const float* __restrict__ rsum)
{
    __shared__ unsigned As[2][8][136];
    __shared__ unsigned Bs[2][8][200];
    const int head = blockIdx.z >> 1, kz = blockIdx.z & 1;
    const int bm = blockIdx.y * 128;
    const int tid = threadIdx.x;
    const int lane = tid & 31, warp = tid >> 5;
    const int g = lane >> 2, tg = lane & 3;
    const int warpM = warp & 1, warpN = warp >> 1;

    const unsigned* Ap = Aw + (size_t)head * (SEQn * (SEQn / 2))
                       + (size_t)(bm + (tid >> 1)) * (SEQn / 2)
                       + (size_t)kz * 512 + (tid & 1) * 4;
    const int k2r = tid >> 5;
    const unsigned* Bp = Bw + ((size_t)kz * 1024) * 96 + lane * 3;
    const int nb = lane * 6;

    uint4 pa;
    unsigned rb0[3], rb1[3];
    pa = *(const uint4*)(Ap);
    {
        const unsigned* p0 = Bp + (size_t)(2 * k2r) * 96;
        const unsigned* p1 = p0 + 96;
        rb0[0] = p0[0]; rb0[1] = p0[1]; rb0[2] = p0[2];
        rb1[0] = p1[0]; rb1[1] = p1[1]; rb1[2] = p1[2];
    }
    {
        const unsigned* u = (const unsigned*)&pa;
#pragma unroll
        for (int i = 0; i < 4; i++) As[0][(tid & 1) * 4 + i][tid >> 1] = u[i];
#pragma unroll
        for (int j = 0; j < 3; j++) {
            Bs[0][k2r][nb + 2 * j]     = __byte_perm(rb0[j], rb1[j], 0x5410);
            Bs[0][k2r][nb + 2 * j + 1] = __byte_perm(rb0[j], rb1[j], 0x7632);
        }
    }
    __syncthreads();

    float acc[4][6][4];
#pragma unroll
    for (int mt = 0; mt < 4; mt++)
#pragma unroll
        for (int nt = 0; nt < 6; nt++)
#pragma unroll
            for (int u = 0; u < 4; u++) acc[mt][nt][u] = 0.f;

    const int nst = 64;
    for (int st = 0; st < nst; st++) {
        if (st + 1 < nst) {
            pa = *(const uint4*)(Ap + (st + 1) * 8);
            const unsigned* p0 = Bp + (size_t)((st + 1) * 16 + 2 * k2r) * 96;
            const unsigned* p1 = p0 + 96;
            rb0[0] = p0[0]; rb0[1] = p0[1]; rb0[2] = p0[2];
            rb1[0] = p1[0]; rb1[1] = p1[1]; rb1[2] = p1[2];
        }
        const int buf = st & 1;
        {
            unsigned af[4][4], bf[6][2];
#pragma unroll
            for (int mt = 0; mt < 4; mt++) {
                int m = warpM * 64 + mt * 16 + g;
                af[mt][0] = As[buf][tg][m];
                af[mt][1] = As[buf][tg][m + 8];
                af[mt][2] = As[buf][tg + 4][m];
                af[mt][3] = As[buf][tg + 4][m + 8];
            }
#pragma unroll
            for (int nt = 0; nt < 6; nt++) {
                int n = warpN * 48 + nt * 8 + g;
                bf[nt][0] = Bs[buf][tg][n];
                bf[nt][1] = Bs[buf][tg + 4][n];
            }
#pragma unroll
            for (int mt = 0; mt < 4; mt++)
#pragma unroll
                for (int nt = 0; nt < 6; nt++)
                    mma_f16(acc[mt][nt], af[mt], bf[nt]);
        }
        if (st + 1 < nst) {
            const int nbuf = (st + 1) & 1;
            const unsigned* u = (const unsigned*)&pa;
#pragma unroll
            for (int i = 0; i < 4; i++) As[nbuf][(tid & 1) * 4 + i][tid >> 1] = u[i];
#pragma unroll
            for (int j = 0; j < 3; j++) {
                Bs[nbuf][k2r][nb + 2 * j]     = __byte_perm(rb0[j], rb1[j], 0x5410);
                Bs[nbuf][k2r][nb + 2 * j + 1] = __byte_perm(rb0[j], rb1[j], 0x7632);
            }
        }
        __syncthreads();
    }

#pragma unroll
    for (int mt = 0; mt < 4; mt++) {
        const int m0 = bm + warpM * 64 + mt * 16 + g;
        const int m1 = m0 + 8;
        float inv0 = 1.f / rsum[(size_t)head * SEQn + m0];
        float inv1 = 1.f / rsum[(size_t)head * SEQn + m1];
#pragma unroll
        for (int nt = 0; nt < 6; nt++) {
            const int n = head * DVn + warpN * 48 + nt * 8 + tg * 2;
            float* p0 = &C[(long long)m0 * (Hn * DVn) + n];
            float* p1 = &C[(long long)m1 * (Hn * DVn) + n];
            atomicAdd(p0,     acc[mt][nt][0] * inv0);
            atomicAdd(p0 + 1, acc[mt][nt][1] * inv0);
            atomicAdd(p1,     acc[mt][nt][2] * inv1);
            atomicAdd(p1 + 1, acc[mt][nt][3] * inv1);
        }
    }
}

/* ---------------- norms ---------------- */
__global__ void rmsnorm_k(const float* __restrict__ x, const float* __restrict__ w,
                          float* __restrict__ y, int cols)
{
    long long r = blockIdx.x;
    const float* xr = x + r * cols;
    float ss = 0.f;
    for (int c = threadIdx.x; c < cols; c += blockDim.x) { float v = xr[c]; ss += v * v; }
    ss = blockReduce<0>(ss);
    float inv = rsqrtf(ss / cols + EPS_RMS);
    for (int c = threadIdx.x; c < cols; c += blockDim.x)
        y[r * cols + c] = xr[c] * inv * w[c];
}

/* warp-per-row RMSNorm for 128-wide rows (pairwise track). 8 rows/block. */
__global__ __launch_bounds__(256) void rmsnorm128_k(
    const float* __restrict__ x, const float* __restrict__ w, float* __restrict__ y)
{
    const int row = blockIdx.x * 8 + (threadIdx.x >> 5);
    const int lane = threadIdx.x & 31;
    float4 v = *(const float4*)(x + (size_t)row * DPn + lane * 4);
    float ss = v.x * v.x + v.y * v.y + v.z * v.z + v.w * v.w;
#pragma unroll
    for (int o = 16; o > 0; o >>= 1)
        ss += __shfl_xor_sync(0xffffffffu, ss, o);
    float inv = rsqrtf(ss * (1.f / DPn) + EPS_RMS);
    float4 w4 = *(const float4*)(w + lane * 4);
    float4 out;
    out.x = v.x * inv * w4.x; out.y = v.y * inv * w4.y;
    out.z = v.z * inv * w4.z; out.w = v.w * inv * w4.w;
    *(float4*)(y + (size_t)row * DPn + lane * 4) = out;
}

/* res += rmsnorm(x)*w1; if (w2) out = rmsnorm(res)*w2.  cols=768, 256 thr. */
__global__ void rmsnorm_add_norm_k(const float* __restrict__ x, const float* __restrict__ w1,
                                   float* __restrict__ res, const float* __restrict__ w2,
                                   float* __restrict__ out)
{
    long long r = blockIdx.x;
    const int cols = Dn;
    const float* xr = x + r * cols;
    float xv[3], rv[3];
    float ss = 0.f;
#pragma unroll
    for (int u = 0; u < 3; u++) {
        xv[u] = xr[threadIdx.x + u * 256];
        ss += xv[u] * xv[u];
    }
    ss = blockReduce<0>(ss);
    float inv = rsqrtf(ss / cols + EPS_RMS);
    float ss2 = 0.f;
#pragma unroll
    for (int u = 0; u < 3; u++) {
        int c = threadIdx.x + u * 256;
        float v = res[r * cols + c] + xv[u] * inv * w1[c];
        res[r * cols + c] = v;
        rv[u] = v;
        ss2 += v * v;
    }
    if (w2) {
        ss2 = blockReduce<0>(ss2);
        float inv2 = rsqrtf(ss2 / cols + EPS_RMS);
#pragma unroll
        for (int u = 0; u < 3; u++) {
            int c = threadIdx.x + u * 256;
            out[r * cols + c] = rv[u] * inv2 * w2[c];
        }
    }
}

/* -------- qkv post: warp-per-segment LayerNorm + scale + rotary.
   warp 0-7 = q heads, warp 8 = k, warp 9 = v (v written as fp16). ---- */
__global__ __launch_bounds__(320) void qkv_post_k(
    const float* __restrict__ qkv,
    const float* __restrict__ qn, const float* __restrict__ kn,
    const float* __restrict__ vn,
    float* __restrict__ q, float* __restrict__ k, float* __restrict__ v)
{
    const int n = blockIdx.x;
    const int s = threadIdx.x >> 5;
    const int lane = threadIdx.x & 31;
    if (s < 9) {
        const int off = (s < 8) ? s * 128 : 1024;
        float4 x = *(const float4*)(qkv + (size_t)n * NQKVn + off + lane * 4);
        float sum = x.x + x.y + x.z + x.w;
        float sq = x.x * x.x + x.y * x.y + x.z * x.z + x.w * x.w;
#pragma unroll
        for (int o = 16; o > 0; o >>= 1) {
            sum += __shfl_xor_sync(0xffffffffu, sum, o);
            sq  += __shfl_xor_sync(0xffffffffu, sq, o);
        }
        float mu = sum * (1.f / 128.f);
        float var = sq * (1.f / 128.f) - mu * mu;
        float inv = rsqrtf(var + EPS_LN);
        const float* w = (s < 8) ? qn : kn;
        float4 w4 = *(const float4*)(w + lane * 4);
        float sc = (s < 8) ? 0.125f : 1.f;
        float y0 = (x.x - mu) * inv * w4.x * sc;
        float y1 = (x.y - mu) * inv * w4.y * sc;
        float y2 = (x.z - mu) * inv * w4.z * sc;
        float y3 = (x.w - mu) * inv * w4.w * sc;
        float p0 = __shfl_xor_sync(0xffffffffu, y0, 16);
        float sgn = (lane < 16) ? -1.f : 1.f;
        float invf = ((lane & 15) == 0) ? 0.1f : 0.f;
        float f = (float)n * invf;
        float c = cosf(f), si = sinf(f);
        float4 out = make_float4(y0 * c + sgn * p0 * si, y1, y2, y3);
        if (s < 8) *(float4*)(q + ((size_t)s * SEQn + n) * DQKn + lane * 4) = out;
        else       *(float4*)(k + (size_t)n * DQKn + lane * 4) = out;
    } else {
        const float* src = qkv + (size_t)n * NQKVn + 1152 + lane * 6;
        float2 a = *(const float2*)(src);
        float2 b = *(const float2*)(src + 2);
        float2 c2 = *(const float2*)(src + 4);
        float sum = a.x + a.y + b.x + b.y + c2.x + c2.y;
        float sq = a.x * a.x + a.y * a.y + b.x * b.x + b.y * b.y
                 + c2.x * c2.x + c2.y * c2.y;
#pragma unroll
        for (int o = 16; o > 0; o >>= 1) {
            sum += __shfl_xor_sync(0xffffffffu, sum, o);
            sq  += __shfl_xor_sync(0xffffffffu, sq, o);
        }
        float mu = sum * (1.f / 192.f);
        float var = sq * (1.f / 192.f) - mu * mu;
        float inv = rsqrtf(var + EPS_LN);
        const float* wv = vn + lane * 6;
        float2 wa = *(const float2*)(wv);
        float2 wb = *(const float2*)(wv + 2);
        float2 wc = *(const float2*)(wv + 4);
        unsigned* dst = (unsigned*)v + (size_t)n * (DVn / 2) + lane * 3;
        dst[0] = pack_f16((a.x - mu) * inv * wa.x,  (a.y - mu) * inv * wa.y);
        dst[1] = pack_f16((b.x - mu) * inv * wb.x,  (b.y - mu) * inv * wb.y);
        dst[2] = pack_f16((c2.x - mu) * inv * wc.x, (c2.y - mu) * inv * wc.y);
    }
}

/* ------------- pairwise bias: rms -> gelu -> [128->8]. ------------- */
__global__ __launch_bounds__(256) void pb_kernel(
    const float* __restrict__ pair, const float* __restrict__ rw,
    const float* __restrict__ proj, float* __restrict__ pb)
{
    const int lane = threadIdx.x & 31;
    const int warp = threadIdx.x >> 5;
    const int pair0 = (blockIdx.x * 8 + warp) * 8;
    float pr[4][8];
#pragma unroll
    for (int c = 0; c < 4; c++) {
        const float* p0 = proj + (size_t)(lane * 4 + c) * Hn;
        float4 a = *(const float4*)p0;
        float4 b = *(const float4*)(p0 + 4);
        pr[c][0] = a.x; pr[c][1] = a.y; pr[c][2] = a.z; pr[c][3] = a.w;
        pr[c][4] = b.x; pr[c][5] = b.y; pr[c][6] = b.z; pr[c][7] = b.w;
    }
    const float4 w4 = *(const float4*)(rw + lane * 4);

    float4 xnext = *(const float4*)(pair + (size_t)pair0 * DPn + lane * 4);
    for (int pp = 0; pp < 8; pp++) {
        const int idx = pair0 + pp;
        float4 x = xnext;
        if (pp < 7)
            xnext = *(const float4*)(pair + (size_t)(idx + 1) * DPn + lane * 4);
        float ss = x.x * x.x + x.y * x.y + x.z * x.z + x.w * x.w;
#pragma unroll
        for (int off = 16; off > 0; off >>= 1)
            ss += __shfl_xor_sync(0xffffffffu, ss, off);
        float inv = rsqrtf(ss * (1.f / DPn) + EPS_RMS);
        float gl[4];
        {
            float y0 = x.x * inv * w4.x, y1 = x.y * inv * w4.y;
            float y2 = x.z * inv * w4.z, y3 = x.w * inv * w4.w;
            gl[0] = 0.5f * y0 * (1.f + erff(y0 * 0.70710678118654752f));
            gl[1] = 0.5f * y1 * (1.f + erff(y1 * 0.70710678118654752f));
            gl[2] = 0.5f * y2 * (1.f + erff(y2 * 0.70710678118654752f));
            gl[3] = 0.5f * y3 * (1.f + erff(y3 * 0.70710678118654752f));
        }
        float p[8] = {0.f, 0.f, 0.f, 0.f, 0.f, 0.f, 0.f, 0.f};
#pragma unroll
        for (int c = 0; c < 4; c++)
#pragma unroll
            for (int h = 0; h < 8; h++)
                p[h] = fmaf(gl[c], pr[c][h], p[h]);
#pragma unroll
        for (int off = 16; off > 0; off >>= 1)
#pragma unroll
            for (int h = 0; h < 8; h++)
                p[h] += __shfl_xor_sync(0xffffffffu, p[h], off);
        if (lane < 8) {
            float out = p[0];
#pragma unroll
            for (int h = 1; h < 8; h++) if (lane == h) out = p[h];
            int i = idx >> 8, j = idx & 255;
            pb[((size_t)lane * NPn + i) * NPn + j] = out;
        }
    }
}

/* ---------------- host launcher ---------------- */
static inline void launch_gemm(bool tb, int mode, int M, int N, int K,
                               const float* A, int lda, long long sA,
                               const float* B, int ldb, long long sB,
                               float* C, int ldc, long long sC, int batch,
                               const float* bias, const float* pbias,
                               float* rsum, const float* rscale,
                               int ksplit = 1, bool af16 = false)
{
    dim3 g((N + 127) / 128, M / 128, batch * ksplit), b(256);
    if (tb) {
        if (mode == 3)      gemm_tc<true, 3, false><<<g, b>>>(M, N, K, A, lda, sA, B, ldb, sB, C, ldc, sC, bias, pbias, rsum, rscale, 1);
        else if (mode == 4) gemm_tc<true, 4, false><<<g, b>>>(M, N, K, A, lda, sA, B, ldb, sB, C, ldc, sC, bias, pbias, rsum, rscale, 1);
        else                gemm_tc<true, 0, false><<<g, b>>>(M, N, K, A, lda, sA, B, ldb, sB, C, ldc, sC, bias, pbias, rsum, rscale, 1);
    } else {
        if (mode == 1)      gemm_tc<false, 1, false><<<g, b>>>(M, N, K, A, lda, sA, B, ldb, sB, C, ldc, sC, bias, pbias, rsum, rscale, 1);
        else if (mode == 6) gemm_tc<false, 6, false><<<g, b>>>(M, N, K, A, lda, sA, B, ldb, sB, C, ldc, sC, bias, pbias, rsum, rscale, 1);
        else if (mode == 2) {
            if (af16) gemm_tc<false, 2, true><<<g, b>>>(M, N, K, A, lda, sA, B, ldb, sB, C, ldc, sC, bias, pbias, rsum, rscale, 1);
            else      gemm_tc<false, 2, false><<<g, b>>>(M, N, K, A, lda, sA, B, ldb, sB, C, ldc, sC, bias, pbias, rsum, rscale, 1);
        }
        else if (mode == 5) {
            if (af16) gemm_tc<false, 5, true><<<g, b>>>(M, N, K, A, lda, sA, B, ldb, sB, C, ldc, sC, bias, pbias, rsum, rscale, ksplit);
            else      gemm_tc<false, 5, false><<<g, b>>>(M, N, K, A, lda, sA, B, ldb, sB, C, ldc, sC, bias, pbias, rsum, rscale, ksplit);
        }
        else                gemm_tc<false, 0, false><<<g, b>>>(M, N, K, A, lda, sA, B, ldb, sB, C, ldc, sC, bias, pbias, rsum, rscale, 1);
    }
}

extern "C" void kernel_launch(void* const* d_in, const int* in_sizes, int n_in,
                              void* d_out, int out_size)
{
    (void)in_sizes; (void)n_in; (void)out_size;
    const float* in_single = (const float*)d_in[0];
    const float* in_pair   = (const float*)d_in[1];
    const float* W_attn_pre  = (const float*)d_in[2];
    const float* W_attn_post = (const float*)d_in[3];
    const float* W_qkv  = (const float*)d_in[4];
    const float* W_qn   = (const float*)d_in[5];
    const float* W_kn   = (const float*)d_in[6];
    const float* W_vn   = (const float*)d_in[7];
    const float* W_brms = (const float*)d_in[8];
    const float* W_bproj= (const float*)d_in[9];
    const float* W_out  = (const float*)d_in[10];
    const float* W_ffpre = (const float*)d_in[11];
    const float* W_ffpost= (const float*)d_in[12];
    const float* W_ff1  = (const float*)d_in[13];
    const float* B_ff1  = (const float*)d_in[14];
    const float* W_ff2  = (const float*)d_in[15];
    const float* B_ff2  = (const float*)d_in[16];
    const float* W_ppre = (const float*)d_in[17];
    const float* W_pqk  = (const float*)d_in[18];
    const float* W_pv   = (const float*)d_in[19];
    const float* B_pv   = (const float*)d_in[20];
    const float* W_pffpre = (const float*)d_in[21];
    const float* W_pff1 = (const float*)d_in[22];
    const float* B_pff1 = (const float*)d_in[23];
    const float* W_pff2 = (const float*)d_in[24];
    const float* B_pff2 = (const float*)d_in[25];

    float *xn, *qkv, *q, *k, *v, *sim, *pb, *ao, *t1, *rsum;
    float *pxn, *pqk, *pv, *psim, *prsum, *pt;
    cudaGetSymbolAddress((void**)&xn, g_xn);
    cudaGetSymbolAddress((void**)&qkv, g_qkv);
    cudaGetSymbolAddress((void**)&q, g_q);
    cudaGetSymbolAddress((void**)&k, g_k);
    cudaGetSymbolAddress((void**)&v, g_v);
    cudaGetSymbolAddress((void**)&sim, g_sim);
    cudaGetSymbolAddress((void**)&pb, g_pb);
    cudaGetSymbolAddress((void**)&ao, g_ao);
    cudaGetSymbolAddress((void**)&t1, g_t1);
    cudaGetSymbolAddress((void**)&rsum, g_rsum);
    cudaGetSymbolAddress((void**)&pxn, g_pxn);
    cudaGetSymbolAddress((void**)&pqk, g_pqk);
    cudaGetSymbolAddress((void**)&pv, g_pv);
    cudaGetSymbolAddress((void**)&psim, g_psim);
    cudaGetSymbolAddress((void**)&prsum, g_prsum);
    cudaGetSymbolAddress((void**)&pt, g_pt);

    /* residual streams live directly in d_out: [single | pairwise] */
    float* single = (float*)d_out;
    float* pair   = (float*)d_out + (size_t)SEQn * Dn;
    cudaMemcpyAsync(single, in_single, (size_t)SEQn * Dn * 4, cudaMemcpyDeviceToDevice);
    cudaMemcpyAsync(pair, in_pair, (size_t)NPn * NPn * DPn * 4, cudaMemcpyDeviceToDevice);

    /* xn = rmsnorm(single, attn_pre[0]) for the first layer */
    rmsnorm_k<<<SEQn, 256>>>(single, W_attn_pre, xn, Dn);

    for (int i = 0; i < 4; i++) {
        /* ---- single-track attention ---- */
        {
            int na = SEQn * NQKVn, nb2 = Hn * SEQn, nc = SEQn * Hn * DVn;
            zero3_k<<<(na + nb2 + nc + 255) / 256, 256>>>(qkv, na, rsum, nb2, ao, nc);
        }
        launch_gemm(false, 5, SEQn, NQKVn, Dn / 2, xn, Dn, 0,
                    W_qkv + (long long)i * Dn * NQKVn, NQKVn, 0, qkv, NQKVn, 0, 1,
                    nullptr, nullptr, nullptr, nullptr, 2);
        qkv_post_k<<<SEQn, 320>>>(qkv, W_qn + i * DQKn, W_kn + i * DQKn,
                                  W_vn + i * DVn, q, k, v);
        pb_kernel<<<NPn * NPn / 64, 256>>>(pair, W_brms + i * DPn, W_bproj + i * DPn * Hn, pb);
        /* P = exp(softclamp(qk^T + pb)) -> f16 sim + rowsums */
        launch_gemm(true, 3, SEQn, SEQn, DQKn, q, DQKn, (long long)SEQn * DQKn,
                    k, DQKn, 0, sim, SEQn, (long long)SEQn * SEQn / 2, Hn,
                    nullptr, pb, rsum, nullptr);
        /* O = (P/rowsum) V — f16 mma, split-K x2 */
        gemm_av_f16<<<dim3(1, SEQn / 128, Hn * 2), 256>>>(
            (const unsigned*)sim, (const unsigned*)v, ao, rsum);
        /* t1 = ao @ W_out, split-K x3 */
        zero_k<<<(SEQn * Dn + 255) / 256, 256>>>(t1, SEQn * Dn);
        launch_gemm(false, 5, SEQn, Dn, (Hn * DVn) / 3, ao, Hn * DVn, 0,
                    W_out + (long long)i * Hn * DVn * Dn, Dn, 0, t1, Dn, 0, 1,
                    nullptr, nullptr, nullptr, nullptr, 3);
        rmsnorm_add_norm_k<<<SEQn, 256>>>(t1, W_attn_post + i * Dn, single,
                                          W_ffpre + i * Dn, xn);

        /* ---- single-track FF ---- */
        /* ao (f16) = relu(xn @ W_ff1 + b) */
        launch_gemm(false, 6, SEQn, FFIn, Dn, xn, Dn, 0,
                    W_ff1 + (long long)i * Dn * FFIn, FFIn, 0, ao, FFIn, 0, 1,
                    B_ff1 + i * FFIn, nullptr, nullptr, nullptr);
        /* t1 = ao(f16) @ W_ff2 + b, split-K x3, A read as f16 */
        zero_k<<<(SEQn * Dn + 255) / 256, 256>>>(t1, SEQn * Dn);
        launch_gemm(false, 5, SEQn, Dn, FFIn / 3, ao, FFIn, 0,
                    W_ff2 + (long long)i * FFIn * Dn, Dn, 0, t1, Dn, 0, 1,
                    B_ff2 + i * Dn, nullptr, nullptr, nullptr, 3, true);
        rmsnorm_add_norm_k<<<SEQn, 256>>>(t1, W_ffpost + i * Dn, single,
                                          (i < 3) ? W_attn_pre + (i + 1) * Dn : nullptr, xn);

        /* ---- pairwise track (layers 0, 2) ---- */
        if ((i & 1) == 0) {
            int j = i / 2;
            rmsnorm128_k<<<NPn * NPn / 8, 256>>>(pair, W_ppre + j * DPn, pxn);
            launch_gemm(false, 0, NPn * NPn, 2 * DPn, DPn, pxn, DPn, 0,
                        W_pqk + (long long)j * DPn * 2 * DPn, 2 * DPn, 0,
                        pqk, 2 * DPn, 0, 1, nullptr, nullptr, nullptr, nullptr);
            launch_gemm(false, 0, NPn * NPn, DPn, DPn, pxn, DPn, 0,
                        W_pv + (long long)j * DPn * DPn, DPn, 0,
                        pv, DPn, 0, 1, B_pv + j * DPn, nullptr, nullptr, nullptr);
            zero_k<<<(NPn * NPn + 255) / 256, 256>>>(prsum, NPn * NPn);
            /* psim (f16) = exp(pq @ pk^T) + rowsums */
            launch_gemm(true, 4, NPn, NPn, DPn, pqk, 2 * DPn, (long long)NPn * 2 * DPn,
                        pqk + DPn, 2 * DPn, (long long)NPn * 2 * DPn,
                        psim, NPn, (long long)NPn * NPn / 2, NPn,
                        nullptr, nullptr, prsum, nullptr);
            /* pair += (psim(f16)/rowsum) @ pv */
            launch_gemm(false, 2, NPn, DPn, NPn, psim, NPn, (long long)NPn * NPn,
                        pv, DPn, (long long)NPn * DPn,
                        pair, DPn, (long long)NPn * DPn, NPn,
                        nullptr, nullptr, nullptr, prsum, 1, true);
            rmsnorm128_k<<<NPn * NPn / 8, 256>>>(pair, W_pffpre + j * DPn, pxn);
            launch_gemm(false, 1, NPn * NPn, DPIn, DPn, pxn, DPn, 0,
                        W_pff1 + (long long)j * DPn * DPIn, DPIn, 0,
                        pt, DPIn, 0, 1, B_pff1 + j * DPIn, nullptr, nullptr, nullptr);
            launch_gemm(false, 2, NPn * NPn, DPn, DPIn, pt, DPIn, 0,
                        W_pff2 + (long long)j * DPIn * DPn, DPn, 0,
                        pair, DPn, 0, 1, B_pff2 + j * DPn, nullptr, nullptr, nullptr);
        }
    }
}